// round 8
// baseline (speedup 1.0000x reference)
#include <cuda_runtime.h>
#include <cuda_bf16.h>
#include <cstdint>

#define BATCH 4
#define S_LEN 2048
#define EMB   1024
#define NH    16
#define HD    64
#define M_TOT (BATCH * S_LEN)   // 8192
#define BH    (BATCH * NH)      // 64
#define WSZ   ((size_t)EMB * EMB)

// ---------------------------------------------------------------------------
// Scratch (device globals — no allocation allowed)
// ---------------------------------------------------------------------------
__device__ __nv_bfloat16 g_xhi[(size_t)M_TOT * EMB];
__device__ __nv_bfloat16 g_xlo[(size_t)M_TOT * EMB];
__device__ __nv_bfloat16 g_whi[4][WSZ];
__device__ __nv_bfloat16 g_wlo[4][WSZ];
__device__ __nv_bfloat16 g_qhi[(size_t)BH * S_LEN * HD];
__device__ __nv_bfloat16 g_qlo[(size_t)BH * S_LEN * HD];
__device__ __nv_bfloat16 g_khi[(size_t)BH * S_LEN * HD];
__device__ __nv_bfloat16 g_klo[(size_t)BH * S_LEN * HD];
__device__ __nv_bfloat16 g_vhi[(size_t)BH * S_LEN * HD];
__device__ __nv_bfloat16 g_vlo[(size_t)BH * S_LEN * HD];
__device__ __nv_bfloat16 g_ahi[(size_t)M_TOT * EMB];
__device__ __nv_bfloat16 g_alo[(size_t)M_TOT * EMB];

// ---------------------------------------------------------------------------
// helpers
// ---------------------------------------------------------------------------
__device__ __forceinline__ uint32_t smem_u32(const void* p) {
    uint32_t a;
    asm("{ .reg .u64 t; cvta.to.shared.u64 t, %1; cvt.u32.u64 %0, t; }"
        : "=r"(a) : "l"(p));
    return a;
}
__device__ __forceinline__ void cp_async16(uint32_t dst, const void* src) {
    asm volatile("cp.async.cg.shared.global [%0], [%1], 16;"
                 :: "r"(dst), "l"(__cvta_generic_to_global(src)) : "memory");
}
#define CP_COMMIT()  asm volatile("cp.async.commit_group;" ::: "memory")
#define CP_WAIT(n)   asm volatile("cp.async.wait_group %0;" :: "n"(n) : "memory")

__device__ __forceinline__ void ldm_x4(uint32_t* r, uint32_t addr) {
    asm volatile("ldmatrix.sync.aligned.m8n8.x4.shared.b16 {%0,%1,%2,%3}, [%4];"
                 : "=r"(r[0]), "=r"(r[1]), "=r"(r[2]), "=r"(r[3]) : "r"(addr));
}
__device__ __forceinline__ void ldm_x2(uint32_t* r, uint32_t addr) {
    asm volatile("ldmatrix.sync.aligned.m8n8.x2.shared.b16 {%0,%1}, [%2];"
                 : "=r"(r[0]), "=r"(r[1]) : "r"(addr));
}
__device__ __forceinline__ void ldm_x2_t(uint32_t* r, uint32_t addr) {
    asm volatile("ldmatrix.sync.aligned.m8n8.x2.trans.shared.b16 {%0,%1}, [%2];"
                 : "=r"(r[0]), "=r"(r[1]) : "r"(addr));
}
__device__ __forceinline__ void mma_bf16(float* c, const uint32_t* a, const uint32_t* b) {
    asm volatile(
        "mma.sync.aligned.m16n8k16.row.col.f32.bf16.bf16.f32 "
        "{%0,%1,%2,%3}, {%4,%5,%6,%7}, {%8,%9}, {%0,%1,%2,%3};"
        : "+f"(c[0]), "+f"(c[1]), "+f"(c[2]), "+f"(c[3])
        : "r"(a[0]), "r"(a[1]), "r"(a[2]), "r"(a[3]), "r"(b[0]), "r"(b[1]));
}
__device__ __forceinline__ uint32_t pack_bf16x2(float lo, float hi) {
    uint32_t r;
    asm("cvt.rn.bf16x2.f32 %0, %1, %2;" : "=r"(r) : "f"(hi), "f"(lo));
    return r;
}

// ---------------------------------------------------------------------------
// single fused convert: x + 4 weights -> bf16 hi/lo
// ---------------------------------------------------------------------------
#define N4X (M_TOT * EMB / 4)
#define N4W (EMB * EMB / 4)
#define N4ALL (N4X + 4 * N4W)

__global__ void __launch_bounds__(256)
convert_all(const float4* __restrict__ x,
            const float4* __restrict__ Wq, const float4* __restrict__ Wk,
            const float4* __restrict__ Wv, const float4* __restrict__ Wo,
            __nv_bfloat16* __restrict__ xhi, __nv_bfloat16* __restrict__ xlo,
            __nv_bfloat16* __restrict__ whi, __nv_bfloat16* __restrict__ wlo)
{
    int i = blockIdx.x * 256 + threadIdx.x;
    if (i >= N4ALL) return;

    const float4* in;
    __nv_bfloat16 *hp, *lp;
    int idx;
    if (i < N4X) {
        in = x; hp = xhi; lp = xlo; idx = i;
    } else {
        int j = i - N4X;
        int w = j >> 18;
        idx = j & (N4W - 1);
        in = (w == 0) ? Wq : (w == 1) ? Wk : (w == 2) ? Wv : Wo;
        hp = whi + (size_t)w * WSZ;
        lp = wlo + (size_t)w * WSZ;
    }
    float4 v = in[idx];
    __nv_bfloat16 h0 = __float2bfloat16(v.x);
    __nv_bfloat16 h1 = __float2bfloat16(v.y);
    __nv_bfloat16 h2 = __float2bfloat16(v.z);
    __nv_bfloat16 h3 = __float2bfloat16(v.w);
    __nv_bfloat16 l0 = __float2bfloat16(v.x - __bfloat162float(h0));
    __nv_bfloat16 l1 = __float2bfloat16(v.y - __bfloat162float(h1));
    __nv_bfloat16 l2 = __float2bfloat16(v.z - __bfloat162float(h2));
    __nv_bfloat16 l3 = __float2bfloat16(v.w - __bfloat162float(h3));
    __nv_bfloat162* h2p = (__nv_bfloat162*)hp;
    __nv_bfloat162* l2p = (__nv_bfloat162*)lp;
    h2p[2 * idx + 0] = __halves2bfloat162(h0, h1);
    h2p[2 * idx + 1] = __halves2bfloat162(h2, h3);
    l2p[2 * idx + 0] = __halves2bfloat162(l0, l1);
    l2p[2 * idx + 1] = __halves2bfloat162(l2, l3);
}

// ---------------------------------------------------------------------------
// GEMM: 128x128 CTA tile, 4 warps (2x2) of 64x64, BK=32, 2-stage, 2 CTAs/SM
// ---------------------------------------------------------------------------
#define ROWB 80
#define TILE_B (128 * ROWB)
#define ST_AH 0
#define ST_AL (1 * TILE_B)
#define ST_BH (2 * TILE_B)
#define ST_BL (3 * TILE_B)
#define STAGE_B (4 * TILE_B)          // 40960
#define GEMM_SMEM (2 * STAGE_B)       // 81920
#define KITER (EMB / 32)              // 32

#define GEMM_MAINLOOP()                                                        \
    float acc[4][8][4];                                                        \
    _Pragma("unroll")                                                          \
    for (int i = 0; i < 4; i++)                                                \
        _Pragma("unroll")                                                      \
        for (int j = 0; j < 8; j++)                                            \
            _Pragma("unroll")                                                  \
            for (int k = 0; k < 4; k++) acc[i][j][k] = 0.0f;                   \
    const int a_row = wm * 64 + (lid & 15);                                    \
    const int a_kh  = (lid >> 4) * 16;                                         \
    const int b_row = wn * 64 + (lid & 7);                                     \
    const int b_kh  = ((lid >> 3) & 1) * 16;                                   \
    stage(0, 0);                                                               \
    _Pragma("unroll 1")                                                        \
    for (int kc = 0; kc < KITER; kc++) {                                       \
        CP_WAIT(0);                                                            \
        __syncthreads();                                                       \
        if (kc + 1 < KITER) stage((kc + 1) & 1, kc + 1);                       \
        const uint32_t bufb = sb + (kc & 1) * STAGE_B;                         \
        _Pragma("unroll")                                                      \
        for (int ks = 0; ks < 2; ks++) {                                       \
            const uint32_t kso = ks * 32;                                      \
            uint32_t ah[4][4], al[4][4];                                       \
            _Pragma("unroll")                                                  \
            for (int mi = 0; mi < 4; mi++) {                                   \
                uint32_t ra = (a_row + mi * 16) * ROWB + kso + a_kh;           \
                ldm_x4(ah[mi], bufb + ST_AH + ra);                             \
                ldm_x4(al[mi], bufb + ST_AL + ra);                             \
            }                                                                  \
            _Pragma("unroll")                                                  \
            for (int ni = 0; ni < 8; ni++) {                                   \
                uint32_t bhf[2], blf[2];                                       \
                uint32_t rb = (b_row + ni * 8) * ROWB + kso + b_kh;            \
                ldm_x2(bhf, bufb + ST_BH + rb);                                \
                ldm_x2(blf, bufb + ST_BL + rb);                                \
                _Pragma("unroll")                                              \
                for (int mi = 0; mi < 4; mi++) {                               \
                    mma_bf16(acc[mi][ni], ah[mi], bhf);                        \
                    mma_bf16(acc[mi][ni], ah[mi], blf);                        \
                    mma_bf16(acc[mi][ni], al[mi], bhf);                        \
                }                                                              \
            }                                                                  \
        }                                                                      \
    }

// staging for 128 threads: each thread 2 rows x 2 segs per array
#define GEMM_STAGE_LAMBDA()                                                    \
    auto stage = [&](int buf, int kc) {                                        \
        const uint32_t base = sb + buf * STAGE_B;                              \
        const int seg0 = (tid & 1) * 32;                                       \
        const int gcol0 = kc * 32 + (seg0 >> 1);                               \
        _Pragma("unroll")                                                      \
        for (int rr = 0; rr < 2; rr++) {                                       \
            int row = (tid >> 1) + rr * 64;                                    \
            _Pragma("unroll")                                                  \
            for (int t = 0; t < 2; t++) {                                      \
                uint32_t so = row * ROWB + seg0 + t * 16;                      \
                int gcol = gcol0 + t * 8;                                      \
                cp_async16(base + ST_AH + so, gA[0] + (size_t)row * EMB + gcol); \
                cp_async16(base + ST_AL + so, gA[1] + (size_t)row * EMB + gcol); \
                cp_async16(base + ST_BH + so, gB[0] + (size_t)row * EMB + gcol); \
                cp_async16(base + ST_BL + so, gB[1] + (size_t)row * EMB + gcol); \
            }                                                                  \
        }                                                                      \
        CP_COMMIT();                                                           \
    };

// fused QKV GEMM: grid (24, 64); bn>>3 selects {Q,K,V}
__global__ void __launch_bounds__(128, 2)
gemm_qkv(const __nv_bfloat16* __restrict__ Ahi, const __nv_bfloat16* __restrict__ Alo,
         const __nv_bfloat16* __restrict__ Whi, const __nv_bfloat16* __restrict__ Wlo,
         const float* __restrict__ bq, const float* __restrict__ bk,
         const float* __restrict__ bv,
         __nv_bfloat16* __restrict__ qhi, __nv_bfloat16* __restrict__ qlo,
         __nv_bfloat16* __restrict__ khi, __nv_bfloat16* __restrict__ klo,
         __nv_bfloat16* __restrict__ vhi, __nv_bfloat16* __restrict__ vlo)
{
    extern __shared__ char smem[];
    const uint32_t sb = smem_u32(smem);
    const int tid = threadIdx.x;
    const int wid = tid >> 5;
    const int lid = tid & 31;
    const int bn  = blockIdx.x;
    const int w   = bn >> 3;
    const int tm  = blockIdx.y * 128;
    const int tn  = (bn & 7) * 128;
    const int wm  = wid >> 1;          // 0..1
    const int wn  = wid & 1;           // 0..1

    const float* bias = (w == 0) ? bq : (w == 1) ? bk : bv;
    __nv_bfloat16* Chi = (w == 0) ? qhi : (w == 1) ? khi : vhi;
    __nv_bfloat16* Clo = (w == 0) ? qlo : (w == 1) ? klo : vlo;

    const __nv_bfloat16* gA[2] = { Ahi + (size_t)tm * EMB, Alo + (size_t)tm * EMB };
    const __nv_bfloat16* gB[2] = { Whi + (size_t)w * WSZ + (size_t)tn * EMB,
                                   Wlo + (size_t)w * WSZ + (size_t)tn * EMB };

    GEMM_STAGE_LAMBDA()
    GEMM_MAINLOOP()

    // epilogue: split bf16, scatter to [B,H,S,D]
    const int g   = lid >> 2;
    const int tig = lid & 3;
#pragma unroll
    for (int ni = 0; ni < 8; ni++) {
        const int n = tn + wn * 64 + ni * 8 + tig * 2;
        const float b0 = bias[n], b1 = bias[n + 1];
        const int hh = n >> 6, dd = n & 63;
#pragma unroll
        for (int mi = 0; mi < 4; mi++) {
#pragma unroll
            for (int half = 0; half < 2; half++) {
                int m = tm + wm * 64 + mi * 16 + g + half * 8;
                float vx = acc[mi][ni][half * 2 + 0] + b0;
                float vy = acc[mi][ni][half * 2 + 1] + b1;
                int bb = m >> 11, ss = m & 2047;
                size_t idx = (((size_t)(bb * NH + hh) * S_LEN) + ss) * HD + dd;
                __nv_bfloat16 hx = __float2bfloat16(vx);
                __nv_bfloat16 hy = __float2bfloat16(vy);
                __nv_bfloat16 lx = __float2bfloat16(vx - __bfloat162float(hx));
                __nv_bfloat16 ly = __float2bfloat16(vy - __bfloat162float(hy));
                *(__nv_bfloat162*)(Chi + idx) = __halves2bfloat162(hx, hy);
                *(__nv_bfloat162*)(Clo + idx) = __halves2bfloat162(lx, ly);
            }
        }
    }
}

// output projection GEMM: fp32 C row-major
__global__ void __launch_bounds__(128, 2)
gemm_out(const __nv_bfloat16* __restrict__ Ahi, const __nv_bfloat16* __restrict__ Alo,
         const __nv_bfloat16* __restrict__ Bhi, const __nv_bfloat16* __restrict__ Blo,
         const float* __restrict__ bias, float* __restrict__ C)
{
    extern __shared__ char smem[];
    const uint32_t sb = smem_u32(smem);
    const int tid = threadIdx.x;
    const int wid = tid >> 5;
    const int lid = tid & 31;
    const int tm  = blockIdx.y * 128;
    const int tn  = blockIdx.x * 128;
    const int wm  = wid >> 1;
    const int wn  = wid & 1;

    const __nv_bfloat16* gA[2] = { Ahi + (size_t)tm * EMB, Alo + (size_t)tm * EMB };
    const __nv_bfloat16* gB[2] = { Bhi + (size_t)tn * EMB, Blo + (size_t)tn * EMB };

    GEMM_STAGE_LAMBDA()
    GEMM_MAINLOOP()

    const int g   = lid >> 2;
    const int tig = lid & 3;
#pragma unroll
    for (int ni = 0; ni < 8; ni++) {
        const int n = tn + wn * 64 + ni * 8 + tig * 2;
        const float b0 = bias[n], b1 = bias[n + 1];
#pragma unroll
        for (int mi = 0; mi < 4; mi++) {
#pragma unroll
            for (int half = 0; half < 2; half++) {
                int m = tm + wm * 64 + mi * 16 + g + half * 8;
                float2 v;
                v.x = acc[mi][ni][half * 2 + 0] + b0;
                v.y = acc[mi][ni][half * 2 + 1] + b1;
                *(float2*)(C + (size_t)m * EMB + n) = v;
            }
        }
    }
}

// ---------------------------------------------------------------------------
// Flash attention: 4 warps x 32 q-rows, Q persistent smem, 2-stage KV, 2 CTAs/SM
// ---------------------------------------------------------------------------
#define FROWB 144
#define FQ_H  0                       // 128*144 = 18432
#define FQ_L  18432
#define F_KH  0
#define F_KL  9216
#define F_VH  18432
#define F_VL  27648
#define F_STAGE 36864
#define F_STG0 36864
#define FLASH_SMEM (F_STG0 + 2 * F_STAGE)   // 110592
#define NCHUNK (S_LEN / 64)           // 32

__global__ void __launch_bounds__(128, 2)
flash_mma(const __nv_bfloat16* __restrict__ Qhi, const __nv_bfloat16* __restrict__ Qlo,
          const __nv_bfloat16* __restrict__ Khi, const __nv_bfloat16* __restrict__ Klo,
          const __nv_bfloat16* __restrict__ Vhi, const __nv_bfloat16* __restrict__ Vlo,
          __nv_bfloat16* __restrict__ Ohi, __nv_bfloat16* __restrict__ Olo)
{
    extern __shared__ char smem[];
    const uint32_t sb = smem_u32(smem);
    const int tid = threadIdx.x;
    const int wid = tid >> 5;          // 0..3
    const int lid = tid & 31;
    const int bh  = blockIdx.y;
    const int b   = bh >> 4;
    const int h   = bh & 15;
    const int q0  = blockIdx.x * 128;

    const __nv_bfloat16* Qh_g = Qhi + ((size_t)bh * S_LEN + q0) * HD;
    const __nv_bfloat16* Ql_g = Qlo + ((size_t)bh * S_LEN + q0) * HD;
    const __nv_bfloat16* Kh_g = Khi + (size_t)bh * S_LEN * HD;
    const __nv_bfloat16* Kl_g = Klo + (size_t)bh * S_LEN * HD;
    const __nv_bfloat16* Vh_g = Vhi + (size_t)bh * S_LEN * HD;
    const __nv_bfloat16* Vl_g = Vlo + (size_t)bh * S_LEN * HD;

    // ---- KV staging (128 threads: 4 segs/row, 2 threads/row, 4 arrays) ----
    const int s_row = tid >> 1;        // 0..63
    const int s_sg0 = (tid & 1) * 4;
    auto stage = [&](int c) {
        const uint32_t base = sb + F_STG0 + (c & 1) * F_STAGE;
        const size_t gbase = (size_t)(c * 64 + s_row) * HD;
#pragma unroll
        for (int t = 0; t < 4; t++) {
            int seg = s_sg0 + t;
            uint32_t so = s_row * FROWB + seg * 16;
            const size_t go = gbase + seg * 8;
            cp_async16(base + F_KH + so, Kh_g + go);
            cp_async16(base + F_KL + so, Kl_g + go);
            cp_async16(base + F_VH + so, Vh_g + go);
            cp_async16(base + F_VL + so, Vl_g + go);
        }
        CP_COMMIT();
    };

    stage(0);   // prefetch first KV chunk, overlaps Q staging below

    // ---- stage Q (128 x 64) hi/lo into persistent smem ----
    {
        int row = tid;
#pragma unroll
        for (int t = 0; t < 8; t++) {
            *(uint4*)(smem + FQ_H + row * FROWB + t * 16) =
                *(const uint4*)(Qh_g + (size_t)row * HD + t * 8);
            *(uint4*)(smem + FQ_L + row * FROWB + t * 16) =
                *(const uint4*)(Ql_g + (size_t)row * HD + t * 8);
        }
    }
    __syncthreads();

    float o[2][8][4];
#pragma unroll
    for (int mi = 0; mi < 2; mi++)
#pragma unroll
        for (int ni = 0; ni < 8; ni++)
#pragma unroll
            for (int j = 0; j < 4; j++) o[mi][ni][j] = 0.0f;
    float mrun[2][2], lrun[2][2];
#pragma unroll
    for (int mi = 0; mi < 2; mi++)
        for (int hf = 0; hf < 2; hf++) { mrun[mi][hf] = -1e30f; lrun[mi][hf] = 0.0f; }

    const int a_row = wid * 32 + (lid & 15);
    const int a_kh  = (lid >> 4) * 16;
    const int b_row = lid & 7;
    const int b_kh  = ((lid >> 3) & 1) * 16;
    const int v_row = lid & 15;

#pragma unroll 1
    for (int c = 0; c < NCHUNK; c++) {
        CP_WAIT(0);
        __syncthreads();
        if (c + 1 < NCHUNK) stage(c + 1);
        const uint32_t bufb = sb + F_STG0 + (c & 1) * F_STAGE;

        // ---- scores: S = Qh·Kh + Qh·Kl + Ql·Kh ----
        float sc[2][8][4];
#pragma unroll
        for (int mi = 0; mi < 2; mi++)
#pragma unroll
            for (int ni = 0; ni < 8; ni++)
#pragma unroll
                for (int j = 0; j < 4; j++) sc[mi][ni][j] = 0.0f;

#pragma unroll
        for (int ks = 0; ks < 4; ks++) {
            uint32_t qh4[2][4], ql4[2][4];
#pragma unroll
            for (int mi = 0; mi < 2; mi++) {
                uint32_t ra = (a_row + mi * 16) * FROWB + ks * 32 + a_kh;
                ldm_x4(qh4[mi], sb + FQ_H + ra);
                ldm_x4(ql4[mi], sb + FQ_L + ra);
            }
            const uint32_t kso = ks * 32 + b_kh;
#pragma unroll
            for (int ni = 0; ni < 8; ni++) {
                uint32_t kh[2], kl[2];
                uint32_t rb = (ni * 8 + b_row) * FROWB + kso;
                ldm_x2(kh, bufb + F_KH + rb);
                ldm_x2(kl, bufb + F_KL + rb);
#pragma unroll
                for (int mi = 0; mi < 2; mi++) {
                    mma_bf16(sc[mi][ni], qh4[mi], kh);
                    mma_bf16(sc[mi][ni], qh4[mi], kl);
                    mma_bf16(sc[mi][ni], ql4[mi], kh);
                }
            }
        }

        // ---- online softmax (per mi) ----
#pragma unroll
        for (int mi = 0; mi < 2; mi++) {
            float mx0 = -1e30f, mx1 = -1e30f;
#pragma unroll
            for (int ni = 0; ni < 8; ni++) {
                mx0 = fmaxf(mx0, fmaxf(sc[mi][ni][0], sc[mi][ni][1]));
                mx1 = fmaxf(mx1, fmaxf(sc[mi][ni][2], sc[mi][ni][3]));
            }
            mx0 *= 0.125f; mx1 *= 0.125f;
            mx0 = fmaxf(mx0, __shfl_xor_sync(~0u, mx0, 1));
            mx0 = fmaxf(mx0, __shfl_xor_sync(~0u, mx0, 2));
            mx1 = fmaxf(mx1, __shfl_xor_sync(~0u, mx1, 1));
            mx1 = fmaxf(mx1, __shfl_xor_sync(~0u, mx1, 2));
            float mn0 = fmaxf(mrun[mi][0], mx0), mn1 = fmaxf(mrun[mi][1], mx1);
            float corr0 = __expf(mrun[mi][0] - mn0), corr1 = __expf(mrun[mi][1] - mn1);
            mrun[mi][0] = mn0; mrun[mi][1] = mn1;

            float s0 = 0.0f, s1 = 0.0f;
#pragma unroll
            for (int ni = 0; ni < 8; ni++) {
                sc[mi][ni][0] = __expf(fmaf(sc[mi][ni][0], 0.125f, -mn0));
                sc[mi][ni][1] = __expf(fmaf(sc[mi][ni][1], 0.125f, -mn0));
                sc[mi][ni][2] = __expf(fmaf(sc[mi][ni][2], 0.125f, -mn1));
                sc[mi][ni][3] = __expf(fmaf(sc[mi][ni][3], 0.125f, -mn1));
                s0 += sc[mi][ni][0] + sc[mi][ni][1];
                s1 += sc[mi][ni][2] + sc[mi][ni][3];
            }
            s0 += __shfl_xor_sync(~0u, s0, 1);
            s0 += __shfl_xor_sync(~0u, s0, 2);
            s1 += __shfl_xor_sync(~0u, s1, 1);
            s1 += __shfl_xor_sync(~0u, s1, 2);
            lrun[mi][0] = lrun[mi][0] * corr0 + s0;
            lrun[mi][1] = lrun[mi][1] * corr1 + s1;

#pragma unroll
            for (int ni = 0; ni < 8; ni++) {
                o[mi][ni][0] *= corr0; o[mi][ni][1] *= corr0;
                o[mi][ni][2] *= corr1; o[mi][ni][3] *= corr1;
            }
        }

        // ---- pack P into A-fragments (hi/lo) per mi ----
        uint32_t ph[2][4][4], pl[2][4][4];
#pragma unroll
        for (int mi = 0; mi < 2; mi++) {
#pragma unroll
            for (int kk = 0; kk < 4; kk++) {
                float p00 = sc[mi][2 * kk][0],     p01 = sc[mi][2 * kk][1];
                float p02 = sc[mi][2 * kk][2],     p03 = sc[mi][2 * kk][3];
                float p10 = sc[mi][2 * kk + 1][0], p11 = sc[mi][2 * kk + 1][1];
                float p12 = sc[mi][2 * kk + 1][2], p13 = sc[mi][2 * kk + 1][3];
                __nv_bfloat16 h00 = __float2bfloat16(p00), h01 = __float2bfloat16(p01);
                __nv_bfloat16 h02 = __float2bfloat16(p02), h03 = __float2bfloat16(p03);
                __nv_bfloat16 h10 = __float2bfloat16(p10), h11 = __float2bfloat16(p11);
                __nv_bfloat16 h12 = __float2bfloat16(p12), h13 = __float2bfloat16(p13);
                ph[mi][kk][0] = pack_bf16x2(p00, p01);
                ph[mi][kk][1] = pack_bf16x2(p02, p03);
                ph[mi][kk][2] = pack_bf16x2(p10, p11);
                ph[mi][kk][3] = pack_bf16x2(p12, p13);
                pl[mi][kk][0] = pack_bf16x2(p00 - __bfloat162float(h00), p01 - __bfloat162float(h01));
                pl[mi][kk][1] = pack_bf16x2(p02 - __bfloat162float(h02), p03 - __bfloat162float(h03));
                pl[mi][kk][2] = pack_bf16x2(p10 - __bfloat162float(h10), p11 - __bfloat162float(h11));
                pl[mi][kk][3] = pack_bf16x2(p12 - __bfloat162float(h12), p13 - __bfloat162float(h13));
            }
        }

        // ---- O += Ph·Vh + Ph·Vl + Pl·Vh ----
#pragma unroll
        for (int ks = 0; ks < 4; ks++) {
#pragma unroll
            for (int ni = 0; ni < 8; ni++) {
                uint32_t vh[2], vl[2];
                uint32_t rv = (ks * 16 + v_row) * FROWB + ni * 16;
                ldm_x2_t(vh, bufb + F_VH + rv);
                ldm_x2_t(vl, bufb + F_VL + rv);
#pragma unroll
                for (int mi = 0; mi < 2; mi++) {
                    mma_bf16(o[mi][ni], ph[mi][ks], vh);
                    mma_bf16(o[mi][ni], ph[mi][ks], vl);
                    mma_bf16(o[mi][ni], pl[mi][ks], vh);
                }
            }
        }
    }

    // ---- epilogue ----
    const int g   = lid >> 2;
    const int tig = lid & 3;
#pragma unroll
    for (int mi = 0; mi < 2; mi++) {
#pragma unroll
        for (int half = 0; half < 2; half++) {
            int s = q0 + wid * 32 + mi * 16 + g + half * 8;
            float inv = 1.0f / lrun[mi][half];
            size_t rowbase = ((size_t)(b * S_LEN + s)) * EMB + h * HD;
#pragma unroll
            for (int ni = 0; ni < 8; ni++) {
                float vx = o[mi][ni][half * 2 + 0] * inv;
                float vy = o[mi][ni][half * 2 + 1] * inv;
                __nv_bfloat16 hx = __float2bfloat16(vx);
                __nv_bfloat16 hy = __float2bfloat16(vy);
                __nv_bfloat16 lx = __float2bfloat16(vx - __bfloat162float(hx));
                __nv_bfloat16 ly = __float2bfloat16(vy - __bfloat162float(hy));
                size_t idx = rowbase + ni * 8 + tig * 2;
                *(__nv_bfloat162*)(Ohi + idx) = __halves2bfloat162(hx, hy);
                *(__nv_bfloat162*)(Olo + idx) = __halves2bfloat162(lx, ly);
            }
        }
    }
}

// ---------------------------------------------------------------------------
// Launch
// ---------------------------------------------------------------------------
extern "C" void kernel_launch(void* const* d_in, const int* in_sizes, int n_in,
                              void* d_out, int out_size)
{
    const float* x  = (const float*)d_in[0];
    const float* Wq = (const float*)d_in[1];
    const float* bq = (const float*)d_in[2];
    const float* Wk = (const float*)d_in[3];
    const float* bk = (const float*)d_in[4];
    const float* Wv = (const float*)d_in[5];
    const float* bv = (const float*)d_in[6];
    const float* Wo = (const float*)d_in[7];
    const float* bo = (const float*)d_in[8];
    float* out = (float*)d_out;

    __nv_bfloat16 *xhi, *xlo, *whi, *wlo, *ahi, *alo;
    __nv_bfloat16 *qhi, *qlo, *khi, *klo, *vhi, *vlo;
    cudaGetSymbolAddress((void**)&xhi, g_xhi);
    cudaGetSymbolAddress((void**)&xlo, g_xlo);
    cudaGetSymbolAddress((void**)&whi, g_whi);
    cudaGetSymbolAddress((void**)&wlo, g_wlo);
    cudaGetSymbolAddress((void**)&ahi, g_ahi);
    cudaGetSymbolAddress((void**)&alo, g_alo);
    cudaGetSymbolAddress((void**)&qhi, g_qhi);
    cudaGetSymbolAddress((void**)&qlo, g_qlo);
    cudaGetSymbolAddress((void**)&khi, g_khi);
    cudaGetSymbolAddress((void**)&klo, g_klo);
    cudaGetSymbolAddress((void**)&vhi, g_vhi);
    cudaGetSymbolAddress((void**)&vlo, g_vlo);

    cudaFuncSetAttribute(gemm_qkv, cudaFuncAttributeMaxDynamicSharedMemorySize, GEMM_SMEM);
    cudaFuncSetAttribute(gemm_out, cudaFuncAttributeMaxDynamicSharedMemorySize, GEMM_SMEM);
    cudaFuncSetAttribute(flash_mma, cudaFuncAttributeMaxDynamicSharedMemorySize, FLASH_SMEM);

    convert_all<<<(N4ALL + 255) / 256, 256>>>((const float4*)x,
        (const float4*)Wq, (const float4*)Wk, (const float4*)Wv, (const float4*)Wo,
        xhi, xlo, whi, wlo);

    dim3 gq(24, M_TOT / 128);          // fused QKV
    gemm_qkv<<<gq, 128, GEMM_SMEM>>>(xhi, xlo, whi, wlo, bq, bk, bv,
                                     qhi, qlo, khi, klo, vhi, vlo);

    dim3 ga(S_LEN / 128, BH);          // (16, 64)
    flash_mma<<<ga, 128, FLASH_SMEM>>>(qhi, qlo, khi, klo, vhi, vlo, ahi, alo);

    dim3 gg(EMB / 128, M_TOT / 128);   // (8, 64)
    gemm_out<<<gg, 128, GEMM_SMEM>>>(ahi, alo, whi + 3 * WSZ, wlo + 3 * WSZ, bo, out);
}

// round 9
// speedup vs baseline: 1.0405x; 1.0405x over previous
#include <cuda_runtime.h>
#include <cuda_bf16.h>
#include <cstdint>

#define BATCH 4
#define S_LEN 2048
#define EMB   1024
#define NH    16
#define HD    64
#define M_TOT (BATCH * S_LEN)   // 8192
#define BH    (BATCH * NH)      // 64
#define WSZ   ((size_t)EMB * EMB)

// ---------------------------------------------------------------------------
// Scratch (device globals — no allocation allowed)
// ---------------------------------------------------------------------------
__device__ __nv_bfloat16 g_xhi[(size_t)M_TOT * EMB];
__device__ __nv_bfloat16 g_xlo[(size_t)M_TOT * EMB];
__device__ __nv_bfloat16 g_whi[4][WSZ];
__device__ __nv_bfloat16 g_wlo[4][WSZ];
__device__ __nv_bfloat16 g_qhi[(size_t)BH * S_LEN * HD];
__device__ __nv_bfloat16 g_qlo[(size_t)BH * S_LEN * HD];
__device__ __nv_bfloat16 g_khi[(size_t)BH * S_LEN * HD];
__device__ __nv_bfloat16 g_klo[(size_t)BH * S_LEN * HD];
__device__ __nv_bfloat16 g_vhi[(size_t)BH * S_LEN * HD];
__device__ __nv_bfloat16 g_vlo[(size_t)BH * S_LEN * HD];
__device__ __nv_bfloat16 g_ahi[(size_t)M_TOT * EMB];
__device__ __nv_bfloat16 g_alo[(size_t)M_TOT * EMB];

// ---------------------------------------------------------------------------
// helpers
// ---------------------------------------------------------------------------
__device__ __forceinline__ uint32_t smem_u32(const void* p) {
    uint32_t a;
    asm("{ .reg .u64 t; cvta.to.shared.u64 t, %1; cvt.u32.u64 %0, t; }"
        : "=r"(a) : "l"(p));
    return a;
}
__device__ __forceinline__ void cp_async16(uint32_t dst, const void* src) {
    asm volatile("cp.async.cg.shared.global [%0], [%1], 16;"
                 :: "r"(dst), "l"(__cvta_generic_to_global(src)) : "memory");
}
#define CP_COMMIT()  asm volatile("cp.async.commit_group;" ::: "memory")
#define CP_WAIT(n)   asm volatile("cp.async.wait_group %0;" :: "n"(n) : "memory")

__device__ __forceinline__ void ldm_x4(uint32_t* r, uint32_t addr) {
    asm volatile("ldmatrix.sync.aligned.m8n8.x4.shared.b16 {%0,%1,%2,%3}, [%4];"
                 : "=r"(r[0]), "=r"(r[1]), "=r"(r[2]), "=r"(r[3]) : "r"(addr));
}
__device__ __forceinline__ void ldm_x2(uint32_t* r, uint32_t addr) {
    asm volatile("ldmatrix.sync.aligned.m8n8.x2.shared.b16 {%0,%1}, [%2];"
                 : "=r"(r[0]), "=r"(r[1]) : "r"(addr));
}
__device__ __forceinline__ void ldm_x2_t(uint32_t* r, uint32_t addr) {
    asm volatile("ldmatrix.sync.aligned.m8n8.x2.trans.shared.b16 {%0,%1}, [%2];"
                 : "=r"(r[0]), "=r"(r[1]) : "r"(addr));
}
__device__ __forceinline__ void mma_bf16(float* c, const uint32_t* a, const uint32_t* b) {
    asm volatile(
        "mma.sync.aligned.m16n8k16.row.col.f32.bf16.bf16.f32 "
        "{%0,%1,%2,%3}, {%4,%5,%6,%7}, {%8,%9}, {%0,%1,%2,%3};"
        : "+f"(c[0]), "+f"(c[1]), "+f"(c[2]), "+f"(c[3])
        : "r"(a[0]), "r"(a[1]), "r"(a[2]), "r"(a[3]), "r"(b[0]), "r"(b[1]));
}
__device__ __forceinline__ uint32_t pack_bf16x2(float lo, float hi) {
    uint32_t r;
    asm("cvt.rn.bf16x2.f32 %0, %1, %2;" : "=r"(r) : "f"(hi), "f"(lo));
    return r;
}
// swizzle for 64B rows (4 x 16B chunks): chunk c XOR bits of row
__device__ __forceinline__ uint32_t sw64(int row, int c) {
    return (uint32_t)(row * 64 + (((c) ^ ((row >> 1) & 3)) << 4));
}
// standard SW128 for 128B rows
__device__ __forceinline__ uint32_t sw128(uint32_t off) {
    return off ^ ((off >> 3) & 0x70);
}

// ---------------------------------------------------------------------------
// single fused convert: x + 4 weights -> bf16 hi/lo
// ---------------------------------------------------------------------------
#define N4X (M_TOT * EMB / 4)
#define N4W (EMB * EMB / 4)
#define N4ALL (N4X + 4 * N4W)

__global__ void __launch_bounds__(256)
convert_all(const float4* __restrict__ x,
            const float4* __restrict__ Wq, const float4* __restrict__ Wk,
            const float4* __restrict__ Wv, const float4* __restrict__ Wo,
            __nv_bfloat16* __restrict__ xhi, __nv_bfloat16* __restrict__ xlo,
            __nv_bfloat16* __restrict__ whi, __nv_bfloat16* __restrict__ wlo)
{
    int i = blockIdx.x * 256 + threadIdx.x;
    if (i >= N4ALL) return;

    const float4* in;
    __nv_bfloat16 *hp, *lp;
    int idx;
    if (i < N4X) {
        in = x; hp = xhi; lp = xlo; idx = i;
    } else {
        int j = i - N4X;
        int w = j >> 18;
        idx = j & (N4W - 1);
        in = (w == 0) ? Wq : (w == 1) ? Wk : (w == 2) ? Wv : Wo;
        hp = whi + (size_t)w * WSZ;
        lp = wlo + (size_t)w * WSZ;
    }
    float4 v = in[idx];
    __nv_bfloat16 h0 = __float2bfloat16(v.x);
    __nv_bfloat16 h1 = __float2bfloat16(v.y);
    __nv_bfloat16 h2 = __float2bfloat16(v.z);
    __nv_bfloat16 h3 = __float2bfloat16(v.w);
    __nv_bfloat16 l0 = __float2bfloat16(v.x - __bfloat162float(h0));
    __nv_bfloat16 l1 = __float2bfloat16(v.y - __bfloat162float(h1));
    __nv_bfloat16 l2 = __float2bfloat16(v.z - __bfloat162float(h2));
    __nv_bfloat16 l3 = __float2bfloat16(v.w - __bfloat162float(h3));
    __nv_bfloat162* h2p = (__nv_bfloat162*)hp;
    __nv_bfloat162* l2p = (__nv_bfloat162*)lp;
    h2p[2 * idx + 0] = __halves2bfloat162(h0, h1);
    h2p[2 * idx + 1] = __halves2bfloat162(h2, h3);
    l2p[2 * idx + 0] = __halves2bfloat162(l0, l1);
    l2p[2 * idx + 1] = __halves2bfloat162(l2, l3);
}

// ---------------------------------------------------------------------------
// GEMM: 128x128 CTA tile, 8 warps (2m x 4n) of 64x32, BK=32,
//       swizzled 64B rows, 3-stage cp.async (distance 2), 2 CTAs/SM
// ---------------------------------------------------------------------------
#define TILE_B 8192                    // 128 rows * 64B
#define ST_AH 0
#define ST_AL (1 * TILE_B)
#define ST_BH (2 * TILE_B)
#define ST_BL (3 * TILE_B)
#define STAGE_B (4 * TILE_B)           // 32768
#define GEMM_SMEM (3 * STAGE_B)        // 98304 (x2 CTAs = 196K)
#define KITER (EMB / 32)               // 32

#define GEMM_MAINLOOP()                                                        \
    float acc[4][4][4];                                                        \
    _Pragma("unroll")                                                          \
    for (int i = 0; i < 4; i++)                                                \
        _Pragma("unroll")                                                      \
        for (int j = 0; j < 4; j++)                                            \
            _Pragma("unroll")                                                  \
            for (int k = 0; k < 4; k++) acc[i][j][k] = 0.0f;                   \
    const int a_row = wm * 64 + (lid & 15);                                    \
    const int a_c   = (lid >> 4);       /* extra chunk for k-half */           \
    const int b_row = wn * 32 + (lid & 7);                                     \
    const int b_c   = ((lid >> 3) & 1);                                        \
    stage(0, 0); stage(1, 1);                                                  \
    _Pragma("unroll 1")                                                        \
    for (int kc = 0; kc < KITER; kc++) {                                       \
        if (kc + 1 < KITER) { CP_WAIT(1); } else { CP_WAIT(0); }               \
        __syncthreads();                                                       \
        if (kc + 2 < KITER) stage((kc + 2) % 3, kc + 2);                       \
        const uint32_t bufb = sb + (kc % 3) * STAGE_B;                         \
        _Pragma("unroll")                                                      \
        for (int ks = 0; ks < 2; ks++) {                                       \
            const int kc0 = ks * 2;                                            \
            uint32_t ah[4][4], al[4][4], bhf[4][2], blf[4][2];                 \
            _Pragma("unroll")                                                  \
            for (int mi = 0; mi < 4; mi++) {                                   \
                uint32_t ra = sw64(a_row + mi * 16, kc0 + a_c);                \
                ldm_x4(ah[mi], bufb + ST_AH + ra);                             \
                ldm_x4(al[mi], bufb + ST_AL + ra);                             \
            }                                                                  \
            _Pragma("unroll")                                                  \
            for (int ni = 0; ni < 4; ni++) {                                   \
                uint32_t rb = sw64(b_row + ni * 8, kc0 + b_c);                 \
                ldm_x2(bhf[ni], bufb + ST_BH + rb);                            \
                ldm_x2(blf[ni], bufb + ST_BL + rb);                            \
            }                                                                  \
            _Pragma("unroll")                                                  \
            for (int mi = 0; mi < 4; mi++)                                     \
                _Pragma("unroll")                                              \
                for (int ni = 0; ni < 4; ni++) {                               \
                    mma_bf16(acc[mi][ni], ah[mi], bhf[ni]);                    \
                    mma_bf16(acc[mi][ni], ah[mi], blf[ni]);                    \
                    mma_bf16(acc[mi][ni], al[mi], bhf[ni]);                    \
                }                                                              \
        }                                                                      \
    }

// staging for 256 threads: thread -> row = tid>>1, chunks c = (tid&1)*2 + {0,1}
#define GEMM_STAGE_LAMBDA()                                                    \
    auto stage = [&](int buf, int kc) {                                        \
        const uint32_t base = sb + buf * STAGE_B;                              \
        const int row = tid >> 1;                                              \
        _Pragma("unroll")                                                      \
        for (int t = 0; t < 2; t++) {                                          \
            int c = (tid & 1) * 2 + t;                                         \
            uint32_t so = sw64(row, c);                                        \
            int gcol = kc * 32 + c * 8;                                        \
            cp_async16(base + ST_AH + so, gA[0] + (size_t)row * EMB + gcol);   \
            cp_async16(base + ST_AL + so, gA[1] + (size_t)row * EMB + gcol);   \
            cp_async16(base + ST_BH + so, gB[0] + (size_t)row * EMB + gcol);   \
            cp_async16(base + ST_BL + so, gB[1] + (size_t)row * EMB + gcol);   \
        }                                                                      \
        CP_COMMIT();                                                           \
    };

// fused QKV GEMM: grid (24, 64); bn>>3 selects {Q,K,V}
__global__ void __launch_bounds__(256, 2)
gemm_qkv(const __nv_bfloat16* __restrict__ Ahi, const __nv_bfloat16* __restrict__ Alo,
         const __nv_bfloat16* __restrict__ Whi, const __nv_bfloat16* __restrict__ Wlo,
         const float* __restrict__ bq, const float* __restrict__ bk,
         const float* __restrict__ bv,
         __nv_bfloat16* __restrict__ qhi, __nv_bfloat16* __restrict__ qlo,
         __nv_bfloat16* __restrict__ khi, __nv_bfloat16* __restrict__ klo,
         __nv_bfloat16* __restrict__ vhi, __nv_bfloat16* __restrict__ vlo)
{
    extern __shared__ char smem[];
    const uint32_t sb = smem_u32(smem);
    const int tid = threadIdx.x;
    const int wid = tid >> 5;
    const int lid = tid & 31;
    const int bn  = blockIdx.x;
    const int w   = bn >> 3;
    const int tm  = blockIdx.y * 128;
    const int tn  = (bn & 7) * 128;
    const int wm  = wid >> 2;          // 0..1
    const int wn  = wid & 3;           // 0..3

    const float* bias = (w == 0) ? bq : (w == 1) ? bk : bv;
    __nv_bfloat16* Chi = (w == 0) ? qhi : (w == 1) ? khi : vhi;
    __nv_bfloat16* Clo = (w == 0) ? qlo : (w == 1) ? klo : vlo;

    const __nv_bfloat16* gA[2] = { Ahi + (size_t)tm * EMB, Alo + (size_t)tm * EMB };
    const __nv_bfloat16* gB[2] = { Whi + (size_t)w * WSZ + (size_t)tn * EMB,
                                   Wlo + (size_t)w * WSZ + (size_t)tn * EMB };

    GEMM_STAGE_LAMBDA()
    GEMM_MAINLOOP()

    // epilogue: split bf16, scatter to [B,H,S,D]
    const int g   = lid >> 2;
    const int tig = lid & 3;
#pragma unroll
    for (int ni = 0; ni < 4; ni++) {
        const int n = tn + wn * 32 + ni * 8 + tig * 2;
        const float b0 = bias[n], b1 = bias[n + 1];
        const int hh = n >> 6, dd = n & 63;
#pragma unroll
        for (int mi = 0; mi < 4; mi++) {
#pragma unroll
            for (int half = 0; half < 2; half++) {
                int m = tm + wm * 64 + mi * 16 + g + half * 8;
                float vx = acc[mi][ni][half * 2 + 0] + b0;
                float vy = acc[mi][ni][half * 2 + 1] + b1;
                int bb = m >> 11, ss = m & 2047;
                size_t idx = (((size_t)(bb * NH + hh) * S_LEN) + ss) * HD + dd;
                __nv_bfloat16 hx = __float2bfloat16(vx);
                __nv_bfloat16 hy = __float2bfloat16(vy);
                __nv_bfloat16 lx = __float2bfloat16(vx - __bfloat162float(hx));
                __nv_bfloat16 ly = __float2bfloat16(vy - __bfloat162float(hy));
                *(__nv_bfloat162*)(Chi + idx) = __halves2bfloat162(hx, hy);
                *(__nv_bfloat162*)(Clo + idx) = __halves2bfloat162(lx, ly);
            }
        }
    }
}

// output projection GEMM: fp32 C row-major
__global__ void __launch_bounds__(256, 2)
gemm_out(const __nv_bfloat16* __restrict__ Ahi, const __nv_bfloat16* __restrict__ Alo,
         const __nv_bfloat16* __restrict__ Bhi, const __nv_bfloat16* __restrict__ Blo,
         const float* __restrict__ bias, float* __restrict__ C)
{
    extern __shared__ char smem[];
    const uint32_t sb = smem_u32(smem);
    const int tid = threadIdx.x;
    const int wid = tid >> 5;
    const int lid = tid & 31;
    const int tm  = blockIdx.y * 128;
    const int tn  = blockIdx.x * 128;
    const int wm  = wid >> 2;
    const int wn  = wid & 3;

    const __nv_bfloat16* gA[2] = { Ahi + (size_t)tm * EMB, Alo + (size_t)tm * EMB };
    const __nv_bfloat16* gB[2] = { Bhi + (size_t)tn * EMB, Blo + (size_t)tn * EMB };

    GEMM_STAGE_LAMBDA()
    GEMM_MAINLOOP()

    const int g   = lid >> 2;
    const int tig = lid & 3;
#pragma unroll
    for (int ni = 0; ni < 4; ni++) {
        const int n = tn + wn * 32 + ni * 8 + tig * 2;
        const float b0 = bias[n], b1 = bias[n + 1];
#pragma unroll
        for (int mi = 0; mi < 4; mi++) {
#pragma unroll
            for (int half = 0; half < 2; half++) {
                int m = tm + wm * 64 + mi * 16 + g + half * 8;
                float2 v;
                v.x = acc[mi][ni][half * 2 + 0] + b0;
                v.y = acc[mi][ni][half * 2 + 1] + b1;
                *(float2*)(C + (size_t)m * EMB + n) = v;
            }
        }
    }
}

// ---------------------------------------------------------------------------
// Flash attention: 8 warps x 16 q-rows, Q persistent smem (SW128),
//                  2-stage KV (SW128), 2 CTAs/SM
// ---------------------------------------------------------------------------
#define FQ_H  0                        // 128 rows * 128B = 16384
#define FQ_L  16384
#define F_KH  0
#define F_KL  8192                     // 64 rows * 128B
#define F_VH  16384
#define F_VL  24576
#define F_STAGE 32768
#define F_STG0 32768                   // KV stages after Q region (32768)
#define FLASH_SMEM (F_STG0 + 2 * F_STAGE)   // 98304
#define NCHUNK (S_LEN / 64)            // 32

__global__ void __launch_bounds__(256, 2)
flash_mma(const __nv_bfloat16* __restrict__ Qhi, const __nv_bfloat16* __restrict__ Qlo,
          const __nv_bfloat16* __restrict__ Khi, const __nv_bfloat16* __restrict__ Klo,
          const __nv_bfloat16* __restrict__ Vhi, const __nv_bfloat16* __restrict__ Vlo,
          __nv_bfloat16* __restrict__ Ohi, __nv_bfloat16* __restrict__ Olo)
{
    extern __shared__ char smem[];
    const uint32_t sb = smem_u32(smem);
    const int tid = threadIdx.x;
    const int wid = tid >> 5;
    const int lid = tid & 31;
    const int bh  = blockIdx.y;
    const int b   = bh >> 4;
    const int h   = bh & 15;
    const int q0  = blockIdx.x * 128;

    const __nv_bfloat16* Qh_g = Qhi + ((size_t)bh * S_LEN + q0) * HD;
    const __nv_bfloat16* Ql_g = Qlo + ((size_t)bh * S_LEN + q0) * HD;
    const __nv_bfloat16* Kh_g = Khi + (size_t)bh * S_LEN * HD;
    const __nv_bfloat16* Kl_g = Klo + (size_t)bh * S_LEN * HD;
    const __nv_bfloat16* Vh_g = Vhi + (size_t)bh * S_LEN * HD;
    const __nv_bfloat16* Vl_g = Vlo + (size_t)bh * S_LEN * HD;

    // ---- KV staging: row = tid>>2 (0..63), chunks c = (tid&3)*2 + {0,1} ----
    const int s_row = tid >> 2;
    auto stage = [&](int c) {
        const uint32_t base = sb + F_STG0 + (c & 1) * F_STAGE;
        const size_t gbase = (size_t)(c * 64 + s_row) * HD;
#pragma unroll
        for (int t = 0; t < 2; t++) {
            int seg = (tid & 3) * 2 + t;
            uint32_t so = sw128((uint32_t)(s_row * 128 + seg * 16));
            const size_t go = gbase + seg * 8;
            cp_async16(base + F_KH + so, Kh_g + go);
            cp_async16(base + F_KL + so, Kl_g + go);
            cp_async16(base + F_VH + so, Vh_g + go);
            cp_async16(base + F_VL + so, Vl_g + go);
        }
        CP_COMMIT();
    };

    stage(0);   // prefetch first KV chunk, overlaps Q staging below

    // ---- stage Q (128 x 64) hi/lo into persistent swizzled smem ----
    {
        int row = tid >> 1;
#pragma unroll
        for (int t = 0; t < 4; t++) {
            int seg = (tid & 1) * 4 + t;
            uint32_t so = sw128((uint32_t)(row * 128 + seg * 16));
            *(uint4*)(smem + FQ_H + so) = *(const uint4*)(Qh_g + (size_t)row * HD + seg * 8);
            *(uint4*)(smem + FQ_L + so) = *(const uint4*)(Ql_g + (size_t)row * HD + seg * 8);
        }
    }
    __syncthreads();

    float o[8][4];
#pragma unroll
    for (int ni = 0; ni < 8; ni++)
#pragma unroll
        for (int j = 0; j < 4; j++) o[ni][j] = 0.0f;
    float m0 = -1e30f, m1 = -1e30f, l0 = 0.0f, l1 = 0.0f;

    const int a_row = wid * 16 + (lid & 15);
    const int a_c   = (lid >> 4);
    const int b_row = lid & 7;
    const int b_c   = ((lid >> 3) & 1);
    const int v_row = lid & 15;

#pragma unroll 1
    for (int c = 0; c < NCHUNK; c++) {
        CP_WAIT(0);
        __syncthreads();
        if (c + 1 < NCHUNK) stage(c + 1);
        const uint32_t bufb = sb + F_STG0 + (c & 1) * F_STAGE;

        // ---- scores: S = Qh·Kh + Qh·Kl + Ql·Kh ----
        float sc[8][4];
#pragma unroll
        for (int ni = 0; ni < 8; ni++)
#pragma unroll
            for (int j = 0; j < 4; j++) sc[ni][j] = 0.0f;

#pragma unroll
        for (int ks = 0; ks < 4; ks++) {
            uint32_t qh4[4], ql4[4];
            uint32_t ra = sw128((uint32_t)(a_row * 128 + (ks * 2 + a_c) * 16));
            ldm_x4(qh4, sb + FQ_H + ra);
            ldm_x4(ql4, sb + FQ_L + ra);
#pragma unroll
            for (int ni = 0; ni < 8; ni++) {
                uint32_t kh[2], kl[2];
                uint32_t rb = sw128((uint32_t)((ni * 8 + b_row) * 128 + (ks * 2 + b_c) * 16));
                ldm_x2(kh, bufb + F_KH + rb);
                ldm_x2(kl, bufb + F_KL + rb);
                mma_bf16(sc[ni], qh4, kh);
                mma_bf16(sc[ni], qh4, kl);
                mma_bf16(sc[ni], ql4, kh);
            }
        }

        // ---- online softmax ----
        float mx0 = -1e30f, mx1 = -1e30f;
#pragma unroll
        for (int ni = 0; ni < 8; ni++) {
            mx0 = fmaxf(mx0, fmaxf(sc[ni][0], sc[ni][1]));
            mx1 = fmaxf(mx1, fmaxf(sc[ni][2], sc[ni][3]));
        }
        mx0 *= 0.125f; mx1 *= 0.125f;
        mx0 = fmaxf(mx0, __shfl_xor_sync(~0u, mx0, 1));
        mx0 = fmaxf(mx0, __shfl_xor_sync(~0u, mx0, 2));
        mx1 = fmaxf(mx1, __shfl_xor_sync(~0u, mx1, 1));
        mx1 = fmaxf(mx1, __shfl_xor_sync(~0u, mx1, 2));
        float mn0 = fmaxf(m0, mx0), mn1 = fmaxf(m1, mx1);
        float corr0 = __expf(m0 - mn0), corr1 = __expf(m1 - mn1);
        m0 = mn0; m1 = mn1;

        float s0 = 0.0f, s1 = 0.0f;
#pragma unroll
        for (int ni = 0; ni < 8; ni++) {
            sc[ni][0] = __expf(fmaf(sc[ni][0], 0.125f, -mn0));
            sc[ni][1] = __expf(fmaf(sc[ni][1], 0.125f, -mn0));
            sc[ni][2] = __expf(fmaf(sc[ni][2], 0.125f, -mn1));
            sc[ni][3] = __expf(fmaf(sc[ni][3], 0.125f, -mn1));
            s0 += sc[ni][0] + sc[ni][1];
            s1 += sc[ni][2] + sc[ni][3];
        }
        s0 += __shfl_xor_sync(~0u, s0, 1);
        s0 += __shfl_xor_sync(~0u, s0, 2);
        s1 += __shfl_xor_sync(~0u, s1, 1);
        s1 += __shfl_xor_sync(~0u, s1, 2);
        l0 = l0 * corr0 + s0;
        l1 = l1 * corr1 + s1;

#pragma unroll
        for (int ni = 0; ni < 8; ni++) {
            o[ni][0] *= corr0; o[ni][1] *= corr0;
            o[ni][2] *= corr1; o[ni][3] *= corr1;
        }

        // ---- pack P into A-fragments (hi/lo) ----
        uint32_t ph[4][4], pl[4][4];
#pragma unroll
        for (int kk = 0; kk < 4; kk++) {
            float p00 = sc[2 * kk][0],     p01 = sc[2 * kk][1];
            float p02 = sc[2 * kk][2],     p03 = sc[2 * kk][3];
            float p10 = sc[2 * kk + 1][0], p11 = sc[2 * kk + 1][1];
            float p12 = sc[2 * kk + 1][2], p13 = sc[2 * kk + 1][3];
            __nv_bfloat16 h00 = __float2bfloat16(p00), h01 = __float2bfloat16(p01);
            __nv_bfloat16 h02 = __float2bfloat16(p02), h03 = __float2bfloat16(p03);
            __nv_bfloat16 h10 = __float2bfloat16(p10), h11 = __float2bfloat16(p11);
            __nv_bfloat16 h12 = __float2bfloat16(p12), h13 = __float2bfloat16(p13);
            ph[kk][0] = pack_bf16x2(p00, p01);
            ph[kk][1] = pack_bf16x2(p02, p03);
            ph[kk][2] = pack_bf16x2(p10, p11);
            ph[kk][3] = pack_bf16x2(p12, p13);
            pl[kk][0] = pack_bf16x2(p00 - __bfloat162float(h00), p01 - __bfloat162float(h01));
            pl[kk][1] = pack_bf16x2(p02 - __bfloat162float(h02), p03 - __bfloat162float(h03));
            pl[kk][2] = pack_bf16x2(p10 - __bfloat162float(h10), p11 - __bfloat162float(h11));
            pl[kk][3] = pack_bf16x2(p12 - __bfloat162float(h12), p13 - __bfloat162float(h13));
        }

        // ---- O += Ph·Vh + Ph·Vl + Pl·Vh ----
#pragma unroll
        for (int ks = 0; ks < 4; ks++) {
#pragma unroll
            for (int ni = 0; ni < 8; ni++) {
                uint32_t vh[2], vl[2];
                uint32_t rv = sw128((uint32_t)((ks * 16 + v_row) * 128 + ni * 16));
                ldm_x2_t(vh, bufb + F_VH + rv);
                ldm_x2_t(vl, bufb + F_VL + rv);
                mma_bf16(o[ni], ph[ks], vh);
                mma_bf16(o[ni], ph[ks], vl);
                mma_bf16(o[ni], pl[ks], vh);
            }
        }
    }

    // ---- epilogue ----
    const int g   = lid >> 2;
    const int tig = lid & 3;
    const float inv0 = 1.0f / l0, inv1 = 1.0f / l1;
#pragma unroll
    for (int half = 0; half < 2; half++) {
        int s = q0 + wid * 16 + g + half * 8;
        float inv = half ? inv1 : inv0;
        size_t rowbase = ((size_t)(b * S_LEN + s)) * EMB + h * HD;
#pragma unroll
        for (int ni = 0; ni < 8; ni++) {
            float vx = o[ni][half * 2 + 0] * inv;
            float vy = o[ni][half * 2 + 1] * inv;
            __nv_bfloat16 hx = __float2bfloat16(vx);
            __nv_bfloat16 hy = __float2bfloat16(vy);
            __nv_bfloat16 lx = __float2bfloat16(vx - __bfloat162float(hx));
            __nv_bfloat16 ly = __float2bfloat16(vy - __bfloat162float(hy));
            size_t idx = rowbase + ni * 8 + tig * 2;
            *(__nv_bfloat162*)(Ohi + idx) = __halves2bfloat162(hx, hy);
            *(__nv_bfloat162*)(Olo + idx) = __halves2bfloat162(lx, ly);
        }
    }
}

// ---------------------------------------------------------------------------
// Launch
// ---------------------------------------------------------------------------
extern "C" void kernel_launch(void* const* d_in, const int* in_sizes, int n_in,
                              void* d_out, int out_size)
{
    const float* x  = (const float*)d_in[0];
    const float* Wq = (const float*)d_in[1];
    const float* bq = (const float*)d_in[2];
    const float* Wk = (const float*)d_in[3];
    const float* bk = (const float*)d_in[4];
    const float* Wv = (const float*)d_in[5];
    const float* bv = (const float*)d_in[6];
    const float* Wo = (const float*)d_in[7];
    const float* bo = (const float*)d_in[8];
    float* out = (float*)d_out;

    __nv_bfloat16 *xhi, *xlo, *whi, *wlo, *ahi, *alo;
    __nv_bfloat16 *qhi, *qlo, *khi, *klo, *vhi, *vlo;
    cudaGetSymbolAddress((void**)&xhi, g_xhi);
    cudaGetSymbolAddress((void**)&xlo, g_xlo);
    cudaGetSymbolAddress((void**)&whi, g_whi);
    cudaGetSymbolAddress((void**)&wlo, g_wlo);
    cudaGetSymbolAddress((void**)&ahi, g_ahi);
    cudaGetSymbolAddress((void**)&alo, g_alo);
    cudaGetSymbolAddress((void**)&qhi, g_qhi);
    cudaGetSymbolAddress((void**)&qlo, g_qlo);
    cudaGetSymbolAddress((void**)&khi, g_khi);
    cudaGetSymbolAddress((void**)&klo, g_klo);
    cudaGetSymbolAddress((void**)&vhi, g_vhi);
    cudaGetSymbolAddress((void**)&vlo, g_vlo);

    cudaFuncSetAttribute(gemm_qkv, cudaFuncAttributeMaxDynamicSharedMemorySize, GEMM_SMEM);
    cudaFuncSetAttribute(gemm_out, cudaFuncAttributeMaxDynamicSharedMemorySize, GEMM_SMEM);
    cudaFuncSetAttribute(flash_mma, cudaFuncAttributeMaxDynamicSharedMemorySize, FLASH_SMEM);

    convert_all<<<(N4ALL + 255) / 256, 256>>>((const float4*)x,
        (const float4*)Wq, (const float4*)Wk, (const float4*)Wv, (const float4*)Wo,
        xhi, xlo, whi, wlo);

    dim3 gq(24, M_TOT / 128);          // fused QKV
    gemm_qkv<<<gq, 256, GEMM_SMEM>>>(xhi, xlo, whi, wlo, bq, bk, bv,
                                     qhi, qlo, khi, klo, vhi, vlo);

    dim3 ga(S_LEN / 128, BH);          // (16, 64)
    flash_mma<<<ga, 256, FLASH_SMEM>>>(qhi, qlo, khi, klo, vhi, vlo, ahi, alo);

    dim3 gg(EMB / 128, M_TOT / 128);   // (8, 64)
    gemm_out<<<gg, 256, GEMM_SMEM>>>(ahi, alo, whi + 3 * WSZ, wlo + 3 * WSZ, bo, out);
}

// round 10
// speedup vs baseline: 1.0836x; 1.0414x over previous
#include <cuda_runtime.h>
#include <cuda_bf16.h>
#include <cstdint>

#define BATCH 4
#define S_LEN 2048
#define EMB   1024
#define NH    16
#define HD    64
#define M_TOT (BATCH * S_LEN)   // 8192
#define BH    (BATCH * NH)      // 64
#define WSZ   ((size_t)EMB * EMB)

// ---------------------------------------------------------------------------
// Scratch (device globals — no allocation allowed)
// ---------------------------------------------------------------------------
__device__ __nv_bfloat16 g_xhi[(size_t)M_TOT * EMB];
__device__ __nv_bfloat16 g_xlo[(size_t)M_TOT * EMB];
__device__ __nv_bfloat16 g_whi[4][WSZ];
__device__ __nv_bfloat16 g_wlo[4][WSZ];
__device__ __nv_bfloat16 g_qhi[(size_t)BH * S_LEN * HD];
__device__ __nv_bfloat16 g_qlo[(size_t)BH * S_LEN * HD];
__device__ __nv_bfloat16 g_khi[(size_t)BH * S_LEN * HD];
__device__ __nv_bfloat16 g_klo[(size_t)BH * S_LEN * HD];
__device__ __nv_bfloat16 g_vhi[(size_t)BH * S_LEN * HD];
__device__ __nv_bfloat16 g_vlo[(size_t)BH * S_LEN * HD];
__device__ __nv_bfloat16 g_ahi[(size_t)M_TOT * EMB];
__device__ __nv_bfloat16 g_alo[(size_t)M_TOT * EMB];

// ---------------------------------------------------------------------------
// helpers
// ---------------------------------------------------------------------------
__device__ __forceinline__ uint32_t smem_u32(const void* p) {
    uint32_t a;
    asm("{ .reg .u64 t; cvta.to.shared.u64 t, %1; cvt.u32.u64 %0, t; }"
        : "=r"(a) : "l"(p));
    return a;
}
__device__ __forceinline__ void cp_async16(uint32_t dst, const void* src) {
    asm volatile("cp.async.cg.shared.global [%0], [%1], 16;"
                 :: "r"(dst), "l"(__cvta_generic_to_global(src)) : "memory");
}
#define CP_COMMIT()  asm volatile("cp.async.commit_group;" ::: "memory")
#define CP_WAIT(n)   asm volatile("cp.async.wait_group %0;" :: "n"(n) : "memory")

__device__ __forceinline__ void ldm_x4(uint32_t* r, uint32_t addr) {
    asm volatile("ldmatrix.sync.aligned.m8n8.x4.shared.b16 {%0,%1,%2,%3}, [%4];"
                 : "=r"(r[0]), "=r"(r[1]), "=r"(r[2]), "=r"(r[3]) : "r"(addr));
}
__device__ __forceinline__ void ldm_x4_t(uint32_t* r, uint32_t addr) {
    asm volatile("ldmatrix.sync.aligned.m8n8.x4.trans.shared.b16 {%0,%1,%2,%3}, [%4];"
                 : "=r"(r[0]), "=r"(r[1]), "=r"(r[2]), "=r"(r[3]) : "r"(addr));
}
__device__ __forceinline__ void mma_bf16(float* c, const uint32_t* a, const uint32_t* b) {
    asm volatile(
        "mma.sync.aligned.m16n8k16.row.col.f32.bf16.bf16.f32 "
        "{%0,%1,%2,%3}, {%4,%5,%6,%7}, {%8,%9}, {%0,%1,%2,%3};"
        : "+f"(c[0]), "+f"(c[1]), "+f"(c[2]), "+f"(c[3])
        : "r"(a[0]), "r"(a[1]), "r"(a[2]), "r"(a[3]), "r"(b[0]), "r"(b[1]));
}
__device__ __forceinline__ uint32_t pack_bf16x2(float lo, float hi) {
    uint32_t r;
    asm("cvt.rn.bf16x2.f32 %0, %1, %2;" : "=r"(r) : "f"(hi), "f"(lo));
    return r;
}
// swizzle for 64B rows (4 x 16B chunks)
__device__ __forceinline__ uint32_t sw64(int row, int c) {
    return (uint32_t)(row * 64 + (((c) ^ ((row >> 1) & 3)) << 4));
}
// standard SW128 for 128B rows
__device__ __forceinline__ uint32_t sw128(uint32_t off) {
    return off ^ ((off >> 3) & 0x70);
}

// ---------------------------------------------------------------------------
// single fused convert: x + 4 weights -> bf16 hi/lo
// ---------------------------------------------------------------------------
#define N4X (M_TOT * EMB / 4)
#define N4W (EMB * EMB / 4)
#define N4ALL (N4X + 4 * N4W)

__global__ void __launch_bounds__(256)
convert_all(const float4* __restrict__ x,
            const float4* __restrict__ Wq, const float4* __restrict__ Wk,
            const float4* __restrict__ Wv, const float4* __restrict__ Wo,
            __nv_bfloat16* __restrict__ xhi, __nv_bfloat16* __restrict__ xlo,
            __nv_bfloat16* __restrict__ whi, __nv_bfloat16* __restrict__ wlo)
{
    int i = blockIdx.x * 256 + threadIdx.x;
    if (i >= N4ALL) return;

    const float4* in;
    __nv_bfloat16 *hp, *lp;
    int idx;
    if (i < N4X) {
        in = x; hp = xhi; lp = xlo; idx = i;
    } else {
        int j = i - N4X;
        int w = j >> 18;
        idx = j & (N4W - 1);
        in = (w == 0) ? Wq : (w == 1) ? Wk : (w == 2) ? Wv : Wo;
        hp = whi + (size_t)w * WSZ;
        lp = wlo + (size_t)w * WSZ;
    }
    float4 v = in[idx];
    __nv_bfloat16 h0 = __float2bfloat16(v.x);
    __nv_bfloat16 h1 = __float2bfloat16(v.y);
    __nv_bfloat16 h2 = __float2bfloat16(v.z);
    __nv_bfloat16 h3 = __float2bfloat16(v.w);
    __nv_bfloat16 l0 = __float2bfloat16(v.x - __bfloat162float(h0));
    __nv_bfloat16 l1 = __float2bfloat16(v.y - __bfloat162float(h1));
    __nv_bfloat16 l2 = __float2bfloat16(v.z - __bfloat162float(h2));
    __nv_bfloat16 l3 = __float2bfloat16(v.w - __bfloat162float(h3));
    __nv_bfloat162* h2p = (__nv_bfloat162*)hp;
    __nv_bfloat162* l2p = (__nv_bfloat162*)lp;
    h2p[2 * idx + 0] = __halves2bfloat162(h0, h1);
    h2p[2 * idx + 1] = __halves2bfloat162(h2, h3);
    l2p[2 * idx + 0] = __halves2bfloat162(l0, l1);
    l2p[2 * idx + 1] = __halves2bfloat162(l2, l3);
}

// ---------------------------------------------------------------------------
// GEMM: 128x128 CTA tile, 8 warps (2m x 4n) of 64x32, BK=32,
//       swizzled 64B rows, 3-stage cp.async (distance 2), 2 CTAs/SM,
//       x4 ldmatrix for B (2 n-tiles per instruction)
// ---------------------------------------------------------------------------
#define TILE_B 8192                    // 128 rows * 64B
#define ST_AH 0
#define ST_AL (1 * TILE_B)
#define ST_BH (2 * TILE_B)
#define ST_BL (3 * TILE_B)
#define STAGE_B (4 * TILE_B)           // 32768
#define GEMM_SMEM (3 * STAGE_B)        // 98304 (x2 CTAs = 196K)
#define KITER (EMB / 32)               // 32

#define GEMM_MAINLOOP()                                                        \
    float acc[4][4][4];                                                        \
    _Pragma("unroll")                                                          \
    for (int i = 0; i < 4; i++)                                                \
        _Pragma("unroll")                                                      \
        for (int j = 0; j < 4; j++)                                            \
            _Pragma("unroll")                                                  \
            for (int k = 0; k < 4; k++) acc[i][j][k] = 0.0f;                   \
    const int a_row  = wm * 64 + (lid & 15);                                   \
    const int a_c    = (lid >> 4);                                             \
    /* x4 B layout: lanes 0-7 m0(ni,k0), 8-15 m1(ni,k1),                       \
                    16-23 m2(ni+1,k0), 24-31 m3(ni+1,k1) */                    \
    const int b_row4 = wn * 32 + (lid & 7) + ((lid >> 4) << 3);                \
    const int b_c    = (lid >> 3) & 1;                                         \
    stage(0, 0); stage(1, 1);                                                  \
    _Pragma("unroll 1")                                                        \
    for (int kc = 0; kc < KITER; kc++) {                                       \
        if (kc + 1 < KITER) { CP_WAIT(1); } else { CP_WAIT(0); }               \
        __syncthreads();                                                       \
        if (kc + 2 < KITER) stage((kc + 2) % 3, kc + 2);                       \
        const uint32_t bufb = sb + (kc % 3) * STAGE_B;                         \
        _Pragma("unroll")                                                      \
        for (int ks = 0; ks < 2; ks++) {                                       \
            const int kc0 = ks * 2;                                            \
            uint32_t ah[4][4], al[4][4], bhf[4][2], blf[4][2];                 \
            _Pragma("unroll")                                                  \
            for (int mi = 0; mi < 4; mi++) {                                   \
                uint32_t ra = sw64(a_row + mi * 16, kc0 + a_c);                \
                ldm_x4(ah[mi], bufb + ST_AH + ra);                             \
                ldm_x4(al[mi], bufb + ST_AL + ra);                             \
            }                                                                  \
            _Pragma("unroll")                                                  \
            for (int n2 = 0; n2 < 2; n2++) {                                   \
                uint32_t rb = sw64(b_row4 + n2 * 16, kc0 + b_c);               \
                uint32_t t4[4];                                                \
                ldm_x4(t4, bufb + ST_BH + rb);                                 \
                bhf[n2 * 2][0] = t4[0]; bhf[n2 * 2][1] = t4[1];                \
                bhf[n2 * 2 + 1][0] = t4[2]; bhf[n2 * 2 + 1][1] = t4[3];        \
                ldm_x4(t4, bufb + ST_BL + rb);                                 \
                blf[n2 * 2][0] = t4[0]; blf[n2 * 2][1] = t4[1];                \
                blf[n2 * 2 + 1][0] = t4[2]; blf[n2 * 2 + 1][1] = t4[3];        \
            }                                                                  \
            _Pragma("unroll")                                                  \
            for (int mi = 0; mi < 4; mi++)                                     \
                _Pragma("unroll")                                              \
                for (int ni = 0; ni < 4; ni++) {                               \
                    mma_bf16(acc[mi][ni], ah[mi], bhf[ni]);                    \
                    mma_bf16(acc[mi][ni], ah[mi], blf[ni]);                    \
                    mma_bf16(acc[mi][ni], al[mi], bhf[ni]);                    \
                }                                                              \
        }                                                                      \
    }

// staging for 256 threads: thread -> row = tid>>1, chunks c = (tid&1)*2 + {0,1}
#define GEMM_STAGE_LAMBDA()                                                    \
    auto stage = [&](int buf, int kc) {                                        \
        const uint32_t base = sb + buf * STAGE_B;                              \
        const int row = tid >> 1;                                              \
        _Pragma("unroll")                                                      \
        for (int t = 0; t < 2; t++) {                                          \
            int c = (tid & 1) * 2 + t;                                         \
            uint32_t so = sw64(row, c);                                        \
            int gcol = kc * 32 + c * 8;                                        \
            cp_async16(base + ST_AH + so, gA[0] + (size_t)row * EMB + gcol);   \
            cp_async16(base + ST_AL + so, gA[1] + (size_t)row * EMB + gcol);   \
            cp_async16(base + ST_BH + so, gB[0] + (size_t)row * EMB + gcol);   \
            cp_async16(base + ST_BL + so, gB[1] + (size_t)row * EMB + gcol);   \
        }                                                                      \
        CP_COMMIT();                                                           \
    };

// fused QKV GEMM: grid (24, 64); bn>>3 selects {Q,K,V}
__global__ void __launch_bounds__(256, 2)
gemm_qkv(const __nv_bfloat16* __restrict__ Ahi, const __nv_bfloat16* __restrict__ Alo,
         const __nv_bfloat16* __restrict__ Whi, const __nv_bfloat16* __restrict__ Wlo,
         const float* __restrict__ bq, const float* __restrict__ bk,
         const float* __restrict__ bv,
         __nv_bfloat16* __restrict__ qhi, __nv_bfloat16* __restrict__ qlo,
         __nv_bfloat16* __restrict__ khi, __nv_bfloat16* __restrict__ klo,
         __nv_bfloat16* __restrict__ vhi, __nv_bfloat16* __restrict__ vlo)
{
    extern __shared__ char smem[];
    const uint32_t sb = smem_u32(smem);
    const int tid = threadIdx.x;
    const int wid = tid >> 5;
    const int lid = tid & 31;
    const int bn  = blockIdx.x;
    const int w   = bn >> 3;
    const int tm  = blockIdx.y * 128;
    const int tn  = (bn & 7) * 128;
    const int wm  = wid >> 2;          // 0..1
    const int wn  = wid & 3;           // 0..3

    const float* bias = (w == 0) ? bq : (w == 1) ? bk : bv;
    __nv_bfloat16* Chi = (w == 0) ? qhi : (w == 1) ? khi : vhi;
    __nv_bfloat16* Clo = (w == 0) ? qlo : (w == 1) ? klo : vlo;

    const __nv_bfloat16* gA[2] = { Ahi + (size_t)tm * EMB, Alo + (size_t)tm * EMB };
    const __nv_bfloat16* gB[2] = { Whi + (size_t)w * WSZ + (size_t)tn * EMB,
                                   Wlo + (size_t)w * WSZ + (size_t)tn * EMB };

    GEMM_STAGE_LAMBDA()
    GEMM_MAINLOOP()

    // epilogue: split bf16, scatter to [B,H,S,D]
    const int g   = lid >> 2;
    const int tig = lid & 3;
#pragma unroll
    for (int ni = 0; ni < 4; ni++) {
        const int n = tn + wn * 32 + ni * 8 + tig * 2;
        const float b0 = bias[n], b1 = bias[n + 1];
        const int hh = n >> 6, dd = n & 63;
#pragma unroll
        for (int mi = 0; mi < 4; mi++) {
#pragma unroll
            for (int half = 0; half < 2; half++) {
                int m = tm + wm * 64 + mi * 16 + g + half * 8;
                float vx = acc[mi][ni][half * 2 + 0] + b0;
                float vy = acc[mi][ni][half * 2 + 1] + b1;
                int bb = m >> 11, ss = m & 2047;
                size_t idx = (((size_t)(bb * NH + hh) * S_LEN) + ss) * HD + dd;
                __nv_bfloat16 hx = __float2bfloat16(vx);
                __nv_bfloat16 hy = __float2bfloat16(vy);
                __nv_bfloat16 lx = __float2bfloat16(vx - __bfloat162float(hx));
                __nv_bfloat16 ly = __float2bfloat16(vy - __bfloat162float(hy));
                *(__nv_bfloat162*)(Chi + idx) = __halves2bfloat162(hx, hy);
                *(__nv_bfloat162*)(Clo + idx) = __halves2bfloat162(lx, ly);
            }
        }
    }
}

// output projection GEMM: fp32 C row-major
__global__ void __launch_bounds__(256, 2)
gemm_out(const __nv_bfloat16* __restrict__ Ahi, const __nv_bfloat16* __restrict__ Alo,
         const __nv_bfloat16* __restrict__ Bhi, const __nv_bfloat16* __restrict__ Blo,
         const float* __restrict__ bias, float* __restrict__ C)
{
    extern __shared__ char smem[];
    const uint32_t sb = smem_u32(smem);
    const int tid = threadIdx.x;
    const int wid = tid >> 5;
    const int lid = tid & 31;
    const int tm  = blockIdx.y * 128;
    const int tn  = blockIdx.x * 128;
    const int wm  = wid >> 2;
    const int wn  = wid & 3;

    const __nv_bfloat16* gA[2] = { Ahi + (size_t)tm * EMB, Alo + (size_t)tm * EMB };
    const __nv_bfloat16* gB[2] = { Bhi + (size_t)tn * EMB, Blo + (size_t)tn * EMB };

    GEMM_STAGE_LAMBDA()
    GEMM_MAINLOOP()

    const int g   = lid >> 2;
    const int tig = lid & 3;
#pragma unroll
    for (int ni = 0; ni < 4; ni++) {
        const int n = tn + wn * 32 + ni * 8 + tig * 2;
        const float b0 = bias[n], b1 = bias[n + 1];
#pragma unroll
        for (int mi = 0; mi < 4; mi++) {
#pragma unroll
            for (int half = 0; half < 2; half++) {
                int m = tm + wm * 64 + mi * 16 + g + half * 8;
                float2 v;
                v.x = acc[mi][ni][half * 2 + 0] + b0;
                v.y = acc[mi][ni][half * 2 + 1] + b1;
                *(float2*)(C + (size_t)m * EMB + n) = v;
            }
        }
    }
}

// ---------------------------------------------------------------------------
// Flash attention: 8 warps x 16 q-rows, Q persistent smem (SW128),
//                  2-stage KV (SW128), 2 CTAs/SM, x4 ldmatrix for K and V
// ---------------------------------------------------------------------------
#define FQ_H  0                        // 128 rows * 128B = 16384
#define FQ_L  16384
#define F_KH  0
#define F_KL  8192                     // 64 rows * 128B
#define F_VH  16384
#define F_VL  24576
#define F_STAGE 32768
#define F_STG0 32768                   // KV stages after Q region
#define FLASH_SMEM (F_STG0 + 2 * F_STAGE)   // 98304
#define NCHUNK (S_LEN / 64)            // 32

__global__ void __launch_bounds__(256, 2)
flash_mma(const __nv_bfloat16* __restrict__ Qhi, const __nv_bfloat16* __restrict__ Qlo,
          const __nv_bfloat16* __restrict__ Khi, const __nv_bfloat16* __restrict__ Klo,
          const __nv_bfloat16* __restrict__ Vhi, const __nv_bfloat16* __restrict__ Vlo,
          __nv_bfloat16* __restrict__ Ohi, __nv_bfloat16* __restrict__ Olo)
{
    extern __shared__ char smem[];
    const uint32_t sb = smem_u32(smem);
    const int tid = threadIdx.x;
    const int wid = tid >> 5;
    const int lid = tid & 31;
    const int bh  = blockIdx.y;
    const int b   = bh >> 4;
    const int h   = bh & 15;
    const int q0  = blockIdx.x * 128;

    const __nv_bfloat16* Qh_g = Qhi + ((size_t)bh * S_LEN + q0) * HD;
    const __nv_bfloat16* Ql_g = Qlo + ((size_t)bh * S_LEN + q0) * HD;
    const __nv_bfloat16* Kh_g = Khi + (size_t)bh * S_LEN * HD;
    const __nv_bfloat16* Kl_g = Klo + (size_t)bh * S_LEN * HD;
    const __nv_bfloat16* Vh_g = Vhi + (size_t)bh * S_LEN * HD;
    const __nv_bfloat16* Vl_g = Vlo + (size_t)bh * S_LEN * HD;

    // ---- KV staging: row = tid>>2 (0..63), chunks c = (tid&3)*2 + {0,1} ----
    const int s_row = tid >> 2;
    auto stage = [&](int c) {
        const uint32_t base = sb + F_STG0 + (c & 1) * F_STAGE;
        const size_t gbase = (size_t)(c * 64 + s_row) * HD;
#pragma unroll
        for (int t = 0; t < 2; t++) {
            int seg = (tid & 3) * 2 + t;
            uint32_t so = sw128((uint32_t)(s_row * 128 + seg * 16));
            const size_t go = gbase + seg * 8;
            cp_async16(base + F_KH + so, Kh_g + go);
            cp_async16(base + F_KL + so, Kl_g + go);
            cp_async16(base + F_VH + so, Vh_g + go);
            cp_async16(base + F_VL + so, Vl_g + go);
        }
        CP_COMMIT();
    };

    stage(0);   // prefetch first KV chunk, overlaps Q staging below

    // ---- stage Q (128 x 64) hi/lo into persistent swizzled smem ----
    {
        int row = tid >> 1;
#pragma unroll
        for (int t = 0; t < 4; t++) {
            int seg = (tid & 1) * 4 + t;
            uint32_t so = sw128((uint32_t)(row * 128 + seg * 16));
            *(uint4*)(smem + FQ_H + so) = *(const uint4*)(Qh_g + (size_t)row * HD + seg * 8);
            *(uint4*)(smem + FQ_L + so) = *(const uint4*)(Ql_g + (size_t)row * HD + seg * 8);
        }
    }
    __syncthreads();

    float o[8][4];
#pragma unroll
    for (int ni = 0; ni < 8; ni++)
#pragma unroll
        for (int j = 0; j < 4; j++) o[ni][j] = 0.0f;
    float m0 = -1e30f, m1 = -1e30f, l0 = 0.0f, l1 = 0.0f;

    const int a_row  = wid * 16 + (lid & 15);
    const int a_c    = (lid >> 4);
    // x4 K layout: lanes 0-7 (ni,k0), 8-15 (ni,k1), 16-23 (ni+1,k0), 24-31 (ni+1,k1)
    const int kb_row = (lid & 7) + ((lid >> 4) << 3);
    const int kb_c   = (lid >> 3) & 1;
    // x4_t V layout: lanes 0-7 (k0-7,ni), 8-15 (k8-15,ni), 16-23 (k0-7,ni+1), 24-31 (k8-15,ni+1)
    const int v_row4 = (lid & 7) + (((lid >> 3) & 1) << 3);
    const int v_nh   = (lid >> 4);

#pragma unroll 1
    for (int c = 0; c < NCHUNK; c++) {
        CP_WAIT(0);
        __syncthreads();
        if (c + 1 < NCHUNK) stage(c + 1);
        const uint32_t bufb = sb + F_STG0 + (c & 1) * F_STAGE;

        // ---- scores: S = Qh·Kh + Qh·Kl + Ql·Kh ----
        float sc[8][4];
#pragma unroll
        for (int ni = 0; ni < 8; ni++)
#pragma unroll
            for (int j = 0; j < 4; j++) sc[ni][j] = 0.0f;

#pragma unroll
        for (int ks = 0; ks < 4; ks++) {
            uint32_t qh4[4], ql4[4];
            uint32_t ra = sw128((uint32_t)(a_row * 128 + (ks * 2 + a_c) * 16));
            ldm_x4(qh4, sb + FQ_H + ra);
            ldm_x4(ql4, sb + FQ_L + ra);
#pragma unroll
            for (int n2 = 0; n2 < 4; n2++) {
                uint32_t rb = sw128((uint32_t)((n2 * 16 + kb_row) * 128 + (ks * 2 + kb_c) * 16));
                uint32_t t4[4];
                uint32_t kh0[2], kh1[2], kl0[2], kl1[2];
                ldm_x4(t4, bufb + F_KH + rb);
                kh0[0] = t4[0]; kh0[1] = t4[1]; kh1[0] = t4[2]; kh1[1] = t4[3];
                ldm_x4(t4, bufb + F_KL + rb);
                kl0[0] = t4[0]; kl0[1] = t4[1]; kl1[0] = t4[2]; kl1[1] = t4[3];
                mma_bf16(sc[n2 * 2 + 0], qh4, kh0);
                mma_bf16(sc[n2 * 2 + 0], qh4, kl0);
                mma_bf16(sc[n2 * 2 + 0], ql4, kh0);
                mma_bf16(sc[n2 * 2 + 1], qh4, kh1);
                mma_bf16(sc[n2 * 2 + 1], qh4, kl1);
                mma_bf16(sc[n2 * 2 + 1], ql4, kh1);
            }
        }

        // ---- online softmax ----
        float mx0 = -1e30f, mx1 = -1e30f;
#pragma unroll
        for (int ni = 0; ni < 8; ni++) {
            mx0 = fmaxf(mx0, fmaxf(sc[ni][0], sc[ni][1]));
            mx1 = fmaxf(mx1, fmaxf(sc[ni][2], sc[ni][3]));
        }
        mx0 *= 0.125f; mx1 *= 0.125f;
        mx0 = fmaxf(mx0, __shfl_xor_sync(~0u, mx0, 1));
        mx0 = fmaxf(mx0, __shfl_xor_sync(~0u, mx0, 2));
        mx1 = fmaxf(mx1, __shfl_xor_sync(~0u, mx1, 1));
        mx1 = fmaxf(mx1, __shfl_xor_sync(~0u, mx1, 2));
        float mn0 = fmaxf(m0, mx0), mn1 = fmaxf(m1, mx1);
        float corr0 = __expf(m0 - mn0), corr1 = __expf(m1 - mn1);
        m0 = mn0; m1 = mn1;

        float s0 = 0.0f, s1 = 0.0f;
#pragma unroll
        for (int ni = 0; ni < 8; ni++) {
            sc[ni][0] = __expf(fmaf(sc[ni][0], 0.125f, -mn0));
            sc[ni][1] = __expf(fmaf(sc[ni][1], 0.125f, -mn0));
            sc[ni][2] = __expf(fmaf(sc[ni][2], 0.125f, -mn1));
            sc[ni][3] = __expf(fmaf(sc[ni][3], 0.125f, -mn1));
            s0 += sc[ni][0] + sc[ni][1];
            s1 += sc[ni][2] + sc[ni][3];
        }
        s0 += __shfl_xor_sync(~0u, s0, 1);
        s0 += __shfl_xor_sync(~0u, s0, 2);
        s1 += __shfl_xor_sync(~0u, s1, 1);
        s1 += __shfl_xor_sync(~0u, s1, 2);
        l0 = l0 * corr0 + s0;
        l1 = l1 * corr1 + s1;

#pragma unroll
        for (int ni = 0; ni < 8; ni++) {
            o[ni][0] *= corr0; o[ni][1] *= corr0;
            o[ni][2] *= corr1; o[ni][3] *= corr1;
        }

        // ---- pack P into A-fragments (hi/lo) ----
        uint32_t ph[4][4], pl[4][4];
#pragma unroll
        for (int kk = 0; kk < 4; kk++) {
            float p00 = sc[2 * kk][0],     p01 = sc[2 * kk][1];
            float p02 = sc[2 * kk][2],     p03 = sc[2 * kk][3];
            float p10 = sc[2 * kk + 1][0], p11 = sc[2 * kk + 1][1];
            float p12 = sc[2 * kk + 1][2], p13 = sc[2 * kk + 1][3];
            __nv_bfloat16 h00 = __float2bfloat16(p00), h01 = __float2bfloat16(p01);
            __nv_bfloat16 h02 = __float2bfloat16(p02), h03 = __float2bfloat16(p03);
            __nv_bfloat16 h10 = __float2bfloat16(p10), h11 = __float2bfloat16(p11);
            __nv_bfloat16 h12 = __float2bfloat16(p12), h13 = __float2bfloat16(p13);
            ph[kk][0] = pack_bf16x2(p00, p01);
            ph[kk][1] = pack_bf16x2(p02, p03);
            ph[kk][2] = pack_bf16x2(p10, p11);
            ph[kk][3] = pack_bf16x2(p12, p13);
            pl[kk][0] = pack_bf16x2(p00 - __bfloat162float(h00), p01 - __bfloat162float(h01));
            pl[kk][1] = pack_bf16x2(p02 - __bfloat162float(h02), p03 - __bfloat162float(h03));
            pl[kk][2] = pack_bf16x2(p10 - __bfloat162float(h10), p11 - __bfloat162float(h11));
            pl[kk][3] = pack_bf16x2(p12 - __bfloat162float(h12), p13 - __bfloat162float(h13));
        }

        // ---- O += Ph·Vh + Ph·Vl + Pl·Vh ----
#pragma unroll
        for (int ks = 0; ks < 4; ks++) {
#pragma unroll
            for (int n2 = 0; n2 < 4; n2++) {
                uint32_t rv = sw128((uint32_t)((ks * 16 + v_row4) * 128 + (n2 * 2 + v_nh) * 16));
                uint32_t t4[4];
                uint32_t vh0[2], vh1[2], vl0[2], vl1[2];
                ldm_x4_t(t4, bufb + F_VH + rv);
                vh0[0] = t4[0]; vh0[1] = t4[1]; vh1[0] = t4[2]; vh1[1] = t4[3];
                ldm_x4_t(t4, bufb + F_VL + rv);
                vl0[0] = t4[0]; vl0[1] = t4[1]; vl1[0] = t4[2]; vl1[1] = t4[3];
                mma_bf16(o[n2 * 2 + 0], ph[ks], vh0);
                mma_bf16(o[n2 * 2 + 0], ph[ks], vl0);
                mma_bf16(o[n2 * 2 + 0], pl[ks], vh0);
                mma_bf16(o[n2 * 2 + 1], ph[ks], vh1);
                mma_bf16(o[n2 * 2 + 1], ph[ks], vl1);
                mma_bf16(o[n2 * 2 + 1], pl[ks], vh1);
            }
        }
    }

    // ---- epilogue ----
    const int g   = lid >> 2;
    const int tig = lid & 3;
    const float inv0 = 1.0f / l0, inv1 = 1.0f / l1;
#pragma unroll
    for (int half = 0; half < 2; half++) {
        int s = q0 + wid * 16 + g + half * 8;
        float inv = half ? inv1 : inv0;
        size_t rowbase = ((size_t)(b * S_LEN + s)) * EMB + h * HD;
#pragma unroll
        for (int ni = 0; ni < 8; ni++) {
            float vx = o[ni][half * 2 + 0] * inv;
            float vy = o[ni][half * 2 + 1] * inv;
            __nv_bfloat16 hx = __float2bfloat16(vx);
            __nv_bfloat16 hy = __float2bfloat16(vy);
            __nv_bfloat16 lx = __float2bfloat16(vx - __bfloat162float(hx));
            __nv_bfloat16 ly = __float2bfloat16(vy - __bfloat162float(hy));
            size_t idx = rowbase + ni * 8 + tig * 2;
            *(__nv_bfloat162*)(Ohi + idx) = __halves2bfloat162(hx, hy);
            *(__nv_bfloat162*)(Olo + idx) = __halves2bfloat162(lx, ly);
        }
    }
}

// ---------------------------------------------------------------------------
// Launch
// ---------------------------------------------------------------------------
extern "C" void kernel_launch(void* const* d_in, const int* in_sizes, int n_in,
                              void* d_out, int out_size)
{
    const float* x  = (const float*)d_in[0];
    const float* Wq = (const float*)d_in[1];
    const float* bq = (const float*)d_in[2];
    const float* Wk = (const float*)d_in[3];
    const float* bk = (const float*)d_in[4];
    const float* Wv = (const float*)d_in[5];
    const float* bv = (const float*)d_in[6];
    const float* Wo = (const float*)d_in[7];
    const float* bo = (const float*)d_in[8];
    float* out = (float*)d_out;

    __nv_bfloat16 *xhi, *xlo, *whi, *wlo, *ahi, *alo;
    __nv_bfloat16 *qhi, *qlo, *khi, *klo, *vhi, *vlo;
    cudaGetSymbolAddress((void**)&xhi, g_xhi);
    cudaGetSymbolAddress((void**)&xlo, g_xlo);
    cudaGetSymbolAddress((void**)&whi, g_whi);
    cudaGetSymbolAddress((void**)&wlo, g_wlo);
    cudaGetSymbolAddress((void**)&ahi, g_ahi);
    cudaGetSymbolAddress((void**)&alo, g_alo);
    cudaGetSymbolAddress((void**)&qhi, g_qhi);
    cudaGetSymbolAddress((void**)&qlo, g_qlo);
    cudaGetSymbolAddress((void**)&khi, g_khi);
    cudaGetSymbolAddress((void**)&klo, g_klo);
    cudaGetSymbolAddress((void**)&vhi, g_vhi);
    cudaGetSymbolAddress((void**)&vlo, g_vlo);

    cudaFuncSetAttribute(gemm_qkv, cudaFuncAttributeMaxDynamicSharedMemorySize, GEMM_SMEM);
    cudaFuncSetAttribute(gemm_out, cudaFuncAttributeMaxDynamicSharedMemorySize, GEMM_SMEM);
    cudaFuncSetAttribute(flash_mma, cudaFuncAttributeMaxDynamicSharedMemorySize, FLASH_SMEM);

    convert_all<<<(N4ALL + 255) / 256, 256>>>((const float4*)x,
        (const float4*)Wq, (const float4*)Wk, (const float4*)Wv, (const float4*)Wo,
        xhi, xlo, whi, wlo);

    dim3 gq(24, M_TOT / 128);          // fused QKV
    gemm_qkv<<<gq, 256, GEMM_SMEM>>>(xhi, xlo, whi, wlo, bq, bk, bv,
                                     qhi, qlo, khi, klo, vhi, vlo);

    dim3 ga(S_LEN / 128, BH);          // (16, 64)
    flash_mma<<<ga, 256, FLASH_SMEM>>>(qhi, qlo, khi, klo, vhi, vlo, ahi, alo);

    dim3 gg(EMB / 128, M_TOT / 128);   // (8, 64)
    gemm_out<<<gg, 256, GEMM_SMEM>>>(ahi, alo, whi + 3 * WSZ, wlo + 3 * WSZ, bo, out);
}

// round 11
// speedup vs baseline: 1.0837x; 1.0001x over previous
#include <cuda_runtime.h>
#include <cuda_bf16.h>
#include <cstdint>

#define BATCH 4
#define S_LEN 2048
#define EMB   1024
#define NH    16
#define HD    64
#define M_TOT (BATCH * S_LEN)   // 8192
#define BH    (BATCH * NH)      // 64
#define WSZ   ((size_t)EMB * EMB)

// ---------------------------------------------------------------------------
// Scratch (device globals — no allocation allowed)
// ---------------------------------------------------------------------------
__device__ __nv_bfloat16 g_xhi[(size_t)M_TOT * EMB];
__device__ __nv_bfloat16 g_xlo[(size_t)M_TOT * EMB];
__device__ __nv_bfloat16 g_whi[4][WSZ];
__device__ __nv_bfloat16 g_wlo[4][WSZ];
__device__ __nv_bfloat16 g_qhi[(size_t)BH * S_LEN * HD];
__device__ __nv_bfloat16 g_qlo[(size_t)BH * S_LEN * HD];
__device__ __nv_bfloat16 g_khi[(size_t)BH * S_LEN * HD];
__device__ __nv_bfloat16 g_klo[(size_t)BH * S_LEN * HD];
__device__ __nv_bfloat16 g_vhi[(size_t)BH * S_LEN * HD];
__device__ __nv_bfloat16 g_vlo[(size_t)BH * S_LEN * HD];
__device__ __nv_bfloat16 g_ahi[(size_t)M_TOT * EMB];
__device__ __nv_bfloat16 g_alo[(size_t)M_TOT * EMB];

// ---------------------------------------------------------------------------
// helpers
// ---------------------------------------------------------------------------
__device__ __forceinline__ uint32_t smem_u32(const void* p) {
    uint32_t a;
    asm("{ .reg .u64 t; cvta.to.shared.u64 t, %1; cvt.u32.u64 %0, t; }"
        : "=r"(a) : "l"(p));
    return a;
}
__device__ __forceinline__ void cp_async16(uint32_t dst, const void* src) {
    asm volatile("cp.async.cg.shared.global [%0], [%1], 16;"
                 :: "r"(dst), "l"(__cvta_generic_to_global(src)) : "memory");
}
#define CP_COMMIT()  asm volatile("cp.async.commit_group;" ::: "memory")
#define CP_WAIT(n)   asm volatile("cp.async.wait_group %0;" :: "n"(n) : "memory")

__device__ __forceinline__ void ldm_x4(uint32_t* r, uint32_t addr) {
    asm volatile("ldmatrix.sync.aligned.m8n8.x4.shared.b16 {%0,%1,%2,%3}, [%4];"
                 : "=r"(r[0]), "=r"(r[1]), "=r"(r[2]), "=r"(r[3]) : "r"(addr));
}
__device__ __forceinline__ void ldm_x4_t(uint32_t* r, uint32_t addr) {
    asm volatile("ldmatrix.sync.aligned.m8n8.x4.trans.shared.b16 {%0,%1,%2,%3}, [%4];"
                 : "=r"(r[0]), "=r"(r[1]), "=r"(r[2]), "=r"(r[3]) : "r"(addr));
}
__device__ __forceinline__ void mma_bf16(float* c, const uint32_t* a, const uint32_t* b) {
    asm volatile(
        "mma.sync.aligned.m16n8k16.row.col.f32.bf16.bf16.f32 "
        "{%0,%1,%2,%3}, {%4,%5,%6,%7}, {%8,%9}, {%0,%1,%2,%3};"
        : "+f"(c[0]), "+f"(c[1]), "+f"(c[2]), "+f"(c[3])
        : "r"(a[0]), "r"(a[1]), "r"(a[2]), "r"(a[3]), "r"(b[0]), "r"(b[1]));
}
__device__ __forceinline__ uint32_t pack_bf16x2(float lo, float hi) {
    uint32_t r;
    asm("cvt.rn.bf16x2.f32 %0, %1, %2;" : "=r"(r) : "f"(hi), "f"(lo));
    return r;
}
// swizzle for 64B rows (4 x 16B chunks)
__device__ __forceinline__ uint32_t sw64(int row, int c) {
    return (uint32_t)(row * 64 + (((c) ^ ((row >> 1) & 3)) << 4));
}
// standard SW128 for 128B rows
__device__ __forceinline__ uint32_t sw128(uint32_t off) {
    return off ^ ((off >> 3) & 0x70);
}

// ---------------------------------------------------------------------------
// single fused convert: x + 4 weights -> bf16 hi/lo
// ---------------------------------------------------------------------------
#define N4X (M_TOT * EMB / 4)
#define N4W (EMB * EMB / 4)
#define N4ALL (N4X + 4 * N4W)

__global__ void __launch_bounds__(256)
convert_all(const float4* __restrict__ x,
            const float4* __restrict__ Wq, const float4* __restrict__ Wk,
            const float4* __restrict__ Wv, const float4* __restrict__ Wo,
            __nv_bfloat16* __restrict__ xhi, __nv_bfloat16* __restrict__ xlo,
            __nv_bfloat16* __restrict__ whi, __nv_bfloat16* __restrict__ wlo)
{
    int i = blockIdx.x * 256 + threadIdx.x;
    if (i >= N4ALL) return;

    const float4* in;
    __nv_bfloat16 *hp, *lp;
    int idx;
    if (i < N4X) {
        in = x; hp = xhi; lp = xlo; idx = i;
    } else {
        int j = i - N4X;
        int w = j >> 18;
        idx = j & (N4W - 1);
        in = (w == 0) ? Wq : (w == 1) ? Wk : (w == 2) ? Wv : Wo;
        hp = whi + (size_t)w * WSZ;
        lp = wlo + (size_t)w * WSZ;
    }
    float4 v = in[idx];
    __nv_bfloat16 h0 = __float2bfloat16(v.x);
    __nv_bfloat16 h1 = __float2bfloat16(v.y);
    __nv_bfloat16 h2 = __float2bfloat16(v.z);
    __nv_bfloat16 h3 = __float2bfloat16(v.w);
    __nv_bfloat16 l0 = __float2bfloat16(v.x - __bfloat162float(h0));
    __nv_bfloat16 l1 = __float2bfloat16(v.y - __bfloat162float(h1));
    __nv_bfloat16 l2 = __float2bfloat16(v.z - __bfloat162float(h2));
    __nv_bfloat16 l3 = __float2bfloat16(v.w - __bfloat162float(h3));
    __nv_bfloat162* h2p = (__nv_bfloat162*)hp;
    __nv_bfloat162* l2p = (__nv_bfloat162*)lp;
    h2p[2 * idx + 0] = __halves2bfloat162(h0, h1);
    h2p[2 * idx + 1] = __halves2bfloat162(h2, h3);
    l2p[2 * idx + 0] = __halves2bfloat162(l0, l1);
    l2p[2 * idx + 1] = __halves2bfloat162(l2, l3);
}

// ---------------------------------------------------------------------------
// GEMM: 128x128 CTA tile, 8 warps (2m x 4n) of 64x32, BK=32,
//       swizzled 64B rows, 3-stage cp.async (distance 2), 2 CTAs/SM,
//       x4 ldmatrix for B, TERM-MAJOR MMA ordering (16 indep MMAs between RAWs)
// ---------------------------------------------------------------------------
#define TILE_B 8192                    // 128 rows * 64B
#define ST_AH 0
#define ST_AL (1 * TILE_B)
#define ST_BH (2 * TILE_B)
#define ST_BL (3 * TILE_B)
#define STAGE_B (4 * TILE_B)           // 32768
#define GEMM_SMEM (3 * STAGE_B)        // 98304 (x2 CTAs = 196K)
#define KITER (EMB / 32)               // 32

#define GEMM_MAINLOOP()                                                        \
    float acc[4][4][4];                                                        \
    _Pragma("unroll")                                                          \
    for (int i = 0; i < 4; i++)                                                \
        _Pragma("unroll")                                                      \
        for (int j = 0; j < 4; j++)                                            \
            _Pragma("unroll")                                                  \
            for (int k = 0; k < 4; k++) acc[i][j][k] = 0.0f;                   \
    const int a_row  = wm * 64 + (lid & 15);                                   \
    const int a_c    = (lid >> 4);                                             \
    const int b_row4 = wn * 32 + (lid & 7) + ((lid >> 4) << 3);                \
    const int b_c    = (lid >> 3) & 1;                                         \
    stage(0, 0); stage(1, 1);                                                  \
    _Pragma("unroll 1")                                                        \
    for (int kc = 0; kc < KITER; kc++) {                                       \
        if (kc + 1 < KITER) { CP_WAIT(1); } else { CP_WAIT(0); }               \
        __syncthreads();                                                       \
        if (kc + 2 < KITER) stage((kc + 2) % 3, kc + 2);                       \
        const uint32_t bufb = sb + (kc % 3) * STAGE_B;                         \
        _Pragma("unroll")                                                      \
        for (int ks = 0; ks < 2; ks++) {                                       \
            const int kc0 = ks * 2;                                            \
            uint32_t ah[4][4], al[4][4], bhf[4][2], blf[4][2];                 \
            _Pragma("unroll")                                                  \
            for (int mi = 0; mi < 4; mi++) {                                   \
                uint32_t ra = sw64(a_row + mi * 16, kc0 + a_c);                \
                ldm_x4(ah[mi], bufb + ST_AH + ra);                             \
                ldm_x4(al[mi], bufb + ST_AL + ra);                             \
            }                                                                  \
            _Pragma("unroll")                                                  \
            for (int n2 = 0; n2 < 2; n2++) {                                   \
                uint32_t rb = sw64(b_row4 + n2 * 16, kc0 + b_c);               \
                uint32_t t4[4];                                                \
                ldm_x4(t4, bufb + ST_BH + rb);                                 \
                bhf[n2 * 2][0] = t4[0]; bhf[n2 * 2][1] = t4[1];                \
                bhf[n2 * 2 + 1][0] = t4[2]; bhf[n2 * 2 + 1][1] = t4[3];        \
                ldm_x4(t4, bufb + ST_BL + rb);                                 \
                blf[n2 * 2][0] = t4[0]; blf[n2 * 2][1] = t4[1];                \
                blf[n2 * 2 + 1][0] = t4[2]; blf[n2 * 2 + 1][1] = t4[3];        \
            }                                                                  \
            /* term-major: all 16 hh, then 16 hl, then 16 lh */                \
            _Pragma("unroll")                                                  \
            for (int mi = 0; mi < 4; mi++)                                     \
                _Pragma("unroll")                                              \
                for (int ni = 0; ni < 4; ni++)                                 \
                    mma_bf16(acc[mi][ni], ah[mi], bhf[ni]);                    \
            _Pragma("unroll")                                                  \
            for (int mi = 0; mi < 4; mi++)                                     \
                _Pragma("unroll")                                              \
                for (int ni = 0; ni < 4; ni++)                                 \
                    mma_bf16(acc[mi][ni], ah[mi], blf[ni]);                    \
            _Pragma("unroll")                                                  \
            for (int mi = 0; mi < 4; mi++)                                     \
                _Pragma("unroll")                                              \
                for (int ni = 0; ni < 4; ni++)                                 \
                    mma_bf16(acc[mi][ni], al[mi], bhf[ni]);                    \
        }                                                                      \
    }

// staging for 256 threads: thread -> row = tid>>1, chunks c = (tid&1)*2 + {0,1}
#define GEMM_STAGE_LAMBDA()                                                    \
    auto stage = [&](int buf, int kc) {                                        \
        const uint32_t base = sb + buf * STAGE_B;                              \
        const int row = tid >> 1;                                              \
        _Pragma("unroll")                                                      \
        for (int t = 0; t < 2; t++) {                                          \
            int c = (tid & 1) * 2 + t;                                         \
            uint32_t so = sw64(row, c);                                        \
            int gcol = kc * 32 + c * 8;                                        \
            cp_async16(base + ST_AH + so, gA[0] + (size_t)row * EMB + gcol);   \
            cp_async16(base + ST_AL + so, gA[1] + (size_t)row * EMB + gcol);   \
            cp_async16(base + ST_BH + so, gB[0] + (size_t)row * EMB + gcol);   \
            cp_async16(base + ST_BL + so, gB[1] + (size_t)row * EMB + gcol);   \
        }                                                                      \
        CP_COMMIT();                                                           \
    };

// fused QKV GEMM: grid (24, 64); bn>>3 selects {Q,K,V}
__global__ void __launch_bounds__(256, 2)
gemm_qkv(const __nv_bfloat16* __restrict__ Ahi, const __nv_bfloat16* __restrict__ Alo,
         const __nv_bfloat16* __restrict__ Whi, const __nv_bfloat16* __restrict__ Wlo,
         const float* __restrict__ bq, const float* __restrict__ bk,
         const float* __restrict__ bv,
         __nv_bfloat16* __restrict__ qhi, __nv_bfloat16* __restrict__ qlo,
         __nv_bfloat16* __restrict__ khi, __nv_bfloat16* __restrict__ klo,
         __nv_bfloat16* __restrict__ vhi, __nv_bfloat16* __restrict__ vlo)
{
    extern __shared__ char smem[];
    const uint32_t sb = smem_u32(smem);
    const int tid = threadIdx.x;
    const int wid = tid >> 5;
    const int lid = tid & 31;
    const int bn  = blockIdx.x;
    const int w   = bn >> 3;
    const int tm  = blockIdx.y * 128;
    const int tn  = (bn & 7) * 128;
    const int wm  = wid >> 2;          // 0..1
    const int wn  = wid & 3;           // 0..3

    const float* bias = (w == 0) ? bq : (w == 1) ? bk : bv;
    __nv_bfloat16* Chi = (w == 0) ? qhi : (w == 1) ? khi : vhi;
    __nv_bfloat16* Clo = (w == 0) ? qlo : (w == 1) ? klo : vlo;

    const __nv_bfloat16* gA[2] = { Ahi + (size_t)tm * EMB, Alo + (size_t)tm * EMB };
    const __nv_bfloat16* gB[2] = { Whi + (size_t)w * WSZ + (size_t)tn * EMB,
                                   Wlo + (size_t)w * WSZ + (size_t)tn * EMB };

    GEMM_STAGE_LAMBDA()
    GEMM_MAINLOOP()

    // epilogue: split bf16, scatter to [B,H,S,D]
    const int g   = lid >> 2;
    const int tig = lid & 3;
#pragma unroll
    for (int ni = 0; ni < 4; ni++) {
        const int n = tn + wn * 32 + ni * 8 + tig * 2;
        const float b0 = bias[n], b1 = bias[n + 1];
        const int hh = n >> 6, dd = n & 63;
#pragma unroll
        for (int mi = 0; mi < 4; mi++) {
#pragma unroll
            for (int half = 0; half < 2; half++) {
                int m = tm + wm * 64 + mi * 16 + g + half * 8;
                float vx = acc[mi][ni][half * 2 + 0] + b0;
                float vy = acc[mi][ni][half * 2 + 1] + b1;
                int bb = m >> 11, ss = m & 2047;
                size_t idx = (((size_t)(bb * NH + hh) * S_LEN) + ss) * HD + dd;
                __nv_bfloat16 hx = __float2bfloat16(vx);
                __nv_bfloat16 hy = __float2bfloat16(vy);
                __nv_bfloat16 lx = __float2bfloat16(vx - __bfloat162float(hx));
                __nv_bfloat16 ly = __float2bfloat16(vy - __bfloat162float(hy));
                *(__nv_bfloat162*)(Chi + idx) = __halves2bfloat162(hx, hy);
                *(__nv_bfloat162*)(Clo + idx) = __halves2bfloat162(lx, ly);
            }
        }
    }
}

// output projection GEMM: fp32 C row-major
__global__ void __launch_bounds__(256, 2)
gemm_out(const __nv_bfloat16* __restrict__ Ahi, const __nv_bfloat16* __restrict__ Alo,
         const __nv_bfloat16* __restrict__ Bhi, const __nv_bfloat16* __restrict__ Blo,
         const float* __restrict__ bias, float* __restrict__ C)
{
    extern __shared__ char smem[];
    const uint32_t sb = smem_u32(smem);
    const int tid = threadIdx.x;
    const int wid = tid >> 5;
    const int lid = tid & 31;
    const int tm  = blockIdx.y * 128;
    const int tn  = blockIdx.x * 128;
    const int wm  = wid >> 2;
    const int wn  = wid & 3;

    const __nv_bfloat16* gA[2] = { Ahi + (size_t)tm * EMB, Alo + (size_t)tm * EMB };
    const __nv_bfloat16* gB[2] = { Bhi + (size_t)tn * EMB, Blo + (size_t)tn * EMB };

    GEMM_STAGE_LAMBDA()
    GEMM_MAINLOOP()

    const int g   = lid >> 2;
    const int tig = lid & 3;
#pragma unroll
    for (int ni = 0; ni < 4; ni++) {
        const int n = tn + wn * 32 + ni * 8 + tig * 2;
        const float b0 = bias[n], b1 = bias[n + 1];
#pragma unroll
        for (int mi = 0; mi < 4; mi++) {
#pragma unroll
            for (int half = 0; half < 2; half++) {
                int m = tm + wm * 64 + mi * 16 + g + half * 8;
                float2 v;
                v.x = acc[mi][ni][half * 2 + 0] + b0;
                v.y = acc[mi][ni][half * 2 + 1] + b1;
                *(float2*)(C + (size_t)m * EMB + n) = v;
            }
        }
    }
}

// ---------------------------------------------------------------------------
// Flash attention: 8 warps x 16 q-rows, Q persistent smem (SW128),
//                  2-stage KV (SW128), 2 CTAs/SM, x4 ldmatrix,
//                  interleaved term ordering in QK and PV
// ---------------------------------------------------------------------------
#define FQ_H  0                        // 128 rows * 128B = 16384
#define FQ_L  16384
#define F_KH  0
#define F_KL  8192                     // 64 rows * 128B
#define F_VH  16384
#define F_VL  24576
#define F_STAGE 32768
#define F_STG0 32768                   // KV stages after Q region
#define FLASH_SMEM (F_STG0 + 2 * F_STAGE)   // 98304
#define NCHUNK (S_LEN / 64)            // 32

__global__ void __launch_bounds__(256, 2)
flash_mma(const __nv_bfloat16* __restrict__ Qhi, const __nv_bfloat16* __restrict__ Qlo,
          const __nv_bfloat16* __restrict__ Khi, const __nv_bfloat16* __restrict__ Klo,
          const __nv_bfloat16* __restrict__ Vhi, const __nv_bfloat16* __restrict__ Vlo,
          __nv_bfloat16* __restrict__ Ohi, __nv_bfloat16* __restrict__ Olo)
{
    extern __shared__ char smem[];
    const uint32_t sb = smem_u32(smem);
    const int tid = threadIdx.x;
    const int wid = tid >> 5;
    const int lid = tid & 31;
    const int bh  = blockIdx.y;
    const int b   = bh >> 4;
    const int h   = bh & 15;
    const int q0  = blockIdx.x * 128;

    const __nv_bfloat16* Qh_g = Qhi + ((size_t)bh * S_LEN + q0) * HD;
    const __nv_bfloat16* Ql_g = Qlo + ((size_t)bh * S_LEN + q0) * HD;
    const __nv_bfloat16* Kh_g = Khi + (size_t)bh * S_LEN * HD;
    const __nv_bfloat16* Kl_g = Klo + (size_t)bh * S_LEN * HD;
    const __nv_bfloat16* Vh_g = Vhi + (size_t)bh * S_LEN * HD;
    const __nv_bfloat16* Vl_g = Vlo + (size_t)bh * S_LEN * HD;

    // ---- KV staging ----
    const int s_row = tid >> 2;
    auto stage = [&](int c) {
        const uint32_t base = sb + F_STG0 + (c & 1) * F_STAGE;
        const size_t gbase = (size_t)(c * 64 + s_row) * HD;
#pragma unroll
        for (int t = 0; t < 2; t++) {
            int seg = (tid & 3) * 2 + t;
            uint32_t so = sw128((uint32_t)(s_row * 128 + seg * 16));
            const size_t go = gbase + seg * 8;
            cp_async16(base + F_KH + so, Kh_g + go);
            cp_async16(base + F_KL + so, Kl_g + go);
            cp_async16(base + F_VH + so, Vh_g + go);
            cp_async16(base + F_VL + so, Vl_g + go);
        }
        CP_COMMIT();
    };

    stage(0);   // prefetch first KV chunk, overlaps Q staging below

    // ---- stage Q (128 x 64) hi/lo into persistent swizzled smem ----
    {
        int row = tid >> 1;
#pragma unroll
        for (int t = 0; t < 4; t++) {
            int seg = (tid & 1) * 4 + t;
            uint32_t so = sw128((uint32_t)(row * 128 + seg * 16));
            *(uint4*)(smem + FQ_H + so) = *(const uint4*)(Qh_g + (size_t)row * HD + seg * 8);
            *(uint4*)(smem + FQ_L + so) = *(const uint4*)(Ql_g + (size_t)row * HD + seg * 8);
        }
    }
    __syncthreads();

    float o[8][4];
#pragma unroll
    for (int ni = 0; ni < 8; ni++)
#pragma unroll
        for (int j = 0; j < 4; j++) o[ni][j] = 0.0f;
    float m0 = -1e30f, m1 = -1e30f, l0 = 0.0f, l1 = 0.0f;

    const int a_row  = wid * 16 + (lid & 15);
    const int a_c    = (lid >> 4);
    const int kb_row = (lid & 7) + ((lid >> 4) << 3);
    const int kb_c   = (lid >> 3) & 1;
    const int v_row4 = (lid & 7) + (((lid >> 3) & 1) << 3);
    const int v_nh   = (lid >> 4);

#pragma unroll 1
    for (int c = 0; c < NCHUNK; c++) {
        CP_WAIT(0);
        __syncthreads();
        if (c + 1 < NCHUNK) stage(c + 1);
        const uint32_t bufb = sb + F_STG0 + (c & 1) * F_STAGE;

        // ---- scores: S = Qh·Kh + Qh·Kl + Ql·Kh (term-interleaved) ----
        float sc[8][4];
#pragma unroll
        for (int ni = 0; ni < 8; ni++)
#pragma unroll
            for (int j = 0; j < 4; j++) sc[ni][j] = 0.0f;

#pragma unroll
        for (int ks = 0; ks < 4; ks++) {
            uint32_t qh4[4], ql4[4];
            uint32_t ra = sw128((uint32_t)(a_row * 128 + (ks * 2 + a_c) * 16));
            ldm_x4(qh4, sb + FQ_H + ra);
            ldm_x4(ql4, sb + FQ_L + ra);
#pragma unroll
            for (int n2 = 0; n2 < 4; n2++) {
                uint32_t rb = sw128((uint32_t)((n2 * 16 + kb_row) * 128 + (ks * 2 + kb_c) * 16));
                uint32_t t4[4];
                uint32_t kh0[2], kh1[2], kl0[2], kl1[2];
                ldm_x4(t4, bufb + F_KH + rb);
                kh0[0] = t4[0]; kh0[1] = t4[1]; kh1[0] = t4[2]; kh1[1] = t4[3];
                ldm_x4(t4, bufb + F_KL + rb);
                kl0[0] = t4[0]; kl0[1] = t4[1]; kl1[0] = t4[2]; kl1[1] = t4[3];
                // interleave the two accumulator chains term by term
                mma_bf16(sc[n2 * 2 + 0], qh4, kh0);
                mma_bf16(sc[n2 * 2 + 1], qh4, kh1);
                mma_bf16(sc[n2 * 2 + 0], qh4, kl0);
                mma_bf16(sc[n2 * 2 + 1], qh4, kl1);
                mma_bf16(sc[n2 * 2 + 0], ql4, kh0);
                mma_bf16(sc[n2 * 2 + 1], ql4, kh1);
            }
        }

        // ---- online softmax ----
        float mx0 = -1e30f, mx1 = -1e30f;
#pragma unroll
        for (int ni = 0; ni < 8; ni++) {
            mx0 = fmaxf(mx0, fmaxf(sc[ni][0], sc[ni][1]));
            mx1 = fmaxf(mx1, fmaxf(sc[ni][2], sc[ni][3]));
        }
        mx0 *= 0.125f; mx1 *= 0.125f;
        mx0 = fmaxf(mx0, __shfl_xor_sync(~0u, mx0, 1));
        mx0 = fmaxf(mx0, __shfl_xor_sync(~0u, mx0, 2));
        mx1 = fmaxf(mx1, __shfl_xor_sync(~0u, mx1, 1));
        mx1 = fmaxf(mx1, __shfl_xor_sync(~0u, mx1, 2));
        float mn0 = fmaxf(m0, mx0), mn1 = fmaxf(m1, mx1);
        float corr0 = __expf(m0 - mn0), corr1 = __expf(m1 - mn1);
        m0 = mn0; m1 = mn1;

        float s0 = 0.0f, s1 = 0.0f;
#pragma unroll
        for (int ni = 0; ni < 8; ni++) {
            sc[ni][0] = __expf(fmaf(sc[ni][0], 0.125f, -mn0));
            sc[ni][1] = __expf(fmaf(sc[ni][1], 0.125f, -mn0));
            sc[ni][2] = __expf(fmaf(sc[ni][2], 0.125f, -mn1));
            sc[ni][3] = __expf(fmaf(sc[ni][3], 0.125f, -mn1));
            s0 += sc[ni][0] + sc[ni][1];
            s1 += sc[ni][2] + sc[ni][3];
        }
        s0 += __shfl_xor_sync(~0u, s0, 1);
        s0 += __shfl_xor_sync(~0u, s0, 2);
        s1 += __shfl_xor_sync(~0u, s1, 1);
        s1 += __shfl_xor_sync(~0u, s1, 2);
        l0 = l0 * corr0 + s0;
        l1 = l1 * corr1 + s1;

#pragma unroll
        for (int ni = 0; ni < 8; ni++) {
            o[ni][0] *= corr0; o[ni][1] *= corr0;
            o[ni][2] *= corr1; o[ni][3] *= corr1;
        }

        // ---- pack P into A-fragments (hi/lo) ----
        uint32_t ph[4][4], pl[4][4];
#pragma unroll
        for (int kk = 0; kk < 4; kk++) {
            float p00 = sc[2 * kk][0],     p01 = sc[2 * kk][1];
            float p02 = sc[2 * kk][2],     p03 = sc[2 * kk][3];
            float p10 = sc[2 * kk + 1][0], p11 = sc[2 * kk + 1][1];
            float p12 = sc[2 * kk + 1][2], p13 = sc[2 * kk + 1][3];
            __nv_bfloat16 h00 = __float2bfloat16(p00), h01 = __float2bfloat16(p01);
            __nv_bfloat16 h02 = __float2bfloat16(p02), h03 = __float2bfloat16(p03);
            __nv_bfloat16 h10 = __float2bfloat16(p10), h11 = __float2bfloat16(p11);
            __nv_bfloat16 h12 = __float2bfloat16(p12), h13 = __float2bfloat16(p13);
            ph[kk][0] = pack_bf16x2(p00, p01);
            ph[kk][1] = pack_bf16x2(p02, p03);
            ph[kk][2] = pack_bf16x2(p10, p11);
            ph[kk][3] = pack_bf16x2(p12, p13);
            pl[kk][0] = pack_bf16x2(p00 - __bfloat162float(h00), p01 - __bfloat162float(h01));
            pl[kk][1] = pack_bf16x2(p02 - __bfloat162float(h02), p03 - __bfloat162float(h03));
            pl[kk][2] = pack_bf16x2(p10 - __bfloat162float(h10), p11 - __bfloat162float(h11));
            pl[kk][3] = pack_bf16x2(p12 - __bfloat162float(h12), p13 - __bfloat162float(h13));
        }

        // ---- O += Ph·Vh + Ph·Vl + Pl·Vh (term-interleaved) ----
#pragma unroll
        for (int ks = 0; ks < 4; ks++) {
#pragma unroll
            for (int n2 = 0; n2 < 4; n2++) {
                uint32_t rv = sw128((uint32_t)((ks * 16 + v_row4) * 128 + (n2 * 2 + v_nh) * 16));
                uint32_t t4[4];
                uint32_t vh0[2], vh1[2], vl0[2], vl1[2];
                ldm_x4_t(t4, bufb + F_VH + rv);
                vh0[0] = t4[0]; vh0[1] = t4[1]; vh1[0] = t4[2]; vh1[1] = t4[3];
                ldm_x4_t(t4, bufb + F_VL + rv);
                vl0[0] = t4[0]; vl0[1] = t4[1]; vl1[0] = t4[2]; vl1[1] = t4[3];
                mma_bf16(o[n2 * 2 + 0], ph[ks], vh0);
                mma_bf16(o[n2 * 2 + 1], ph[ks], vh1);
                mma_bf16(o[n2 * 2 + 0], ph[ks], vl0);
                mma_bf16(o[n2 * 2 + 1], ph[ks], vl1);
                mma_bf16(o[n2 * 2 + 0], pl[ks], vh0);
                mma_bf16(o[n2 * 2 + 1], pl[ks], vh1);
            }
        }
    }

    // ---- epilogue ----
    const int g   = lid >> 2;
    const int tig = lid & 3;
    const float inv0 = 1.0f / l0, inv1 = 1.0f / l1;
#pragma unroll
    for (int half = 0; half < 2; half++) {
        int s = q0 + wid * 16 + g + half * 8;
        float inv = half ? inv1 : inv0;
        size_t rowbase = ((size_t)(b * S_LEN + s)) * EMB + h * HD;
#pragma unroll
        for (int ni = 0; ni < 8; ni++) {
            float vx = o[ni][half * 2 + 0] * inv;
            float vy = o[ni][half * 2 + 1] * inv;
            __nv_bfloat16 hx = __float2bfloat16(vx);
            __nv_bfloat16 hy = __float2bfloat16(vy);
            __nv_bfloat16 lx = __float2bfloat16(vx - __bfloat162float(hx));
            __nv_bfloat16 ly = __float2bfloat16(vy - __bfloat162float(hy));
            size_t idx = rowbase + ni * 8 + tig * 2;
            *(__nv_bfloat162*)(Ohi + idx) = __halves2bfloat162(hx, hy);
            *(__nv_bfloat162*)(Olo + idx) = __halves2bfloat162(lx, ly);
        }
    }
}

// ---------------------------------------------------------------------------
// Launch
// ---------------------------------------------------------------------------
extern "C" void kernel_launch(void* const* d_in, const int* in_sizes, int n_in,
                              void* d_out, int out_size)
{
    const float* x  = (const float*)d_in[0];
    const float* Wq = (const float*)d_in[1];
    const float* bq = (const float*)d_in[2];
    const float* Wk = (const float*)d_in[3];
    const float* bk = (const float*)d_in[4];
    const float* Wv = (const float*)d_in[5];
    const float* bv = (const float*)d_in[6];
    const float* Wo = (const float*)d_in[7];
    const float* bo = (const float*)d_in[8];
    float* out = (float*)d_out;

    __nv_bfloat16 *xhi, *xlo, *whi, *wlo, *ahi, *alo;
    __nv_bfloat16 *qhi, *qlo, *khi, *klo, *vhi, *vlo;
    cudaGetSymbolAddress((void**)&xhi, g_xhi);
    cudaGetSymbolAddress((void**)&xlo, g_xlo);
    cudaGetSymbolAddress((void**)&whi, g_whi);
    cudaGetSymbolAddress((void**)&wlo, g_wlo);
    cudaGetSymbolAddress((void**)&ahi, g_ahi);
    cudaGetSymbolAddress((void**)&alo, g_alo);
    cudaGetSymbolAddress((void**)&qhi, g_qhi);
    cudaGetSymbolAddress((void**)&qlo, g_qlo);
    cudaGetSymbolAddress((void**)&khi, g_khi);
    cudaGetSymbolAddress((void**)&klo, g_klo);
    cudaGetSymbolAddress((void**)&vhi, g_vhi);
    cudaGetSymbolAddress((void**)&vlo, g_vlo);

    cudaFuncSetAttribute(gemm_qkv, cudaFuncAttributeMaxDynamicSharedMemorySize, GEMM_SMEM);
    cudaFuncSetAttribute(gemm_out, cudaFuncAttributeMaxDynamicSharedMemorySize, GEMM_SMEM);
    cudaFuncSetAttribute(flash_mma, cudaFuncAttributeMaxDynamicSharedMemorySize, FLASH_SMEM);

    convert_all<<<(N4ALL + 255) / 256, 256>>>((const float4*)x,
        (const float4*)Wq, (const float4*)Wk, (const float4*)Wv, (const float4*)Wo,
        xhi, xlo, whi, wlo);

    dim3 gq(24, M_TOT / 128);          // fused QKV
    gemm_qkv<<<gq, 256, GEMM_SMEM>>>(xhi, xlo, whi, wlo, bq, bk, bv,
                                     qhi, qlo, khi, klo, vhi, vlo);

    dim3 ga(S_LEN / 128, BH);          // (16, 64)
    flash_mma<<<ga, 256, FLASH_SMEM>>>(qhi, qlo, khi, klo, vhi, vlo, ahi, alo);

    dim3 gg(EMB / 128, M_TOT / 128);   // (8, 64)
    gemm_out<<<gg, 256, GEMM_SMEM>>>(ahi, alo, whi + 3 * WSZ, wlo + 3 * WSZ, bo, out);
}

// round 13
// speedup vs baseline: 1.1549x; 1.0657x over previous
#include <cuda_runtime.h>
#include <cuda_bf16.h>
#include <cstdint>

#define BATCH 4
#define S_LEN 2048
#define EMB   1024
#define NH    16
#define HD    64
#define M_TOT (BATCH * S_LEN)   // 8192
#define BH    (BATCH * NH)      // 64
#define WSZ   ((size_t)EMB * EMB)

// ---------------------------------------------------------------------------
// Scratch (device globals — no allocation allowed)
// ---------------------------------------------------------------------------
__device__ __nv_bfloat16 g_xhi[(size_t)M_TOT * EMB];
__device__ __nv_bfloat16 g_xlo[(size_t)M_TOT * EMB];
__device__ __nv_bfloat16 g_whi[4][WSZ];
__device__ __nv_bfloat16 g_wlo[4][WSZ];
__device__ __nv_bfloat16 g_qhi[(size_t)BH * S_LEN * HD];
__device__ __nv_bfloat16 g_qlo[(size_t)BH * S_LEN * HD];
__device__ __nv_bfloat16 g_khi[(size_t)BH * S_LEN * HD];
__device__ __nv_bfloat16 g_klo[(size_t)BH * S_LEN * HD];
__device__ __nv_bfloat16 g_vhi[(size_t)BH * S_LEN * HD];
__device__ __nv_bfloat16 g_vlo[(size_t)BH * S_LEN * HD];
__device__ __nv_bfloat16 g_ahi[(size_t)M_TOT * EMB];
__device__ __nv_bfloat16 g_alo[(size_t)M_TOT * EMB];

// ---------------------------------------------------------------------------
// helpers
// ---------------------------------------------------------------------------
__device__ __forceinline__ uint32_t smem_u32(const void* p) {
    uint32_t a;
    asm("{ .reg .u64 t; cvta.to.shared.u64 t, %1; cvt.u32.u64 %0, t; }"
        : "=r"(a) : "l"(p));
    return a;
}
__device__ __forceinline__ void cp_async16(uint32_t dst, const void* src) {
    asm volatile("cp.async.cg.shared.global [%0], [%1], 16;"
                 :: "r"(dst), "l"(__cvta_generic_to_global(src)) : "memory");
}
#define MBAR_INIT(mbar, cnt) \
    asm volatile("mbarrier.init.shared.b64 [%0], %1;" :: "r"(mbar), "r"(cnt) : "memory")
#define MBAR_ARRIVE(mbar) \
    asm volatile("mbarrier.arrive.shared::cta.b64 _, [%0];" :: "r"(mbar) : "memory")
// .noinc: arrival consumed from the init count (init count == #async arrivals)
#define CPASYNC_MBAR_ARRIVE(mbar) \
    asm volatile("cp.async.mbarrier.arrive.noinc.shared::cta.b64 [%0];" :: "r"(mbar) : "memory")

__device__ __forceinline__ void mbar_wait(uint32_t mbar, uint32_t parity) {
    asm volatile(
        "{\n\t.reg .pred P;\n\t"
        "W_%=:\n\t"
        "mbarrier.try_wait.parity.acquire.cta.shared::cta.b64 P, [%0], %1, 0x989680;\n\t"
        "@P bra D_%=;\n\t"
        "bra W_%=;\n\t"
        "D_%=:\n\t}"
        :: "r"(mbar), "r"(parity) : "memory");
}

__device__ __forceinline__ void ldm_x4(uint32_t* r, uint32_t addr) {
    asm volatile("ldmatrix.sync.aligned.m8n8.x4.shared.b16 {%0,%1,%2,%3}, [%4];"
                 : "=r"(r[0]), "=r"(r[1]), "=r"(r[2]), "=r"(r[3]) : "r"(addr));
}
__device__ __forceinline__ void ldm_x4_t(uint32_t* r, uint32_t addr) {
    asm volatile("ldmatrix.sync.aligned.m8n8.x4.trans.shared.b16 {%0,%1,%2,%3}, [%4];"
                 : "=r"(r[0]), "=r"(r[1]), "=r"(r[2]), "=r"(r[3]) : "r"(addr));
}
__device__ __forceinline__ void mma_bf16(float* c, const uint32_t* a, const uint32_t* b) {
    asm volatile(
        "mma.sync.aligned.m16n8k16.row.col.f32.bf16.bf16.f32 "
        "{%0,%1,%2,%3}, {%4,%5,%6,%7}, {%8,%9}, {%0,%1,%2,%3};"
        : "+f"(c[0]), "+f"(c[1]), "+f"(c[2]), "+f"(c[3])
        : "r"(a[0]), "r"(a[1]), "r"(a[2]), "r"(a[3]), "r"(b[0]), "r"(b[1]));
}
__device__ __forceinline__ uint32_t pack_bf16x2(float lo, float hi) {
    uint32_t r;
    asm("cvt.rn.bf16x2.f32 %0, %1, %2;" : "=r"(r) : "f"(hi), "f"(lo));
    return r;
}
__device__ __forceinline__ uint32_t sw64(int row, int c) {
    return (uint32_t)(row * 64 + (((c) ^ ((row >> 1) & 3)) << 4));
}
__device__ __forceinline__ uint32_t sw128(uint32_t off) {
    return off ^ ((off >> 3) & 0x70);
}

// ---------------------------------------------------------------------------
// single fused convert: x + 4 weights -> bf16 hi/lo
// ---------------------------------------------------------------------------
#define N4X (M_TOT * EMB / 4)
#define N4W (EMB * EMB / 4)
#define N4ALL (N4X + 4 * N4W)

__global__ void __launch_bounds__(256)
convert_all(const float4* __restrict__ x,
            const float4* __restrict__ Wq, const float4* __restrict__ Wk,
            const float4* __restrict__ Wv, const float4* __restrict__ Wo,
            __nv_bfloat16* __restrict__ xhi, __nv_bfloat16* __restrict__ xlo,
            __nv_bfloat16* __restrict__ whi, __nv_bfloat16* __restrict__ wlo)
{
    int i = blockIdx.x * 256 + threadIdx.x;
    if (i >= N4ALL) return;

    const float4* in;
    __nv_bfloat16 *hp, *lp;
    int idx;
    if (i < N4X) {
        in = x; hp = xhi; lp = xlo; idx = i;
    } else {
        int j = i - N4X;
        int w = j >> 18;
        idx = j & (N4W - 1);
        in = (w == 0) ? Wq : (w == 1) ? Wk : (w == 2) ? Wv : Wo;
        hp = whi + (size_t)w * WSZ;
        lp = wlo + (size_t)w * WSZ;
    }
    float4 v = in[idx];
    __nv_bfloat16 h0 = __float2bfloat16(v.x);
    __nv_bfloat16 h1 = __float2bfloat16(v.y);
    __nv_bfloat16 h2 = __float2bfloat16(v.z);
    __nv_bfloat16 h3 = __float2bfloat16(v.w);
    __nv_bfloat16 l0 = __float2bfloat16(v.x - __bfloat162float(h0));
    __nv_bfloat16 l1 = __float2bfloat16(v.y - __bfloat162float(h1));
    __nv_bfloat16 l2 = __float2bfloat16(v.z - __bfloat162float(h2));
    __nv_bfloat16 l3 = __float2bfloat16(v.w - __bfloat162float(h3));
    __nv_bfloat162* h2p = (__nv_bfloat162*)hp;
    __nv_bfloat162* l2p = (__nv_bfloat162*)lp;
    h2p[2 * idx + 0] = __halves2bfloat162(h0, h1);
    h2p[2 * idx + 1] = __halves2bfloat162(h2, h3);
    l2p[2 * idx + 0] = __halves2bfloat162(l0, l1);
    l2p[2 * idx + 1] = __halves2bfloat162(l2, l3);
}

// ---------------------------------------------------------------------------
// GEMM: 128x128 CTA tile, 8 warps (2m x 4n) of 64x32, BK=32,
//       swizzled 64B rows, 3-stage mbarrier producer/consumer pipeline,
//       2 CTAs/SM, x4 ldmatrix for B
// ---------------------------------------------------------------------------
#define TILE_B 8192
#define ST_AH 0
#define ST_AL (1 * TILE_B)
#define ST_BH (2 * TILE_B)
#define ST_BL (3 * TILE_B)
#define STAGE_B (4 * TILE_B)           // 32768
#define MB_OFF (3 * STAGE_B)           // 98304: full[s]@+s*16, empty[s]@+s*16+8
#define GEMM_SMEM (MB_OFF + 48)        // 98352
#define KITER (EMB / 32)               // 32

#define GEMM_MAINLOOP()                                                        \
    if (tid == 0) {                                                            \
        _Pragma("unroll")                                                      \
        for (int s = 0; s < 3; s++) {                                          \
            MBAR_INIT(sb + MB_OFF + s * 16, 256);                              \
            MBAR_INIT(sb + MB_OFF + s * 16 + 8, 256);                          \
        }                                                                      \
    }                                                                          \
    __syncthreads();                                                           \
    float acc[4][4][4];                                                        \
    _Pragma("unroll")                                                          \
    for (int i = 0; i < 4; i++)                                                \
        _Pragma("unroll")                                                      \
        for (int j = 0; j < 4; j++)                                            \
            _Pragma("unroll")                                                  \
            for (int k = 0; k < 4; k++) acc[i][j][k] = 0.0f;                   \
    const int a_row  = wm * 64 + (lid & 15);                                   \
    const int a_c    = (lid >> 4);                                             \
    const int b_row4 = wn * 32 + (lid & 7) + ((lid >> 4) << 3);                \
    const int b_c    = (lid >> 3) & 1;                                         \
    int pstage = 0, pphase = 1, cstage = 0, cphase = 0;                        \
    auto stage_issue = [&](int kc) {                                           \
        uint32_t fb = sb + MB_OFF + pstage * 16;                               \
        mbar_wait(fb + 8, pphase);                                             \
        stage(pstage, kc);                                                     \
        CPASYNC_MBAR_ARRIVE(fb);                                               \
        if (++pstage == 3) { pstage = 0; pphase ^= 1; }                        \
    };                                                                         \
    stage_issue(0); stage_issue(1);                                            \
    _Pragma("unroll 1")                                                        \
    for (int kc = 0; kc < KITER; kc++) {                                       \
        mbar_wait(sb + MB_OFF + cstage * 16, cphase);                          \
        if (kc + 2 < KITER) stage_issue(kc + 2);                               \
        const uint32_t bufb = sb + cstage * STAGE_B;                           \
        _Pragma("unroll")                                                      \
        for (int ks = 0; ks < 2; ks++) {                                       \
            const int kc0 = ks * 2;                                            \
            uint32_t ah[4][4], al[4][4], bhf[4][2], blf[4][2];                 \
            _Pragma("unroll")                                                  \
            for (int mi = 0; mi < 4; mi++) {                                   \
                uint32_t ra = sw64(a_row + mi * 16, kc0 + a_c);                \
                ldm_x4(ah[mi], bufb + ST_AH + ra);                             \
                ldm_x4(al[mi], bufb + ST_AL + ra);                             \
            }                                                                  \
            _Pragma("unroll")                                                  \
            for (int n2 = 0; n2 < 2; n2++) {                                   \
                uint32_t rb = sw64(b_row4 + n2 * 16, kc0 + b_c);               \
                uint32_t t4[4];                                                \
                ldm_x4(t4, bufb + ST_BH + rb);                                 \
                bhf[n2 * 2][0] = t4[0]; bhf[n2 * 2][1] = t4[1];                \
                bhf[n2 * 2 + 1][0] = t4[2]; bhf[n2 * 2 + 1][1] = t4[3];        \
                ldm_x4(t4, bufb + ST_BL + rb);                                 \
                blf[n2 * 2][0] = t4[0]; blf[n2 * 2][1] = t4[1];                \
                blf[n2 * 2 + 1][0] = t4[2]; blf[n2 * 2 + 1][1] = t4[3];        \
            }                                                                  \
            _Pragma("unroll")                                                  \
            for (int mi = 0; mi < 4; mi++)                                     \
                _Pragma("unroll")                                              \
                for (int ni = 0; ni < 4; ni++) {                               \
                    mma_bf16(acc[mi][ni], ah[mi], bhf[ni]);                    \
                    mma_bf16(acc[mi][ni], ah[mi], blf[ni]);                    \
                    mma_bf16(acc[mi][ni], al[mi], bhf[ni]);                    \
                }                                                              \
        }                                                                      \
        MBAR_ARRIVE(sb + MB_OFF + cstage * 16 + 8);                            \
        if (++cstage == 3) { cstage = 0; cphase ^= 1; }                        \
    }

// staging for 256 threads: thread -> row = tid>>1, chunks c = (tid&1)*2 + {0,1}
#define GEMM_STAGE_LAMBDA()                                                    \
    auto stage = [&](int buf, int kc) {                                        \
        const uint32_t base = sb + buf * STAGE_B;                              \
        const int row = tid >> 1;                                              \
        _Pragma("unroll")                                                      \
        for (int t = 0; t < 2; t++) {                                          \
            int c = (tid & 1) * 2 + t;                                         \
            uint32_t so = sw64(row, c);                                        \
            int gcol = kc * 32 + c * 8;                                        \
            cp_async16(base + ST_AH + so, gA[0] + (size_t)row * EMB + gcol);   \
            cp_async16(base + ST_AL + so, gA[1] + (size_t)row * EMB + gcol);   \
            cp_async16(base + ST_BH + so, gB[0] + (size_t)row * EMB + gcol);   \
            cp_async16(base + ST_BL + so, gB[1] + (size_t)row * EMB + gcol);   \
        }                                                                      \
    };

// fused QKV GEMM: grid (24, 64); bn>>3 selects {Q,K,V}
__global__ void __launch_bounds__(256, 2)
gemm_qkv(const __nv_bfloat16* __restrict__ Ahi, const __nv_bfloat16* __restrict__ Alo,
         const __nv_bfloat16* __restrict__ Whi, const __nv_bfloat16* __restrict__ Wlo,
         const float* __restrict__ bq, const float* __restrict__ bk,
         const float* __restrict__ bv,
         __nv_bfloat16* __restrict__ qhi, __nv_bfloat16* __restrict__ qlo,
         __nv_bfloat16* __restrict__ khi, __nv_bfloat16* __restrict__ klo,
         __nv_bfloat16* __restrict__ vhi, __nv_bfloat16* __restrict__ vlo)
{
    extern __shared__ char smem[];
    const uint32_t sb = smem_u32(smem);
    const int tid = threadIdx.x;
    const int wid = tid >> 5;
    const int lid = tid & 31;
    const int bn  = blockIdx.x;
    const int w   = bn >> 3;
    const int tm  = blockIdx.y * 128;
    const int tn  = (bn & 7) * 128;
    const int wm  = wid >> 2;
    const int wn  = wid & 3;

    const float* bias = (w == 0) ? bq : (w == 1) ? bk : bv;
    __nv_bfloat16* Chi = (w == 0) ? qhi : (w == 1) ? khi : vhi;
    __nv_bfloat16* Clo = (w == 0) ? qlo : (w == 1) ? klo : vlo;

    const __nv_bfloat16* gA[2] = { Ahi + (size_t)tm * EMB, Alo + (size_t)tm * EMB };
    const __nv_bfloat16* gB[2] = { Whi + (size_t)w * WSZ + (size_t)tn * EMB,
                                   Wlo + (size_t)w * WSZ + (size_t)tn * EMB };

    GEMM_STAGE_LAMBDA()
    GEMM_MAINLOOP()

    // epilogue: split bf16, scatter to [B,H,S,D]
    const int g   = lid >> 2;
    const int tig = lid & 3;
#pragma unroll
    for (int ni = 0; ni < 4; ni++) {
        const int n = tn + wn * 32 + ni * 8 + tig * 2;
        const float b0 = bias[n], b1 = bias[n + 1];
        const int hh = n >> 6, dd = n & 63;
#pragma unroll
        for (int mi = 0; mi < 4; mi++) {
#pragma unroll
            for (int half = 0; half < 2; half++) {
                int m = tm + wm * 64 + mi * 16 + g + half * 8;
                float vx = acc[mi][ni][half * 2 + 0] + b0;
                float vy = acc[mi][ni][half * 2 + 1] + b1;
                int bb = m >> 11, ss = m & 2047;
                size_t idx = (((size_t)(bb * NH + hh) * S_LEN) + ss) * HD + dd;
                __nv_bfloat16 hx = __float2bfloat16(vx);
                __nv_bfloat16 hy = __float2bfloat16(vy);
                __nv_bfloat16 lx = __float2bfloat16(vx - __bfloat162float(hx));
                __nv_bfloat16 ly = __float2bfloat16(vy - __bfloat162float(hy));
                *(__nv_bfloat162*)(Chi + idx) = __halves2bfloat162(hx, hy);
                *(__nv_bfloat162*)(Clo + idx) = __halves2bfloat162(lx, ly);
            }
        }
    }
}

// output projection GEMM: fp32 C row-major
__global__ void __launch_bounds__(256, 2)
gemm_out(const __nv_bfloat16* __restrict__ Ahi, const __nv_bfloat16* __restrict__ Alo,
         const __nv_bfloat16* __restrict__ Bhi, const __nv_bfloat16* __restrict__ Blo,
         const float* __restrict__ bias, float* __restrict__ C)
{
    extern __shared__ char smem[];
    const uint32_t sb = smem_u32(smem);
    const int tid = threadIdx.x;
    const int wid = tid >> 5;
    const int lid = tid & 31;
    const int tm  = blockIdx.y * 128;
    const int tn  = blockIdx.x * 128;
    const int wm  = wid >> 2;
    const int wn  = wid & 3;

    const __nv_bfloat16* gA[2] = { Ahi + (size_t)tm * EMB, Alo + (size_t)tm * EMB };
    const __nv_bfloat16* gB[2] = { Bhi + (size_t)tn * EMB, Blo + (size_t)tn * EMB };

    GEMM_STAGE_LAMBDA()
    GEMM_MAINLOOP()

    const int g   = lid >> 2;
    const int tig = lid & 3;
#pragma unroll
    for (int ni = 0; ni < 4; ni++) {
        const int n = tn + wn * 32 + ni * 8 + tig * 2;
        const float b0 = bias[n], b1 = bias[n + 1];
#pragma unroll
        for (int mi = 0; mi < 4; mi++) {
#pragma unroll
            for (int half = 0; half < 2; half++) {
                int m = tm + wm * 64 + mi * 16 + g + half * 8;
                float2 v;
                v.x = acc[mi][ni][half * 2 + 0] + b0;
                v.y = acc[mi][ni][half * 2 + 1] + b1;
                *(float2*)(C + (size_t)m * EMB + n) = v;
            }
        }
    }
}

// ---------------------------------------------------------------------------
// Flash attention: 8 warps x 16 q-rows, Q persistent smem (SW128),
//                  2-stage KV with mbarrier pipeline, 2 CTAs/SM, x4 ldmatrix
// ---------------------------------------------------------------------------
#define FQ_H  0
#define FQ_L  16384
#define F_KH  0
#define F_KL  8192
#define F_VH  16384
#define F_VL  24576
#define F_STAGE 32768
#define F_STG0 32768
#define F_MB   (F_STG0 + 2 * F_STAGE)      // 98304
#define FLASH_SMEM (F_MB + 32)             // 98336
#define NCHUNK (S_LEN / 64)                // 32

__global__ void __launch_bounds__(256, 2)
flash_mma(const __nv_bfloat16* __restrict__ Qhi, const __nv_bfloat16* __restrict__ Qlo,
          const __nv_bfloat16* __restrict__ Khi, const __nv_bfloat16* __restrict__ Klo,
          const __nv_bfloat16* __restrict__ Vhi, const __nv_bfloat16* __restrict__ Vlo,
          __nv_bfloat16* __restrict__ Ohi, __nv_bfloat16* __restrict__ Olo)
{
    extern __shared__ char smem[];
    const uint32_t sb = smem_u32(smem);
    const int tid = threadIdx.x;
    const int wid = tid >> 5;
    const int lid = tid & 31;
    const int bh  = blockIdx.y;
    const int b   = bh >> 4;
    const int h   = bh & 15;
    const int q0  = blockIdx.x * 128;

    const __nv_bfloat16* Qh_g = Qhi + ((size_t)bh * S_LEN + q0) * HD;
    const __nv_bfloat16* Ql_g = Qlo + ((size_t)bh * S_LEN + q0) * HD;
    const __nv_bfloat16* Kh_g = Khi + (size_t)bh * S_LEN * HD;
    const __nv_bfloat16* Kl_g = Klo + (size_t)bh * S_LEN * HD;
    const __nv_bfloat16* Vh_g = Vhi + (size_t)bh * S_LEN * HD;
    const __nv_bfloat16* Vl_g = Vlo + (size_t)bh * S_LEN * HD;

    // mbarrier init: full[s] @ F_MB+s*16, empty[s] @ F_MB+s*16+8
    if (tid == 0) {
#pragma unroll
        for (int s = 0; s < 2; s++) {
            MBAR_INIT(sb + F_MB + s * 16, 256);
            MBAR_INIT(sb + F_MB + s * 16 + 8, 256);
        }
    }
    __syncthreads();

    // ---- KV staging ----
    const int s_row = tid >> 2;
    auto stage = [&](int buf, int c) {
        const uint32_t base = sb + F_STG0 + buf * F_STAGE;
        const size_t gbase = (size_t)(c * 64 + s_row) * HD;
#pragma unroll
        for (int t = 0; t < 2; t++) {
            int seg = (tid & 3) * 2 + t;
            uint32_t so = sw128((uint32_t)(s_row * 128 + seg * 16));
            const size_t go = gbase + seg * 8;
            cp_async16(base + F_KH + so, Kh_g + go);
            cp_async16(base + F_KL + so, Kl_g + go);
            cp_async16(base + F_VH + so, Vh_g + go);
            cp_async16(base + F_VL + so, Vl_g + go);
        }
    };

    int pstage = 0, pphase = 1, cstage = 0, cphase = 0;
    auto stage_issue = [&](int c) {
        uint32_t fb = sb + F_MB + pstage * 16;
        mbar_wait(fb + 8, pphase);
        stage(pstage, c);
        CPASYNC_MBAR_ARRIVE(fb);
        if (++pstage == 2) { pstage = 0; pphase ^= 1; }
    };

    stage_issue(0);   // prefetch first KV chunk, overlaps Q staging below

    // ---- stage Q (128 x 64) hi/lo into persistent swizzled smem ----
    {
        int row = tid >> 1;
#pragma unroll
        for (int t = 0; t < 4; t++) {
            int seg = (tid & 1) * 4 + t;
            uint32_t so = sw128((uint32_t)(row * 128 + seg * 16));
            *(uint4*)(smem + FQ_H + so) = *(const uint4*)(Qh_g + (size_t)row * HD + seg * 8);
            *(uint4*)(smem + FQ_L + so) = *(const uint4*)(Ql_g + (size_t)row * HD + seg * 8);
        }
    }
    __syncthreads();   // Q visibility

    float o[8][4];
#pragma unroll
    for (int ni = 0; ni < 8; ni++)
#pragma unroll
        for (int j = 0; j < 4; j++) o[ni][j] = 0.0f;
    float m0 = -1e30f, m1 = -1e30f, l0 = 0.0f, l1 = 0.0f;

    const int a_row  = wid * 16 + (lid & 15);
    const int a_c    = (lid >> 4);
    const int kb_row = (lid & 7) + ((lid >> 4) << 3);
    const int kb_c   = (lid >> 3) & 1;
    const int v_row4 = (lid & 7) + (((lid >> 3) & 1) << 3);
    const int v_nh   = (lid >> 4);

#pragma unroll 1
    for (int c = 0; c < NCHUNK; c++) {
        mbar_wait(sb + F_MB + cstage * 16, cphase);
        if (c + 1 < NCHUNK) stage_issue(c + 1);
        const uint32_t bufb = sb + F_STG0 + cstage * F_STAGE;

        // ---- scores: S = Qh·Kh + Qh·Kl + Ql·Kh ----
        float sc[8][4];
#pragma unroll
        for (int ni = 0; ni < 8; ni++)
#pragma unroll
            for (int j = 0; j < 4; j++) sc[ni][j] = 0.0f;

#pragma unroll
        for (int ks = 0; ks < 4; ks++) {
            uint32_t qh4[4], ql4[4];
            uint32_t ra = sw128((uint32_t)(a_row * 128 + (ks * 2 + a_c) * 16));
            ldm_x4(qh4, sb + FQ_H + ra);
            ldm_x4(ql4, sb + FQ_L + ra);
#pragma unroll
            for (int n2 = 0; n2 < 4; n2++) {
                uint32_t rb = sw128((uint32_t)((n2 * 16 + kb_row) * 128 + (ks * 2 + kb_c) * 16));
                uint32_t t4[4];
                uint32_t kh0[2], kh1[2], kl0[2], kl1[2];
                ldm_x4(t4, bufb + F_KH + rb);
                kh0[0] = t4[0]; kh0[1] = t4[1]; kh1[0] = t4[2]; kh1[1] = t4[3];
                ldm_x4(t4, bufb + F_KL + rb);
                kl0[0] = t4[0]; kl0[1] = t4[1]; kl1[0] = t4[2]; kl1[1] = t4[3];
                mma_bf16(sc[n2 * 2 + 0], qh4, kh0);
                mma_bf16(sc[n2 * 2 + 1], qh4, kh1);
                mma_bf16(sc[n2 * 2 + 0], qh4, kl0);
                mma_bf16(sc[n2 * 2 + 1], qh4, kl1);
                mma_bf16(sc[n2 * 2 + 0], ql4, kh0);
                mma_bf16(sc[n2 * 2 + 1], ql4, kh1);
            }
        }

        // ---- online softmax ----
        float mx0 = -1e30f, mx1 = -1e30f;
#pragma unroll
        for (int ni = 0; ni < 8; ni++) {
            mx0 = fmaxf(mx0, fmaxf(sc[ni][0], sc[ni][1]));
            mx1 = fmaxf(mx1, fmaxf(sc[ni][2], sc[ni][3]));
        }
        mx0 *= 0.125f; mx1 *= 0.125f;
        mx0 = fmaxf(mx0, __shfl_xor_sync(~0u, mx0, 1));
        mx0 = fmaxf(mx0, __shfl_xor_sync(~0u, mx0, 2));
        mx1 = fmaxf(mx1, __shfl_xor_sync(~0u, mx1, 1));
        mx1 = fmaxf(mx1, __shfl_xor_sync(~0u, mx1, 2));
        float mn0 = fmaxf(m0, mx0), mn1 = fmaxf(m1, mx1);
        float corr0 = __expf(m0 - mn0), corr1 = __expf(m1 - mn1);
        m0 = mn0; m1 = mn1;

        float s0 = 0.0f, s1 = 0.0f;
#pragma unroll
        for (int ni = 0; ni < 8; ni++) {
            sc[ni][0] = __expf(fmaf(sc[ni][0], 0.125f, -mn0));
            sc[ni][1] = __expf(fmaf(sc[ni][1], 0.125f, -mn0));
            sc[ni][2] = __expf(fmaf(sc[ni][2], 0.125f, -mn1));
            sc[ni][3] = __expf(fmaf(sc[ni][3], 0.125f, -mn1));
            s0 += sc[ni][0] + sc[ni][1];
            s1 += sc[ni][2] + sc[ni][3];
        }
        s0 += __shfl_xor_sync(~0u, s0, 1);
        s0 += __shfl_xor_sync(~0u, s0, 2);
        s1 += __shfl_xor_sync(~0u, s1, 1);
        s1 += __shfl_xor_sync(~0u, s1, 2);
        l0 = l0 * corr0 + s0;
        l1 = l1 * corr1 + s1;

#pragma unroll
        for (int ni = 0; ni < 8; ni++) {
            o[ni][0] *= corr0; o[ni][1] *= corr0;
            o[ni][2] *= corr1; o[ni][3] *= corr1;
        }

        // ---- pack P into A-fragments (hi/lo) ----
        uint32_t ph[4][4], pl[4][4];
#pragma unroll
        for (int kk = 0; kk < 4; kk++) {
            float p00 = sc[2 * kk][0],     p01 = sc[2 * kk][1];
            float p02 = sc[2 * kk][2],     p03 = sc[2 * kk][3];
            float p10 = sc[2 * kk + 1][0], p11 = sc[2 * kk + 1][1];
            float p12 = sc[2 * kk + 1][2], p13 = sc[2 * kk + 1][3];
            __nv_bfloat16 h00 = __float2bfloat16(p00), h01 = __float2bfloat16(p01);
            __nv_bfloat16 h02 = __float2bfloat16(p02), h03 = __float2bfloat16(p03);
            __nv_bfloat16 h10 = __float2bfloat16(p10), h11 = __float2bfloat16(p11);
            __nv_bfloat16 h12 = __float2bfloat16(p12), h13 = __float2bfloat16(p13);
            ph[kk][0] = pack_bf16x2(p00, p01);
            ph[kk][1] = pack_bf16x2(p02, p03);
            ph[kk][2] = pack_bf16x2(p10, p11);
            ph[kk][3] = pack_bf16x2(p12, p13);
            pl[kk][0] = pack_bf16x2(p00 - __bfloat162float(h00), p01 - __bfloat162float(h01));
            pl[kk][1] = pack_bf16x2(p02 - __bfloat162float(h02), p03 - __bfloat162float(h03));
            pl[kk][2] = pack_bf16x2(p10 - __bfloat162float(h10), p11 - __bfloat162float(h11));
            pl[kk][3] = pack_bf16x2(p12 - __bfloat162float(h12), p13 - __bfloat162float(h13));
        }

        // ---- O += Ph·Vh + Ph·Vl + Pl·Vh ----
#pragma unroll
        for (int ks = 0; ks < 4; ks++) {
#pragma unroll
            for (int n2 = 0; n2 < 4; n2++) {
                uint32_t rv = sw128((uint32_t)((ks * 16 + v_row4) * 128 + (n2 * 2 + v_nh) * 16));
                uint32_t t4[4];
                uint32_t vh0[2], vh1[2], vl0[2], vl1[2];
                ldm_x4_t(t4, bufb + F_VH + rv);
                vh0[0] = t4[0]; vh0[1] = t4[1]; vh1[0] = t4[2]; vh1[1] = t4[3];
                ldm_x4_t(t4, bufb + F_VL + rv);
                vl0[0] = t4[0]; vl0[1] = t4[1]; vl1[0] = t4[2]; vl1[1] = t4[3];
                mma_bf16(o[n2 * 2 + 0], ph[ks], vh0);
                mma_bf16(o[n2 * 2 + 1], ph[ks], vh1);
                mma_bf16(o[n2 * 2 + 0], ph[ks], vl0);
                mma_bf16(o[n2 * 2 + 1], ph[ks], vl1);
                mma_bf16(o[n2 * 2 + 0], pl[ks], vh0);
                mma_bf16(o[n2 * 2 + 1], pl[ks], vh1);
            }
        }

        MBAR_ARRIVE(sb + F_MB + cstage * 16 + 8);
        if (++cstage == 2) { cstage = 0; cphase ^= 1; }
    }

    // ---- epilogue ----
    const int g   = lid >> 2;
    const int tig = lid & 3;
    const float inv0 = 1.0f / l0, inv1 = 1.0f / l1;
#pragma unroll
    for (int half = 0; half < 2; half++) {
        int s = q0 + wid * 16 + g + half * 8;
        float inv = half ? inv1 : inv0;
        size_t rowbase = ((size_t)(b * S_LEN + s)) * EMB + h * HD;
#pragma unroll
        for (int ni = 0; ni < 8; ni++) {
            float vx = o[ni][half * 2 + 0] * inv;
            float vy = o[ni][half * 2 + 1] * inv;
            __nv_bfloat16 hx = __float2bfloat16(vx);
            __nv_bfloat16 hy = __float2bfloat16(vy);
            __nv_bfloat16 lx = __float2bfloat16(vx - __bfloat162float(hx));
            __nv_bfloat16 ly = __float2bfloat16(vy - __bfloat162float(hy));
            size_t idx = rowbase + ni * 8 + tig * 2;
            *(__nv_bfloat162*)(Ohi + idx) = __halves2bfloat162(hx, hy);
            *(__nv_bfloat162*)(Olo + idx) = __halves2bfloat162(lx, ly);
        }
    }
}

// ---------------------------------------------------------------------------
// Launch
// ---------------------------------------------------------------------------
extern "C" void kernel_launch(void* const* d_in, const int* in_sizes, int n_in,
                              void* d_out, int out_size)
{
    const float* x  = (const float*)d_in[0];
    const float* Wq = (const float*)d_in[1];
    const float* bq = (const float*)d_in[2];
    const float* Wk = (const float*)d_in[3];
    const float* bk = (const float*)d_in[4];
    const float* Wv = (const float*)d_in[5];
    const float* bv = (const float*)d_in[6];
    const float* Wo = (const float*)d_in[7];
    const float* bo = (const float*)d_in[8];
    float* out = (float*)d_out;

    __nv_bfloat16 *xhi, *xlo, *whi, *wlo, *ahi, *alo;
    __nv_bfloat16 *qhi, *qlo, *khi, *klo, *vhi, *vlo;
    cudaGetSymbolAddress((void**)&xhi, g_xhi);
    cudaGetSymbolAddress((void**)&xlo, g_xlo);
    cudaGetSymbolAddress((void**)&whi, g_whi);
    cudaGetSymbolAddress((void**)&wlo, g_wlo);
    cudaGetSymbolAddress((void**)&ahi, g_ahi);
    cudaGetSymbolAddress((void**)&alo, g_alo);
    cudaGetSymbolAddress((void**)&qhi, g_qhi);
    cudaGetSymbolAddress((void**)&qlo, g_qlo);
    cudaGetSymbolAddress((void**)&khi, g_khi);
    cudaGetSymbolAddress((void**)&klo, g_klo);
    cudaGetSymbolAddress((void**)&vhi, g_vhi);
    cudaGetSymbolAddress((void**)&vlo, g_vlo);

    cudaFuncSetAttribute(gemm_qkv, cudaFuncAttributeMaxDynamicSharedMemorySize, GEMM_SMEM);
    cudaFuncSetAttribute(gemm_out, cudaFuncAttributeMaxDynamicSharedMemorySize, GEMM_SMEM);
    cudaFuncSetAttribute(flash_mma, cudaFuncAttributeMaxDynamicSharedMemorySize, FLASH_SMEM);

    convert_all<<<(N4ALL + 255) / 256, 256>>>((const float4*)x,
        (const float4*)Wq, (const float4*)Wk, (const float4*)Wv, (const float4*)Wo,
        xhi, xlo, whi, wlo);

    dim3 gq(24, M_TOT / 128);          // fused QKV
    gemm_qkv<<<gq, 256, GEMM_SMEM>>>(xhi, xlo, whi, wlo, bq, bk, bv,
                                     qhi, qlo, khi, klo, vhi, vlo);

    dim3 ga(S_LEN / 128, BH);          // (16, 64)
    flash_mma<<<ga, 256, FLASH_SMEM>>>(qhi, qlo, khi, klo, vhi, vlo, ahi, alo);

    dim3 gg(EMB / 128, M_TOT / 128);   // (8, 64)
    gemm_out<<<gg, 256, GEMM_SMEM>>>(ahi, alo, whi + 3 * WSZ, wlo + 3 * WSZ, bo, out);
}

// round 14
// speedup vs baseline: 1.1818x; 1.0233x over previous
#include <cuda_runtime.h>
#include <cuda_bf16.h>
#include <cstdint>

#define BATCH 4
#define S_LEN 2048
#define EMB   1024
#define NH    16
#define HD    64
#define M_TOT (BATCH * S_LEN)   // 8192
#define BH    (BATCH * NH)      // 64
#define WSZ   ((size_t)EMB * EMB)

// ---------------------------------------------------------------------------
// Scratch (device globals — no allocation allowed)
// ---------------------------------------------------------------------------
__device__ __nv_bfloat16 g_xhi[(size_t)M_TOT * EMB];
__device__ __nv_bfloat16 g_xlo[(size_t)M_TOT * EMB];
__device__ __nv_bfloat16 g_whi[4][WSZ];
__device__ __nv_bfloat16 g_wlo[4][WSZ];
__device__ __nv_bfloat16 g_qhi[(size_t)BH * S_LEN * HD];
__device__ __nv_bfloat16 g_qlo[(size_t)BH * S_LEN * HD];
__device__ __nv_bfloat16 g_khi[(size_t)BH * S_LEN * HD];
__device__ __nv_bfloat16 g_klo[(size_t)BH * S_LEN * HD];
__device__ __nv_bfloat16 g_vhi[(size_t)BH * S_LEN * HD];
__device__ __nv_bfloat16 g_vlo[(size_t)BH * S_LEN * HD];
__device__ __nv_bfloat16 g_ahi[(size_t)M_TOT * EMB];
__device__ __nv_bfloat16 g_alo[(size_t)M_TOT * EMB];

// ---------------------------------------------------------------------------
// helpers
// ---------------------------------------------------------------------------
__device__ __forceinline__ uint32_t smem_u32(const void* p) {
    uint32_t a;
    asm("{ .reg .u64 t; cvta.to.shared.u64 t, %1; cvt.u32.u64 %0, t; }"
        : "=r"(a) : "l"(p));
    return a;
}
__device__ __forceinline__ void cp_async16(uint32_t dst, const void* src) {
    asm volatile("cp.async.cg.shared.global [%0], [%1], 16;"
                 :: "r"(dst), "l"(__cvta_generic_to_global(src)) : "memory");
}
#define MBAR_INIT(mbar, cnt) \
    asm volatile("mbarrier.init.shared.b64 [%0], %1;" :: "r"(mbar), "r"(cnt) : "memory")
#define MBAR_ARRIVE(mbar) \
    asm volatile("mbarrier.arrive.shared::cta.b64 _, [%0];" :: "r"(mbar) : "memory")
#define CPASYNC_MBAR_ARRIVE(mbar) \
    asm volatile("cp.async.mbarrier.arrive.noinc.shared::cta.b64 [%0];" :: "r"(mbar) : "memory")

__device__ __forceinline__ void mbar_wait(uint32_t mbar, uint32_t parity) {
    asm volatile(
        "{\n\t.reg .pred P;\n\t"
        "W_%=:\n\t"
        "mbarrier.try_wait.parity.acquire.cta.shared::cta.b64 P, [%0], %1, 0x989680;\n\t"
        "@P bra D_%=;\n\t"
        "bra W_%=;\n\t"
        "D_%=:\n\t}"
        :: "r"(mbar), "r"(parity) : "memory");
}

__device__ __forceinline__ void ldm_x4(uint32_t* r, uint32_t addr) {
    asm volatile("ldmatrix.sync.aligned.m8n8.x4.shared.b16 {%0,%1,%2,%3}, [%4];"
                 : "=r"(r[0]), "=r"(r[1]), "=r"(r[2]), "=r"(r[3]) : "r"(addr));
}
__device__ __forceinline__ void ldm_x4_t(uint32_t* r, uint32_t addr) {
    asm volatile("ldmatrix.sync.aligned.m8n8.x4.trans.shared.b16 {%0,%1,%2,%3}, [%4];"
                 : "=r"(r[0]), "=r"(r[1]), "=r"(r[2]), "=r"(r[3]) : "r"(addr));
}
__device__ __forceinline__ void mma_bf16(float* c, const uint32_t* a, const uint32_t* b) {
    asm volatile(
        "mma.sync.aligned.m16n8k16.row.col.f32.bf16.bf16.f32 "
        "{%0,%1,%2,%3}, {%4,%5,%6,%7}, {%8,%9}, {%0,%1,%2,%3};"
        : "+f"(c[0]), "+f"(c[1]), "+f"(c[2]), "+f"(c[3])
        : "r"(a[0]), "r"(a[1]), "r"(a[2]), "r"(a[3]), "r"(b[0]), "r"(b[1]));
}
__device__ __forceinline__ uint32_t pack_bf16x2(float lo, float hi) {
    uint32_t r;
    asm("cvt.rn.bf16x2.f32 %0, %1, %2;" : "=r"(r) : "f"(hi), "f"(lo));
    return r;
}
__device__ __forceinline__ uint32_t sw64(int row, int c) {
    return (uint32_t)(row * 64 + (((c) ^ ((row >> 1) & 3)) << 4));
}
__device__ __forceinline__ uint32_t sw128(uint32_t off) {
    return off ^ ((off >> 3) & 0x70);
}

// ---------------------------------------------------------------------------
// single fused convert: x + 4 weights -> bf16 hi/lo
// ---------------------------------------------------------------------------
#define N4X (M_TOT * EMB / 4)
#define N4W (EMB * EMB / 4)
#define N4ALL (N4X + 4 * N4W)

__global__ void __launch_bounds__(256)
convert_all(const float4* __restrict__ x,
            const float4* __restrict__ Wq, const float4* __restrict__ Wk,
            const float4* __restrict__ Wv, const float4* __restrict__ Wo,
            __nv_bfloat16* __restrict__ xhi, __nv_bfloat16* __restrict__ xlo,
            __nv_bfloat16* __restrict__ whi, __nv_bfloat16* __restrict__ wlo)
{
    int i = blockIdx.x * 256 + threadIdx.x;
    if (i >= N4ALL) return;

    const float4* in;
    __nv_bfloat16 *hp, *lp;
    int idx;
    if (i < N4X) {
        in = x; hp = xhi; lp = xlo; idx = i;
    } else {
        int j = i - N4X;
        int w = j >> 18;
        idx = j & (N4W - 1);
        in = (w == 0) ? Wq : (w == 1) ? Wk : (w == 2) ? Wv : Wo;
        hp = whi + (size_t)w * WSZ;
        lp = wlo + (size_t)w * WSZ;
    }
    float4 v = in[idx];
    __nv_bfloat16 h0 = __float2bfloat16(v.x);
    __nv_bfloat16 h1 = __float2bfloat16(v.y);
    __nv_bfloat16 h2 = __float2bfloat16(v.z);
    __nv_bfloat16 h3 = __float2bfloat16(v.w);
    __nv_bfloat16 l0 = __float2bfloat16(v.x - __bfloat162float(h0));
    __nv_bfloat16 l1 = __float2bfloat16(v.y - __bfloat162float(h1));
    __nv_bfloat16 l2 = __float2bfloat16(v.z - __bfloat162float(h2));
    __nv_bfloat16 l3 = __float2bfloat16(v.w - __bfloat162float(h3));
    __nv_bfloat162* h2p = (__nv_bfloat162*)hp;
    __nv_bfloat162* l2p = (__nv_bfloat162*)lp;
    h2p[2 * idx + 0] = __halves2bfloat162(h0, h1);
    h2p[2 * idx + 1] = __halves2bfloat162(h2, h3);
    l2p[2 * idx + 0] = __halves2bfloat162(l0, l1);
    l2p[2 * idx + 1] = __halves2bfloat162(l2, l3);
}

// ---------------------------------------------------------------------------
// GEMM: 128x256 CTA tile, 512 threads (16 warps = 2m x 8n of 64x32), BK=32,
//       swizzled 64B rows, 4-stage mbarrier ring, PAIR consumption
//       (192 HMMA per window), 1 CTA/SM
// ---------------------------------------------------------------------------
#define ST_AH 0
#define ST_AL 8192
#define ST_BH 16384
#define ST_BL 32768
#define STAGE_B 49152
#define MB_OFF (4 * STAGE_B)           // 196608
#define GEMM_SMEM (MB_OFF + 64)        // 196672
#define KITER (EMB / 32)               // 32

// staging for 512 threads: A item = tid (row=tid>>2, c=tid&3);
// B items = tid, tid+512 over 256 rows x 4 chunks
#define GEMM_STAGE_LAMBDA()                                                    \
    auto stage = [&](int buf, int kc) {                                        \
        const uint32_t base = sb + buf * STAGE_B;                              \
        const int arow = tid >> 2, ac = tid & 3;                               \
        const uint32_t soA = sw64(arow, ac);                                   \
        const int gca = kc * 32 + ac * 8;                                      \
        cp_async16(base + ST_AH + soA, gA[0] + (size_t)arow * EMB + gca);      \
        cp_async16(base + ST_AL + soA, gA[1] + (size_t)arow * EMB + gca);      \
        _Pragma("unroll")                                                      \
        for (int t = 0; t < 2; t++) {                                          \
            int item = tid + t * 512;                                          \
            int brow = item >> 2, bc = item & 3;                               \
            uint32_t soB = sw64(brow, bc);                                     \
            int gcb = kc * 32 + bc * 8;                                        \
            cp_async16(base + ST_BH + soB, gB[0] + (size_t)brow * EMB + gcb);  \
            cp_async16(base + ST_BL + soB, gB[1] + (size_t)brow * EMB + gcb);  \
        }                                                                      \
    };

#define GEMM_MAINLOOP()                                                        \
    if (tid == 0) {                                                            \
        _Pragma("unroll")                                                      \
        for (int s = 0; s < 4; s++) {                                          \
            MBAR_INIT(sb + MB_OFF + s * 16, 512);                              \
            MBAR_INIT(sb + MB_OFF + s * 16 + 8, 512);                          \
        }                                                                      \
    }                                                                          \
    __syncthreads();                                                           \
    float acc[4][4][4];                                                        \
    _Pragma("unroll")                                                          \
    for (int i = 0; i < 4; i++)                                                \
        _Pragma("unroll")                                                      \
        for (int j = 0; j < 4; j++)                                            \
            _Pragma("unroll")                                                  \
            for (int k = 0; k < 4; k++) acc[i][j][k] = 0.0f;                   \
    const int a_row  = wm * 64 + (lid & 15);                                   \
    const int a_c    = (lid >> 4);                                             \
    const int b_row4 = wn * 32 + (lid & 7) + ((lid >> 4) << 3);                \
    const int b_c    = (lid >> 3) & 1;                                         \
    auto chunk = [&](uint32_t bufb) {                                          \
        _Pragma("unroll")                                                      \
        for (int ks = 0; ks < 2; ks++) {                                       \
            const int kc0 = ks * 2;                                            \
            uint32_t ah[4][4], al[4][4], bhf[4][2], blf[4][2];                 \
            _Pragma("unroll")                                                  \
            for (int mi = 0; mi < 4; mi++) {                                   \
                uint32_t ra = sw64(a_row + mi * 16, kc0 + a_c);                \
                ldm_x4(ah[mi], bufb + ST_AH + ra);                             \
                ldm_x4(al[mi], bufb + ST_AL + ra);                             \
            }                                                                  \
            _Pragma("unroll")                                                  \
            for (int n2 = 0; n2 < 2; n2++) {                                   \
                uint32_t rb = sw64(b_row4 + n2 * 16, kc0 + b_c);               \
                uint32_t t4[4];                                                \
                ldm_x4(t4, bufb + ST_BH + rb);                                 \
                bhf[n2 * 2][0] = t4[0]; bhf[n2 * 2][1] = t4[1];                \
                bhf[n2 * 2 + 1][0] = t4[2]; bhf[n2 * 2 + 1][1] = t4[3];        \
                ldm_x4(t4, bufb + ST_BL + rb);                                 \
                blf[n2 * 2][0] = t4[0]; blf[n2 * 2][1] = t4[1];                \
                blf[n2 * 2 + 1][0] = t4[2]; blf[n2 * 2 + 1][1] = t4[3];        \
            }                                                                  \
            _Pragma("unroll")                                                  \
            for (int mi = 0; mi < 4; mi++)                                     \
                _Pragma("unroll")                                              \
                for (int ni = 0; ni < 4; ni++) {                               \
                    mma_bf16(acc[mi][ni], ah[mi], bhf[ni]);                    \
                    mma_bf16(acc[mi][ni], ah[mi], blf[ni]);                    \
                    mma_bf16(acc[mi][ni], al[mi], bhf[ni]);                    \
                }                                                              \
        }                                                                      \
    };                                                                         \
    int pstage = 0, pphase = 1;                                                \
    auto stage_issue = [&](int kc) {                                           \
        uint32_t fb = sb + MB_OFF + pstage * 16;                               \
        mbar_wait(fb + 8, pphase);                                             \
        stage(pstage, kc);                                                     \
        CPASYNC_MBAR_ARRIVE(fb);                                               \
        if (++pstage == 4) { pstage = 0; pphase ^= 1; }                        \
    };                                                                         \
    stage_issue(0); stage_issue(1);                                            \
    int cstage = 0, cphase = 0;                                                \
    _Pragma("unroll 1")                                                        \
    for (int kc = 0; kc < KITER; kc += 2) {                                    \
        mbar_wait(sb + MB_OFF + cstage * 16, cphase);                          \
        mbar_wait(sb + MB_OFF + (cstage + 1) * 16, cphase);                    \
        if (kc + 2 < KITER) { stage_issue(kc + 2); stage_issue(kc + 3); }      \
        chunk(sb + cstage * STAGE_B);                                          \
        chunk(sb + (cstage + 1) * STAGE_B);                                    \
        MBAR_ARRIVE(sb + MB_OFF + cstage * 16 + 8);                            \
        MBAR_ARRIVE(sb + MB_OFF + (cstage + 1) * 16 + 8);                      \
        cstage += 2;                                                           \
        if (cstage == 4) { cstage = 0; cphase ^= 1; }                          \
    }

// fused QKV GEMM: grid (12, 64); bn>>2 selects {Q,K,V}, (bn&3)*256 = n-strip
__global__ void __launch_bounds__(512, 1)
gemm_qkv(const __nv_bfloat16* __restrict__ Ahi, const __nv_bfloat16* __restrict__ Alo,
         const __nv_bfloat16* __restrict__ Whi, const __nv_bfloat16* __restrict__ Wlo,
         const float* __restrict__ bq, const float* __restrict__ bk,
         const float* __restrict__ bv,
         __nv_bfloat16* __restrict__ qhi, __nv_bfloat16* __restrict__ qlo,
         __nv_bfloat16* __restrict__ khi, __nv_bfloat16* __restrict__ klo,
         __nv_bfloat16* __restrict__ vhi, __nv_bfloat16* __restrict__ vlo)
{
    extern __shared__ char smem[];
    const uint32_t sb = smem_u32(smem);
    const int tid = threadIdx.x;
    const int wid = tid >> 5;
    const int lid = tid & 31;
    const int bn  = blockIdx.x;
    const int w   = bn >> 2;
    const int tm  = blockIdx.y * 128;
    const int tn  = (bn & 3) * 256;
    const int wm  = wid >> 3;          // 0..1
    const int wn  = wid & 7;           // 0..7

    const float* bias = (w == 0) ? bq : (w == 1) ? bk : bv;
    __nv_bfloat16* Chi = (w == 0) ? qhi : (w == 1) ? khi : vhi;
    __nv_bfloat16* Clo = (w == 0) ? qlo : (w == 1) ? klo : vlo;

    const __nv_bfloat16* gA[2] = { Ahi + (size_t)tm * EMB, Alo + (size_t)tm * EMB };
    const __nv_bfloat16* gB[2] = { Whi + (size_t)w * WSZ + (size_t)tn * EMB,
                                   Wlo + (size_t)w * WSZ + (size_t)tn * EMB };

    GEMM_STAGE_LAMBDA()
    GEMM_MAINLOOP()

    // epilogue: split bf16, scatter to [B,H,S,D]
    const int g   = lid >> 2;
    const int tig = lid & 3;
#pragma unroll
    for (int ni = 0; ni < 4; ni++) {
        const int n = tn + wn * 32 + ni * 8 + tig * 2;
        const float b0 = bias[n], b1 = bias[n + 1];
        const int hh = n >> 6, dd = n & 63;
#pragma unroll
        for (int mi = 0; mi < 4; mi++) {
#pragma unroll
            for (int half = 0; half < 2; half++) {
                int m = tm + wm * 64 + mi * 16 + g + half * 8;
                float vx = acc[mi][ni][half * 2 + 0] + b0;
                float vy = acc[mi][ni][half * 2 + 1] + b1;
                int bb = m >> 11, ss = m & 2047;
                size_t idx = (((size_t)(bb * NH + hh) * S_LEN) + ss) * HD + dd;
                __nv_bfloat16 hx = __float2bfloat16(vx);
                __nv_bfloat16 hy = __float2bfloat16(vy);
                __nv_bfloat16 lx = __float2bfloat16(vx - __bfloat162float(hx));
                __nv_bfloat16 ly = __float2bfloat16(vy - __bfloat162float(hy));
                *(__nv_bfloat162*)(Chi + idx) = __halves2bfloat162(hx, hy);
                *(__nv_bfloat162*)(Clo + idx) = __halves2bfloat162(lx, ly);
            }
        }
    }
}

// output projection GEMM: grid (4, 64), fp32 C row-major
__global__ void __launch_bounds__(512, 1)
gemm_out(const __nv_bfloat16* __restrict__ Ahi, const __nv_bfloat16* __restrict__ Alo,
         const __nv_bfloat16* __restrict__ Bhi, const __nv_bfloat16* __restrict__ Blo,
         const float* __restrict__ bias, float* __restrict__ C)
{
    extern __shared__ char smem[];
    const uint32_t sb = smem_u32(smem);
    const int tid = threadIdx.x;
    const int wid = tid >> 5;
    const int lid = tid & 31;
    const int tm  = blockIdx.y * 128;
    const int tn  = blockIdx.x * 256;
    const int wm  = wid >> 3;
    const int wn  = wid & 7;

    const __nv_bfloat16* gA[2] = { Ahi + (size_t)tm * EMB, Alo + (size_t)tm * EMB };
    const __nv_bfloat16* gB[2] = { Bhi + (size_t)tn * EMB, Blo + (size_t)tn * EMB };

    GEMM_STAGE_LAMBDA()
    GEMM_MAINLOOP()

    const int g   = lid >> 2;
    const int tig = lid & 3;
#pragma unroll
    for (int ni = 0; ni < 4; ni++) {
        const int n = tn + wn * 32 + ni * 8 + tig * 2;
        const float b0 = bias[n], b1 = bias[n + 1];
#pragma unroll
        for (int mi = 0; mi < 4; mi++) {
#pragma unroll
            for (int half = 0; half < 2; half++) {
                int m = tm + wm * 64 + mi * 16 + g + half * 8;
                float2 v;
                v.x = acc[mi][ni][half * 2 + 0] + b0;
                v.y = acc[mi][ni][half * 2 + 1] + b1;
                *(float2*)(C + (size_t)m * EMB + n) = v;
            }
        }
    }
}

// ---------------------------------------------------------------------------
// Flash attention (unchanged from R13 winner): 8 warps x 16 q-rows,
// Q persistent smem (SW128), 2-stage KV mbarrier pipeline, 2 CTAs/SM
// ---------------------------------------------------------------------------
#define FQ_H  0
#define FQ_L  16384
#define F_KH  0
#define F_KL  8192
#define F_VH  16384
#define F_VL  24576
#define F_STAGE 32768
#define F_STG0 32768
#define F_MB   (F_STG0 + 2 * F_STAGE)
#define FLASH_SMEM (F_MB + 32)
#define NCHUNK (S_LEN / 64)

__global__ void __launch_bounds__(256, 2)
flash_mma(const __nv_bfloat16* __restrict__ Qhi, const __nv_bfloat16* __restrict__ Qlo,
          const __nv_bfloat16* __restrict__ Khi, const __nv_bfloat16* __restrict__ Klo,
          const __nv_bfloat16* __restrict__ Vhi, const __nv_bfloat16* __restrict__ Vlo,
          __nv_bfloat16* __restrict__ Ohi, __nv_bfloat16* __restrict__ Olo)
{
    extern __shared__ char smem[];
    const uint32_t sb = smem_u32(smem);
    const int tid = threadIdx.x;
    const int wid = tid >> 5;
    const int lid = tid & 31;
    const int bh  = blockIdx.y;
    const int b   = bh >> 4;
    const int h   = bh & 15;
    const int q0  = blockIdx.x * 128;

    const __nv_bfloat16* Qh_g = Qhi + ((size_t)bh * S_LEN + q0) * HD;
    const __nv_bfloat16* Ql_g = Qlo + ((size_t)bh * S_LEN + q0) * HD;
    const __nv_bfloat16* Kh_g = Khi + (size_t)bh * S_LEN * HD;
    const __nv_bfloat16* Kl_g = Klo + (size_t)bh * S_LEN * HD;
    const __nv_bfloat16* Vh_g = Vhi + (size_t)bh * S_LEN * HD;
    const __nv_bfloat16* Vl_g = Vlo + (size_t)bh * S_LEN * HD;

    if (tid == 0) {
#pragma unroll
        for (int s = 0; s < 2; s++) {
            MBAR_INIT(sb + F_MB + s * 16, 256);
            MBAR_INIT(sb + F_MB + s * 16 + 8, 256);
        }
    }
    __syncthreads();

    const int s_row = tid >> 2;
    auto stage = [&](int buf, int c) {
        const uint32_t base = sb + F_STG0 + buf * F_STAGE;
        const size_t gbase = (size_t)(c * 64 + s_row) * HD;
#pragma unroll
        for (int t = 0; t < 2; t++) {
            int seg = (tid & 3) * 2 + t;
            uint32_t so = sw128((uint32_t)(s_row * 128 + seg * 16));
            const size_t go = gbase + seg * 8;
            cp_async16(base + F_KH + so, Kh_g + go);
            cp_async16(base + F_KL + so, Kl_g + go);
            cp_async16(base + F_VH + so, Vh_g + go);
            cp_async16(base + F_VL + so, Vl_g + go);
        }
    };

    int pstage = 0, pphase = 1, cstage = 0, cphase = 0;
    auto stage_issue = [&](int c) {
        uint32_t fb = sb + F_MB + pstage * 16;
        mbar_wait(fb + 8, pphase);
        stage(pstage, c);
        CPASYNC_MBAR_ARRIVE(fb);
        if (++pstage == 2) { pstage = 0; pphase ^= 1; }
    };

    stage_issue(0);

    {
        int row = tid >> 1;
#pragma unroll
        for (int t = 0; t < 4; t++) {
            int seg = (tid & 1) * 4 + t;
            uint32_t so = sw128((uint32_t)(row * 128 + seg * 16));
            *(uint4*)(smem + FQ_H + so) = *(const uint4*)(Qh_g + (size_t)row * HD + seg * 8);
            *(uint4*)(smem + FQ_L + so) = *(const uint4*)(Ql_g + (size_t)row * HD + seg * 8);
        }
    }
    __syncthreads();

    float o[8][4];
#pragma unroll
    for (int ni = 0; ni < 8; ni++)
#pragma unroll
        for (int j = 0; j < 4; j++) o[ni][j] = 0.0f;
    float m0 = -1e30f, m1 = -1e30f, l0 = 0.0f, l1 = 0.0f;

    const int a_row  = wid * 16 + (lid & 15);
    const int a_c    = (lid >> 4);
    const int kb_row = (lid & 7) + ((lid >> 4) << 3);
    const int kb_c   = (lid >> 3) & 1;
    const int v_row4 = (lid & 7) + (((lid >> 3) & 1) << 3);
    const int v_nh   = (lid >> 4);

#pragma unroll 1
    for (int c = 0; c < NCHUNK; c++) {
        mbar_wait(sb + F_MB + cstage * 16, cphase);
        if (c + 1 < NCHUNK) stage_issue(c + 1);
        const uint32_t bufb = sb + F_STG0 + cstage * F_STAGE;

        float sc[8][4];
#pragma unroll
        for (int ni = 0; ni < 8; ni++)
#pragma unroll
            for (int j = 0; j < 4; j++) sc[ni][j] = 0.0f;

#pragma unroll
        for (int ks = 0; ks < 4; ks++) {
            uint32_t qh4[4], ql4[4];
            uint32_t ra = sw128((uint32_t)(a_row * 128 + (ks * 2 + a_c) * 16));
            ldm_x4(qh4, sb + FQ_H + ra);
            ldm_x4(ql4, sb + FQ_L + ra);
#pragma unroll
            for (int n2 = 0; n2 < 4; n2++) {
                uint32_t rb = sw128((uint32_t)((n2 * 16 + kb_row) * 128 + (ks * 2 + kb_c) * 16));
                uint32_t t4[4];
                uint32_t kh0[2], kh1[2], kl0[2], kl1[2];
                ldm_x4(t4, bufb + F_KH + rb);
                kh0[0] = t4[0]; kh0[1] = t4[1]; kh1[0] = t4[2]; kh1[1] = t4[3];
                ldm_x4(t4, bufb + F_KL + rb);
                kl0[0] = t4[0]; kl0[1] = t4[1]; kl1[0] = t4[2]; kl1[1] = t4[3];
                mma_bf16(sc[n2 * 2 + 0], qh4, kh0);
                mma_bf16(sc[n2 * 2 + 1], qh4, kh1);
                mma_bf16(sc[n2 * 2 + 0], qh4, kl0);
                mma_bf16(sc[n2 * 2 + 1], qh4, kl1);
                mma_bf16(sc[n2 * 2 + 0], ql4, kh0);
                mma_bf16(sc[n2 * 2 + 1], ql4, kh1);
            }
        }

        float mx0 = -1e30f, mx1 = -1e30f;
#pragma unroll
        for (int ni = 0; ni < 8; ni++) {
            mx0 = fmaxf(mx0, fmaxf(sc[ni][0], sc[ni][1]));
            mx1 = fmaxf(mx1, fmaxf(sc[ni][2], sc[ni][3]));
        }
        mx0 *= 0.125f; mx1 *= 0.125f;
        mx0 = fmaxf(mx0, __shfl_xor_sync(~0u, mx0, 1));
        mx0 = fmaxf(mx0, __shfl_xor_sync(~0u, mx0, 2));
        mx1 = fmaxf(mx1, __shfl_xor_sync(~0u, mx1, 1));
        mx1 = fmaxf(mx1, __shfl_xor_sync(~0u, mx1, 2));
        float mn0 = fmaxf(m0, mx0), mn1 = fmaxf(m1, mx1);
        float corr0 = __expf(m0 - mn0), corr1 = __expf(m1 - mn1);
        m0 = mn0; m1 = mn1;

        float s0 = 0.0f, s1 = 0.0f;
#pragma unroll
        for (int ni = 0; ni < 8; ni++) {
            sc[ni][0] = __expf(fmaf(sc[ni][0], 0.125f, -mn0));
            sc[ni][1] = __expf(fmaf(sc[ni][1], 0.125f, -mn0));
            sc[ni][2] = __expf(fmaf(sc[ni][2], 0.125f, -mn1));
            sc[ni][3] = __expf(fmaf(sc[ni][3], 0.125f, -mn1));
            s0 += sc[ni][0] + sc[ni][1];
            s1 += sc[ni][2] + sc[ni][3];
        }
        s0 += __shfl_xor_sync(~0u, s0, 1);
        s0 += __shfl_xor_sync(~0u, s0, 2);
        s1 += __shfl_xor_sync(~0u, s1, 1);
        s1 += __shfl_xor_sync(~0u, s1, 2);
        l0 = l0 * corr0 + s0;
        l1 = l1 * corr1 + s1;

#pragma unroll
        for (int ni = 0; ni < 8; ni++) {
            o[ni][0] *= corr0; o[ni][1] *= corr0;
            o[ni][2] *= corr1; o[ni][3] *= corr1;
        }

        uint32_t ph[4][4], pl[4][4];
#pragma unroll
        for (int kk = 0; kk < 4; kk++) {
            float p00 = sc[2 * kk][0],     p01 = sc[2 * kk][1];
            float p02 = sc[2 * kk][2],     p03 = sc[2 * kk][3];
            float p10 = sc[2 * kk + 1][0], p11 = sc[2 * kk + 1][1];
            float p12 = sc[2 * kk + 1][2], p13 = sc[2 * kk + 1][3];
            __nv_bfloat16 h00 = __float2bfloat16(p00), h01 = __float2bfloat16(p01);
            __nv_bfloat16 h02 = __float2bfloat16(p02), h03 = __float2bfloat16(p03);
            __nv_bfloat16 h10 = __float2bfloat16(p10), h11 = __float2bfloat16(p11);
            __nv_bfloat16 h12 = __float2bfloat16(p12), h13 = __float2bfloat16(p13);
            ph[kk][0] = pack_bf16x2(p00, p01);
            ph[kk][1] = pack_bf16x2(p02, p03);
            ph[kk][2] = pack_bf16x2(p10, p11);
            ph[kk][3] = pack_bf16x2(p12, p13);
            pl[kk][0] = pack_bf16x2(p00 - __bfloat162float(h00), p01 - __bfloat162float(h01));
            pl[kk][1] = pack_bf16x2(p02 - __bfloat162float(h02), p03 - __bfloat162float(h03));
            pl[kk][2] = pack_bf16x2(p10 - __bfloat162float(h10), p11 - __bfloat162float(h11));
            pl[kk][3] = pack_bf16x2(p12 - __bfloat162float(h12), p13 - __bfloat162float(h13));
        }

#pragma unroll
        for (int ks = 0; ks < 4; ks++) {
#pragma unroll
            for (int n2 = 0; n2 < 4; n2++) {
                uint32_t rv = sw128((uint32_t)((ks * 16 + v_row4) * 128 + (n2 * 2 + v_nh) * 16));
                uint32_t t4[4];
                uint32_t vh0[2], vh1[2], vl0[2], vl1[2];
                ldm_x4_t(t4, bufb + F_VH + rv);
                vh0[0] = t4[0]; vh0[1] = t4[1]; vh1[0] = t4[2]; vh1[1] = t4[3];
                ldm_x4_t(t4, bufb + F_VL + rv);
                vl0[0] = t4[0]; vl0[1] = t4[1]; vl1[0] = t4[2]; vl1[1] = t4[3];
                mma_bf16(o[n2 * 2 + 0], ph[ks], vh0);
                mma_bf16(o[n2 * 2 + 1], ph[ks], vh1);
                mma_bf16(o[n2 * 2 + 0], ph[ks], vl0);
                mma_bf16(o[n2 * 2 + 1], ph[ks], vl1);
                mma_bf16(o[n2 * 2 + 0], pl[ks], vh0);
                mma_bf16(o[n2 * 2 + 1], pl[ks], vh1);
            }
        }

        MBAR_ARRIVE(sb + F_MB + cstage * 16 + 8);
        if (++cstage == 2) { cstage = 0; cphase ^= 1; }
    }

    const int g   = lid >> 2;
    const int tig = lid & 3;
    const float inv0 = 1.0f / l0, inv1 = 1.0f / l1;
#pragma unroll
    for (int half = 0; half < 2; half++) {
        int s = q0 + wid * 16 + g + half * 8;
        float inv = half ? inv1 : inv0;
        size_t rowbase = ((size_t)(b * S_LEN + s)) * EMB + h * HD;
#pragma unroll
        for (int ni = 0; ni < 8; ni++) {
            float vx = o[ni][half * 2 + 0] * inv;
            float vy = o[ni][half * 2 + 1] * inv;
            __nv_bfloat16 hx = __float2bfloat16(vx);
            __nv_bfloat16 hy = __float2bfloat16(vy);
            __nv_bfloat16 lx = __float2bfloat16(vx - __bfloat162float(hx));
            __nv_bfloat16 ly = __float2bfloat16(vy - __bfloat162float(hy));
            size_t idx = rowbase + ni * 8 + tig * 2;
            *(__nv_bfloat162*)(Ohi + idx) = __halves2bfloat162(hx, hy);
            *(__nv_bfloat162*)(Olo + idx) = __halves2bfloat162(lx, ly);
        }
    }
}

// ---------------------------------------------------------------------------
// Launch
// ---------------------------------------------------------------------------
extern "C" void kernel_launch(void* const* d_in, const int* in_sizes, int n_in,
                              void* d_out, int out_size)
{
    const float* x  = (const float*)d_in[0];
    const float* Wq = (const float*)d_in[1];
    const float* bq = (const float*)d_in[2];
    const float* Wk = (const float*)d_in[3];
    const float* bk = (const float*)d_in[4];
    const float* Wv = (const float*)d_in[5];
    const float* bv = (const float*)d_in[6];
    const float* Wo = (const float*)d_in[7];
    const float* bo = (const float*)d_in[8];
    float* out = (float*)d_out;

    __nv_bfloat16 *xhi, *xlo, *whi, *wlo, *ahi, *alo;
    __nv_bfloat16 *qhi, *qlo, *khi, *klo, *vhi, *vlo;
    cudaGetSymbolAddress((void**)&xhi, g_xhi);
    cudaGetSymbolAddress((void**)&xlo, g_xlo);
    cudaGetSymbolAddress((void**)&whi, g_whi);
    cudaGetSymbolAddress((void**)&wlo, g_wlo);
    cudaGetSymbolAddress((void**)&ahi, g_ahi);
    cudaGetSymbolAddress((void**)&alo, g_alo);
    cudaGetSymbolAddress((void**)&qhi, g_qhi);
    cudaGetSymbolAddress((void**)&qlo, g_qlo);
    cudaGetSymbolAddress((void**)&khi, g_khi);
    cudaGetSymbolAddress((void**)&klo, g_klo);
    cudaGetSymbolAddress((void**)&vhi, g_vhi);
    cudaGetSymbolAddress((void**)&vlo, g_vlo);

    cudaFuncSetAttribute(gemm_qkv, cudaFuncAttributeMaxDynamicSharedMemorySize, GEMM_SMEM);
    cudaFuncSetAttribute(gemm_out, cudaFuncAttributeMaxDynamicSharedMemorySize, GEMM_SMEM);
    cudaFuncSetAttribute(flash_mma, cudaFuncAttributeMaxDynamicSharedMemorySize, FLASH_SMEM);

    convert_all<<<(N4ALL + 255) / 256, 256>>>((const float4*)x,
        (const float4*)Wq, (const float4*)Wk, (const float4*)Wv, (const float4*)Wo,
        xhi, xlo, whi, wlo);

    dim3 gq(12, M_TOT / 128);          // fused QKV, 256-wide n-strips
    gemm_qkv<<<gq, 512, GEMM_SMEM>>>(xhi, xlo, whi, wlo, bq, bk, bv,
                                     qhi, qlo, khi, klo, vhi, vlo);

    dim3 ga(S_LEN / 128, BH);          // (16, 64)
    flash_mma<<<ga, 256, FLASH_SMEM>>>(qhi, qlo, khi, klo, vhi, vlo, ahi, alo);

    dim3 gg(EMB / 256, M_TOT / 128);   // (4, 64)
    gemm_out<<<gg, 512, GEMM_SMEM>>>(ahi, alo, whi + 3 * WSZ, wlo + 3 * WSZ, bo, out);
}

// round 15
// speedup vs baseline: 1.2463x; 1.0546x over previous
#include <cuda_runtime.h>
#include <cuda_bf16.h>
#include <cstdint>

#define BATCH 4
#define S_LEN 2048
#define EMB   1024
#define NH    16
#define HD    64
#define M_TOT (BATCH * S_LEN)   // 8192
#define BH    (BATCH * NH)      // 64
#define WSZ   ((size_t)EMB * EMB)
#define QSCALE 0.1803368802f    // 0.125 * log2(e)

// ---------------------------------------------------------------------------
// Scratch (device globals — no allocation allowed)
// ---------------------------------------------------------------------------
__device__ __nv_bfloat16 g_xhi[(size_t)M_TOT * EMB];
__device__ __nv_bfloat16 g_xlo[(size_t)M_TOT * EMB];
__device__ __nv_bfloat16 g_whi[4][WSZ];
__device__ __nv_bfloat16 g_wlo[4][WSZ];
__device__ __nv_bfloat16 g_qhi[(size_t)BH * S_LEN * HD];
__device__ __nv_bfloat16 g_qlo[(size_t)BH * S_LEN * HD];
__device__ __nv_bfloat16 g_khi[(size_t)BH * S_LEN * HD];
__device__ __nv_bfloat16 g_klo[(size_t)BH * S_LEN * HD];
__device__ __nv_bfloat16 g_vhi[(size_t)BH * S_LEN * HD];
__device__ __nv_bfloat16 g_vlo[(size_t)BH * S_LEN * HD];
__device__ __nv_bfloat16 g_ahi[(size_t)M_TOT * EMB];
__device__ __nv_bfloat16 g_alo[(size_t)M_TOT * EMB];

// ---------------------------------------------------------------------------
// helpers
// ---------------------------------------------------------------------------
__device__ __forceinline__ uint32_t smem_u32(const void* p) {
    uint32_t a;
    asm("{ .reg .u64 t; cvta.to.shared.u64 t, %1; cvt.u32.u64 %0, t; }"
        : "=r"(a) : "l"(p));
    return a;
}
__device__ __forceinline__ void cp_async16(uint32_t dst, const void* src) {
    asm volatile("cp.async.cg.shared.global [%0], [%1], 16;"
                 :: "r"(dst), "l"(__cvta_generic_to_global(src)) : "memory");
}
#define MBAR_INIT(mbar, cnt) \
    asm volatile("mbarrier.init.shared.b64 [%0], %1;" :: "r"(mbar), "r"(cnt) : "memory")
#define MBAR_ARRIVE(mbar) \
    asm volatile("mbarrier.arrive.shared::cta.b64 _, [%0];" :: "r"(mbar) : "memory")
#define CPASYNC_MBAR_ARRIVE(mbar) \
    asm volatile("cp.async.mbarrier.arrive.noinc.shared::cta.b64 [%0];" :: "r"(mbar) : "memory")

__device__ __forceinline__ void mbar_wait(uint32_t mbar, uint32_t parity) {
    asm volatile(
        "{\n\t.reg .pred P;\n\t"
        "W_%=:\n\t"
        "mbarrier.try_wait.parity.acquire.cta.shared::cta.b64 P, [%0], %1, 0x989680;\n\t"
        "@P bra D_%=;\n\t"
        "bra W_%=;\n\t"
        "D_%=:\n\t}"
        :: "r"(mbar), "r"(parity) : "memory");
}

__device__ __forceinline__ void ldm_x4(uint32_t* r, uint32_t addr) {
    asm volatile("ldmatrix.sync.aligned.m8n8.x4.shared.b16 {%0,%1,%2,%3}, [%4];"
                 : "=r"(r[0]), "=r"(r[1]), "=r"(r[2]), "=r"(r[3]) : "r"(addr));
}
__device__ __forceinline__ void ldm_x4_t(uint32_t* r, uint32_t addr) {
    asm volatile("ldmatrix.sync.aligned.m8n8.x4.trans.shared.b16 {%0,%1,%2,%3}, [%4];"
                 : "=r"(r[0]), "=r"(r[1]), "=r"(r[2]), "=r"(r[3]) : "r"(addr));
}
__device__ __forceinline__ void mma_bf16(float* c, const uint32_t* a, const uint32_t* b) {
    asm volatile(
        "mma.sync.aligned.m16n8k16.row.col.f32.bf16.bf16.f32 "
        "{%0,%1,%2,%3}, {%4,%5,%6,%7}, {%8,%9}, {%0,%1,%2,%3};"
        : "+f"(c[0]), "+f"(c[1]), "+f"(c[2]), "+f"(c[3])
        : "r"(a[0]), "r"(a[1]), "r"(a[2]), "r"(a[3]), "r"(b[0]), "r"(b[1]));
}
__device__ __forceinline__ uint32_t pack_bf16x2(float lo, float hi) {
    uint32_t r;
    asm("cvt.rn.bf16x2.f32 %0, %1, %2;" : "=r"(r) : "f"(hi), "f"(lo));
    return r;
}
__device__ __forceinline__ float ex2f(float x) {
    float r;
    asm("ex2.approx.ftz.f32 %0, %1;" : "=f"(r) : "f"(x));
    return r;
}
__device__ __forceinline__ uint32_t sw64(int row, int c) {
    return (uint32_t)(row * 64 + (((c) ^ ((row >> 1) & 3)) << 4));
}
__device__ __forceinline__ uint32_t sw128(uint32_t off) {
    return off ^ ((off >> 3) & 0x70);
}

// ---------------------------------------------------------------------------
// single fused convert: x + 4 weights -> bf16 hi/lo
// ---------------------------------------------------------------------------
#define N4X (M_TOT * EMB / 4)
#define N4W (EMB * EMB / 4)
#define N4ALL (N4X + 4 * N4W)

__global__ void __launch_bounds__(256)
convert_all(const float4* __restrict__ x,
            const float4* __restrict__ Wq, const float4* __restrict__ Wk,
            const float4* __restrict__ Wv, const float4* __restrict__ Wo,
            __nv_bfloat16* __restrict__ xhi, __nv_bfloat16* __restrict__ xlo,
            __nv_bfloat16* __restrict__ whi, __nv_bfloat16* __restrict__ wlo)
{
    int i = blockIdx.x * 256 + threadIdx.x;
    if (i >= N4ALL) return;

    const float4* in;
    __nv_bfloat16 *hp, *lp;
    int idx;
    if (i < N4X) {
        in = x; hp = xhi; lp = xlo; idx = i;
    } else {
        int j = i - N4X;
        int w = j >> 18;
        idx = j & (N4W - 1);
        in = (w == 0) ? Wq : (w == 1) ? Wk : (w == 2) ? Wv : Wo;
        hp = whi + (size_t)w * WSZ;
        lp = wlo + (size_t)w * WSZ;
    }
    float4 v = in[idx];
    __nv_bfloat16 h0 = __float2bfloat16(v.x);
    __nv_bfloat16 h1 = __float2bfloat16(v.y);
    __nv_bfloat16 h2 = __float2bfloat16(v.z);
    __nv_bfloat16 h3 = __float2bfloat16(v.w);
    __nv_bfloat16 l0 = __float2bfloat16(v.x - __bfloat162float(h0));
    __nv_bfloat16 l1 = __float2bfloat16(v.y - __bfloat162float(h1));
    __nv_bfloat16 l2 = __float2bfloat16(v.z - __bfloat162float(h2));
    __nv_bfloat16 l3 = __float2bfloat16(v.w - __bfloat162float(h3));
    __nv_bfloat162* h2p = (__nv_bfloat162*)hp;
    __nv_bfloat162* l2p = (__nv_bfloat162*)lp;
    h2p[2 * idx + 0] = __halves2bfloat162(h0, h1);
    h2p[2 * idx + 1] = __halves2bfloat162(h2, h3);
    l2p[2 * idx + 0] = __halves2bfloat162(l0, l1);
    l2p[2 * idx + 1] = __halves2bfloat162(l2, l3);
}

// ---------------------------------------------------------------------------
// GEMM: 128x256 CTA tile, 512 threads (16 warps = 2m x 8n of 64x32), BK=32,
//       swizzled 64B rows, 4-stage mbarrier ring, PAIR consumption, 1 CTA/SM
// ---------------------------------------------------------------------------
#define ST_AH 0
#define ST_AL 8192
#define ST_BH 16384
#define ST_BL 32768
#define STAGE_B 49152
#define MB_OFF (4 * STAGE_B)           // 196608
#define GEMM_SMEM (MB_OFF + 64)        // 196672
#define KITER (EMB / 32)               // 32

#define GEMM_STAGE_LAMBDA()                                                    \
    auto stage = [&](int buf, int kc) {                                        \
        const uint32_t base = sb + buf * STAGE_B;                              \
        const int arow = tid >> 2, ac = tid & 3;                               \
        const uint32_t soA = sw64(arow, ac);                                   \
        const int gca = kc * 32 + ac * 8;                                      \
        cp_async16(base + ST_AH + soA, gA[0] + (size_t)arow * EMB + gca);      \
        cp_async16(base + ST_AL + soA, gA[1] + (size_t)arow * EMB + gca);      \
        _Pragma("unroll")                                                      \
        for (int t = 0; t < 2; t++) {                                          \
            int item = tid + t * 512;                                          \
            int brow = item >> 2, bc = item & 3;                               \
            uint32_t soB = sw64(brow, bc);                                     \
            int gcb = kc * 32 + bc * 8;                                        \
            cp_async16(base + ST_BH + soB, gB[0] + (size_t)brow * EMB + gcb);  \
            cp_async16(base + ST_BL + soB, gB[1] + (size_t)brow * EMB + gcb);  \
        }                                                                      \
    };

#define GEMM_MAINLOOP()                                                        \
    if (tid == 0) {                                                            \
        _Pragma("unroll")                                                      \
        for (int s = 0; s < 4; s++) {                                          \
            MBAR_INIT(sb + MB_OFF + s * 16, 512);                              \
            MBAR_INIT(sb + MB_OFF + s * 16 + 8, 512);                          \
        }                                                                      \
    }                                                                          \
    __syncthreads();                                                           \
    float acc[4][4][4];                                                        \
    _Pragma("unroll")                                                          \
    for (int i = 0; i < 4; i++)                                                \
        _Pragma("unroll")                                                      \
        for (int j = 0; j < 4; j++)                                            \
            _Pragma("unroll")                                                  \
            for (int k = 0; k < 4; k++) acc[i][j][k] = 0.0f;                   \
    const int a_row  = wm * 64 + (lid & 15);                                   \
    const int a_c    = (lid >> 4);                                             \
    const int b_row4 = wn * 32 + (lid & 7) + ((lid >> 4) << 3);                \
    const int b_c    = (lid >> 3) & 1;                                         \
    auto chunk = [&](uint32_t bufb) {                                          \
        _Pragma("unroll")                                                      \
        for (int ks = 0; ks < 2; ks++) {                                       \
            const int kc0 = ks * 2;                                            \
            uint32_t ah[4][4], al[4][4], bhf[4][2], blf[4][2];                 \
            _Pragma("unroll")                                                  \
            for (int mi = 0; mi < 4; mi++) {                                   \
                uint32_t ra = sw64(a_row + mi * 16, kc0 + a_c);                \
                ldm_x4(ah[mi], bufb + ST_AH + ra);                             \
                ldm_x4(al[mi], bufb + ST_AL + ra);                             \
            }                                                                  \
            _Pragma("unroll")                                                  \
            for (int n2 = 0; n2 < 2; n2++) {                                   \
                uint32_t rb = sw64(b_row4 + n2 * 16, kc0 + b_c);               \
                uint32_t t4[4];                                                \
                ldm_x4(t4, bufb + ST_BH + rb);                                 \
                bhf[n2 * 2][0] = t4[0]; bhf[n2 * 2][1] = t4[1];                \
                bhf[n2 * 2 + 1][0] = t4[2]; bhf[n2 * 2 + 1][1] = t4[3];        \
                ldm_x4(t4, bufb + ST_BL + rb);                                 \
                blf[n2 * 2][0] = t4[0]; blf[n2 * 2][1] = t4[1];                \
                blf[n2 * 2 + 1][0] = t4[2]; blf[n2 * 2 + 1][1] = t4[3];        \
            }                                                                  \
            _Pragma("unroll")                                                  \
            for (int mi = 0; mi < 4; mi++)                                     \
                _Pragma("unroll")                                              \
                for (int ni = 0; ni < 4; ni++) {                               \
                    mma_bf16(acc[mi][ni], ah[mi], bhf[ni]);                    \
                    mma_bf16(acc[mi][ni], ah[mi], blf[ni]);                    \
                    mma_bf16(acc[mi][ni], al[mi], bhf[ni]);                    \
                }                                                              \
        }                                                                      \
    };                                                                         \
    int pstage = 0, pphase = 1;                                                \
    auto stage_issue = [&](int kc) {                                           \
        uint32_t fb = sb + MB_OFF + pstage * 16;                               \
        mbar_wait(fb + 8, pphase);                                             \
        stage(pstage, kc);                                                     \
        CPASYNC_MBAR_ARRIVE(fb);                                               \
        if (++pstage == 4) { pstage = 0; pphase ^= 1; }                        \
    };                                                                         \
    stage_issue(0); stage_issue(1);                                            \
    int cstage = 0, cphase = 0;                                                \
    _Pragma("unroll 1")                                                        \
    for (int kc = 0; kc < KITER; kc += 2) {                                    \
        mbar_wait(sb + MB_OFF + cstage * 16, cphase);                          \
        mbar_wait(sb + MB_OFF + (cstage + 1) * 16, cphase);                    \
        if (kc + 2 < KITER) { stage_issue(kc + 2); stage_issue(kc + 3); }      \
        chunk(sb + cstage * STAGE_B);                                          \
        chunk(sb + (cstage + 1) * STAGE_B);                                    \
        MBAR_ARRIVE(sb + MB_OFF + cstage * 16 + 8);                            \
        MBAR_ARRIVE(sb + MB_OFF + (cstage + 1) * 16 + 8);                      \
        cstage += 2;                                                           \
        if (cstage == 4) { cstage = 0; cphase ^= 1; }                          \
    }

// fused QKV GEMM: grid (12, 64); bn>>2 selects {Q,K,V}; Q pre-scaled by QSCALE
__global__ void __launch_bounds__(512, 1)
gemm_qkv(const __nv_bfloat16* __restrict__ Ahi, const __nv_bfloat16* __restrict__ Alo,
         const __nv_bfloat16* __restrict__ Whi, const __nv_bfloat16* __restrict__ Wlo,
         const float* __restrict__ bq, const float* __restrict__ bk,
         const float* __restrict__ bv,
         __nv_bfloat16* __restrict__ qhi, __nv_bfloat16* __restrict__ qlo,
         __nv_bfloat16* __restrict__ khi, __nv_bfloat16* __restrict__ klo,
         __nv_bfloat16* __restrict__ vhi, __nv_bfloat16* __restrict__ vlo)
{
    extern __shared__ char smem[];
    const uint32_t sb = smem_u32(smem);
    const int tid = threadIdx.x;
    const int wid = tid >> 5;
    const int lid = tid & 31;
    const int bn  = blockIdx.x;
    const int w   = bn >> 2;
    const int tm  = blockIdx.y * 128;
    const int tn  = (bn & 3) * 256;
    const int wm  = wid >> 3;
    const int wn  = wid & 7;

    const float* bias = (w == 0) ? bq : (w == 1) ? bk : bv;
    __nv_bfloat16* Chi = (w == 0) ? qhi : (w == 1) ? khi : vhi;
    __nv_bfloat16* Clo = (w == 0) ? qlo : (w == 1) ? klo : vlo;
    const float oscale = (w == 0) ? QSCALE : 1.0f;

    const __nv_bfloat16* gA[2] = { Ahi + (size_t)tm * EMB, Alo + (size_t)tm * EMB };
    const __nv_bfloat16* gB[2] = { Whi + (size_t)w * WSZ + (size_t)tn * EMB,
                                   Wlo + (size_t)w * WSZ + (size_t)tn * EMB };

    GEMM_STAGE_LAMBDA()
    GEMM_MAINLOOP()

    // epilogue: scale (Q only), split bf16, scatter to [B,H,S,D]
    const int g   = lid >> 2;
    const int tig = lid & 3;
#pragma unroll
    for (int ni = 0; ni < 4; ni++) {
        const int n = tn + wn * 32 + ni * 8 + tig * 2;
        const float b0 = bias[n], b1 = bias[n + 1];
        const int hh = n >> 6, dd = n & 63;
#pragma unroll
        for (int mi = 0; mi < 4; mi++) {
#pragma unroll
            for (int half = 0; half < 2; half++) {
                int m = tm + wm * 64 + mi * 16 + g + half * 8;
                float vx = (acc[mi][ni][half * 2 + 0] + b0) * oscale;
                float vy = (acc[mi][ni][half * 2 + 1] + b1) * oscale;
                int bb = m >> 11, ss = m & 2047;
                size_t idx = (((size_t)(bb * NH + hh) * S_LEN) + ss) * HD + dd;
                __nv_bfloat16 hx = __float2bfloat16(vx);
                __nv_bfloat16 hy = __float2bfloat16(vy);
                __nv_bfloat16 lx = __float2bfloat16(vx - __bfloat162float(hx));
                __nv_bfloat16 ly = __float2bfloat16(vy - __bfloat162float(hy));
                *(__nv_bfloat162*)(Chi + idx) = __halves2bfloat162(hx, hy);
                *(__nv_bfloat162*)(Clo + idx) = __halves2bfloat162(lx, ly);
            }
        }
    }
}

// output projection GEMM: grid (4, 64), fp32 C row-major
__global__ void __launch_bounds__(512, 1)
gemm_out(const __nv_bfloat16* __restrict__ Ahi, const __nv_bfloat16* __restrict__ Alo,
         const __nv_bfloat16* __restrict__ Bhi, const __nv_bfloat16* __restrict__ Blo,
         const float* __restrict__ bias, float* __restrict__ C)
{
    extern __shared__ char smem[];
    const uint32_t sb = smem_u32(smem);
    const int tid = threadIdx.x;
    const int wid = tid >> 5;
    const int lid = tid & 31;
    const int tm  = blockIdx.y * 128;
    const int tn  = blockIdx.x * 256;
    const int wm  = wid >> 3;
    const int wn  = wid & 7;

    const __nv_bfloat16* gA[2] = { Ahi + (size_t)tm * EMB, Alo + (size_t)tm * EMB };
    const __nv_bfloat16* gB[2] = { Bhi + (size_t)tn * EMB, Blo + (size_t)tn * EMB };

    GEMM_STAGE_LAMBDA()
    GEMM_MAINLOOP()

    const int g   = lid >> 2;
    const int tig = lid & 3;
#pragma unroll
    for (int ni = 0; ni < 4; ni++) {
        const int n = tn + wn * 32 + ni * 8 + tig * 2;
        const float b0 = bias[n], b1 = bias[n + 1];
#pragma unroll
        for (int mi = 0; mi < 4; mi++) {
#pragma unroll
            for (int half = 0; half < 2; half++) {
                int m = tm + wm * 64 + mi * 16 + g + half * 8;
                float2 v;
                v.x = acc[mi][ni][half * 2 + 0] + b0;
                v.y = acc[mi][ni][half * 2 + 1] + b1;
                *(float2*)(C + (size_t)m * EMB + n) = v;
            }
        }
    }
}

// ---------------------------------------------------------------------------
// Flash attention, NO-MAX softmax (scores bounded): P = 2^(s_scaled),
// deferred l reduction. 8 warps x 16 q-rows, Q persistent smem (SW128),
// 2-stage KV mbarrier pipeline, 2 CTAs/SM, x4 ldmatrix.
// ---------------------------------------------------------------------------
#define FQ_H  0
#define FQ_L  16384
#define F_KH  0
#define F_KL  8192
#define F_VH  16384
#define F_VL  24576
#define F_STAGE 32768
#define F_STG0 32768
#define F_MB   (F_STG0 + 2 * F_STAGE)
#define FLASH_SMEM (F_MB + 32)
#define NCHUNK (S_LEN / 64)

__global__ void __launch_bounds__(256, 2)
flash_mma(const __nv_bfloat16* __restrict__ Qhi, const __nv_bfloat16* __restrict__ Qlo,
          const __nv_bfloat16* __restrict__ Khi, const __nv_bfloat16* __restrict__ Klo,
          const __nv_bfloat16* __restrict__ Vhi, const __nv_bfloat16* __restrict__ Vlo,
          __nv_bfloat16* __restrict__ Ohi, __nv_bfloat16* __restrict__ Olo)
{
    extern __shared__ char smem[];
    const uint32_t sb = smem_u32(smem);
    const int tid = threadIdx.x;
    const int wid = tid >> 5;
    const int lid = tid & 31;
    const int bh  = blockIdx.y;
    const int b   = bh >> 4;
    const int h   = bh & 15;
    const int q0  = blockIdx.x * 128;

    const __nv_bfloat16* Qh_g = Qhi + ((size_t)bh * S_LEN + q0) * HD;
    const __nv_bfloat16* Ql_g = Qlo + ((size_t)bh * S_LEN + q0) * HD;
    const __nv_bfloat16* Kh_g = Khi + (size_t)bh * S_LEN * HD;
    const __nv_bfloat16* Kl_g = Klo + (size_t)bh * S_LEN * HD;
    const __nv_bfloat16* Vh_g = Vhi + (size_t)bh * S_LEN * HD;
    const __nv_bfloat16* Vl_g = Vlo + (size_t)bh * S_LEN * HD;

    if (tid == 0) {
#pragma unroll
        for (int s = 0; s < 2; s++) {
            MBAR_INIT(sb + F_MB + s * 16, 256);
            MBAR_INIT(sb + F_MB + s * 16 + 8, 256);
        }
    }
    __syncthreads();

    const int s_row = tid >> 2;
    auto stage = [&](int buf, int c) {
        const uint32_t base = sb + F_STG0 + buf * F_STAGE;
        const size_t gbase = (size_t)(c * 64 + s_row) * HD;
#pragma unroll
        for (int t = 0; t < 2; t++) {
            int seg = (tid & 3) * 2 + t;
            uint32_t so = sw128((uint32_t)(s_row * 128 + seg * 16));
            const size_t go = gbase + seg * 8;
            cp_async16(base + F_KH + so, Kh_g + go);
            cp_async16(base + F_KL + so, Kl_g + go);
            cp_async16(base + F_VH + so, Vh_g + go);
            cp_async16(base + F_VL + so, Vl_g + go);
        }
    };

    int pstage = 0, pphase = 1, cstage = 0, cphase = 0;
    auto stage_issue = [&](int c) {
        uint32_t fb = sb + F_MB + pstage * 16;
        mbar_wait(fb + 8, pphase);
        stage(pstage, c);
        CPASYNC_MBAR_ARRIVE(fb);
        if (++pstage == 2) { pstage = 0; pphase ^= 1; }
    };

    stage_issue(0);

    {
        int row = tid >> 1;
#pragma unroll
        for (int t = 0; t < 4; t++) {
            int seg = (tid & 1) * 4 + t;
            uint32_t so = sw128((uint32_t)(row * 128 + seg * 16));
            *(uint4*)(smem + FQ_H + so) = *(const uint4*)(Qh_g + (size_t)row * HD + seg * 8);
            *(uint4*)(smem + FQ_L + so) = *(const uint4*)(Ql_g + (size_t)row * HD + seg * 8);
        }
    }
    __syncthreads();

    float o[8][4];
#pragma unroll
    for (int ni = 0; ni < 8; ni++)
#pragma unroll
        for (int j = 0; j < 4; j++) o[ni][j] = 0.0f;
    float l0 = 0.0f, l1 = 0.0f;   // deferred-reduction partial sums

    const int a_row  = wid * 16 + (lid & 15);
    const int a_c    = (lid >> 4);
    const int kb_row = (lid & 7) + ((lid >> 4) << 3);
    const int kb_c   = (lid >> 3) & 1;
    const int v_row4 = (lid & 7) + (((lid >> 3) & 1) << 3);
    const int v_nh   = (lid >> 4);

#pragma unroll 1
    for (int c = 0; c < NCHUNK; c++) {
        mbar_wait(sb + F_MB + cstage * 16, cphase);
        if (c + 1 < NCHUNK) stage_issue(c + 1);
        const uint32_t bufb = sb + F_STG0 + cstage * F_STAGE;

        // ---- scores: S = Qh·Kh + Qh·Kl + Ql·Kh  (Q pre-scaled by QSCALE) ----
        float sc[8][4];
#pragma unroll
        for (int ni = 0; ni < 8; ni++)
#pragma unroll
            for (int j = 0; j < 4; j++) sc[ni][j] = 0.0f;

#pragma unroll
        for (int ks = 0; ks < 4; ks++) {
            uint32_t qh4[4], ql4[4];
            uint32_t ra = sw128((uint32_t)(a_row * 128 + (ks * 2 + a_c) * 16));
            ldm_x4(qh4, sb + FQ_H + ra);
            ldm_x4(ql4, sb + FQ_L + ra);
#pragma unroll
            for (int n2 = 0; n2 < 4; n2++) {
                uint32_t rb = sw128((uint32_t)((n2 * 16 + kb_row) * 128 + (ks * 2 + kb_c) * 16));
                uint32_t t4[4];
                uint32_t kh0[2], kh1[2], kl0[2], kl1[2];
                ldm_x4(t4, bufb + F_KH + rb);
                kh0[0] = t4[0]; kh0[1] = t4[1]; kh1[0] = t4[2]; kh1[1] = t4[3];
                ldm_x4(t4, bufb + F_KL + rb);
                kl0[0] = t4[0]; kl0[1] = t4[1]; kl1[0] = t4[2]; kl1[1] = t4[3];
                mma_bf16(sc[n2 * 2 + 0], qh4, kh0);
                mma_bf16(sc[n2 * 2 + 1], qh4, kh1);
                mma_bf16(sc[n2 * 2 + 0], qh4, kl0);
                mma_bf16(sc[n2 * 2 + 1], qh4, kl1);
                mma_bf16(sc[n2 * 2 + 0], ql4, kh0);
                mma_bf16(sc[n2 * 2 + 1], ql4, kh1);
            }
        }

        // ---- no-max softmax: P = 2^s; accumulate partial l ----
#pragma unroll
        for (int ni = 0; ni < 8; ni++) {
            sc[ni][0] = ex2f(sc[ni][0]);
            sc[ni][1] = ex2f(sc[ni][1]);
            sc[ni][2] = ex2f(sc[ni][2]);
            sc[ni][3] = ex2f(sc[ni][3]);
            l0 += sc[ni][0] + sc[ni][1];
            l1 += sc[ni][2] + sc[ni][3];
        }

        // ---- pack P into A-fragments (hi/lo) ----
        uint32_t ph[4][4], pl[4][4];
#pragma unroll
        for (int kk = 0; kk < 4; kk++) {
            float p00 = sc[2 * kk][0],     p01 = sc[2 * kk][1];
            float p02 = sc[2 * kk][2],     p03 = sc[2 * kk][3];
            float p10 = sc[2 * kk + 1][0], p11 = sc[2 * kk + 1][1];
            float p12 = sc[2 * kk + 1][2], p13 = sc[2 * kk + 1][3];
            __nv_bfloat16 h00 = __float2bfloat16(p00), h01 = __float2bfloat16(p01);
            __nv_bfloat16 h02 = __float2bfloat16(p02), h03 = __float2bfloat16(p03);
            __nv_bfloat16 h10 = __float2bfloat16(p10), h11 = __float2bfloat16(p11);
            __nv_bfloat16 h12 = __float2bfloat16(p12), h13 = __float2bfloat16(p13);
            ph[kk][0] = pack_bf16x2(p00, p01);
            ph[kk][1] = pack_bf16x2(p02, p03);
            ph[kk][2] = pack_bf16x2(p10, p11);
            ph[kk][3] = pack_bf16x2(p12, p13);
            pl[kk][0] = pack_bf16x2(p00 - __bfloat162float(h00), p01 - __bfloat162float(h01));
            pl[kk][1] = pack_bf16x2(p02 - __bfloat162float(h02), p03 - __bfloat162float(h03));
            pl[kk][2] = pack_bf16x2(p10 - __bfloat162float(h10), p11 - __bfloat162float(h11));
            pl[kk][3] = pack_bf16x2(p12 - __bfloat162float(h12), p13 - __bfloat162float(h13));
        }

        // ---- O += Ph·Vh + Ph·Vl + Pl·Vh ----
#pragma unroll
        for (int ks = 0; ks < 4; ks++) {
#pragma unroll
            for (int n2 = 0; n2 < 4; n2++) {
                uint32_t rv = sw128((uint32_t)((ks * 16 + v_row4) * 128 + (n2 * 2 + v_nh) * 16));
                uint32_t t4[4];
                uint32_t vh0[2], vh1[2], vl0[2], vl1[2];
                ldm_x4_t(t4, bufb + F_VH + rv);
                vh0[0] = t4[0]; vh0[1] = t4[1]; vh1[0] = t4[2]; vh1[1] = t4[3];
                ldm_x4_t(t4, bufb + F_VL + rv);
                vl0[0] = t4[0]; vl0[1] = t4[1]; vl1[0] = t4[2]; vl1[1] = t4[3];
                mma_bf16(o[n2 * 2 + 0], ph[ks], vh0);
                mma_bf16(o[n2 * 2 + 1], ph[ks], vh1);
                mma_bf16(o[n2 * 2 + 0], ph[ks], vl0);
                mma_bf16(o[n2 * 2 + 1], ph[ks], vl1);
                mma_bf16(o[n2 * 2 + 0], pl[ks], vh0);
                mma_bf16(o[n2 * 2 + 1], pl[ks], vh1);
            }
        }

        MBAR_ARRIVE(sb + F_MB + cstage * 16 + 8);
        if (++cstage == 2) { cstage = 0; cphase ^= 1; }
    }

    // ---- deferred l reduction (once) + epilogue ----
    l0 += __shfl_xor_sync(~0u, l0, 1);
    l0 += __shfl_xor_sync(~0u, l0, 2);
    l1 += __shfl_xor_sync(~0u, l1, 1);
    l1 += __shfl_xor_sync(~0u, l1, 2);

    const int g   = lid >> 2;
    const int tig = lid & 3;
    const float inv0 = 1.0f / l0, inv1 = 1.0f / l1;
#pragma unroll
    for (int half = 0; half < 2; half++) {
        int s = q0 + wid * 16 + g + half * 8;
        float inv = half ? inv1 : inv0;
        size_t rowbase = ((size_t)(b * S_LEN + s)) * EMB + h * HD;
#pragma unroll
        for (int ni = 0; ni < 8; ni++) {
            float vx = o[ni][half * 2 + 0] * inv;
            float vy = o[ni][half * 2 + 1] * inv;
            __nv_bfloat16 hx = __float2bfloat16(vx);
            __nv_bfloat16 hy = __float2bfloat16(vy);
            __nv_bfloat16 lx = __float2bfloat16(vx - __bfloat162float(hx));
            __nv_bfloat16 ly = __float2bfloat16(vy - __bfloat162float(hy));
            size_t idx = rowbase + ni * 8 + tig * 2;
            *(__nv_bfloat162*)(Ohi + idx) = __halves2bfloat162(hx, hy);
            *(__nv_bfloat162*)(Olo + idx) = __halves2bfloat162(lx, ly);
        }
    }
}

// ---------------------------------------------------------------------------
// Launch
// ---------------------------------------------------------------------------
extern "C" void kernel_launch(void* const* d_in, const int* in_sizes, int n_in,
                              void* d_out, int out_size)
{
    const float* x  = (const float*)d_in[0];
    const float* Wq = (const float*)d_in[1];
    const float* bq = (const float*)d_in[2];
    const float* Wk = (const float*)d_in[3];
    const float* bk = (const float*)d_in[4];
    const float* Wv = (const float*)d_in[5];
    const float* bv = (const float*)d_in[6];
    const float* Wo = (const float*)d_in[7];
    const float* bo = (const float*)d_in[8];
    float* out = (float*)d_out;

    __nv_bfloat16 *xhi, *xlo, *whi, *wlo, *ahi, *alo;
    __nv_bfloat16 *qhi, *qlo, *khi, *klo, *vhi, *vlo;
    cudaGetSymbolAddress((void**)&xhi, g_xhi);
    cudaGetSymbolAddress((void**)&xlo, g_xlo);
    cudaGetSymbolAddress((void**)&whi, g_whi);
    cudaGetSymbolAddress((void**)&wlo, g_wlo);
    cudaGetSymbolAddress((void**)&ahi, g_ahi);
    cudaGetSymbolAddress((void**)&alo, g_alo);
    cudaGetSymbolAddress((void**)&qhi, g_qhi);
    cudaGetSymbolAddress((void**)&qlo, g_qlo);
    cudaGetSymbolAddress((void**)&khi, g_khi);
    cudaGetSymbolAddress((void**)&klo, g_klo);
    cudaGetSymbolAddress((void**)&vhi, g_vhi);
    cudaGetSymbolAddress((void**)&vlo, g_vlo);

    cudaFuncSetAttribute(gemm_qkv, cudaFuncAttributeMaxDynamicSharedMemorySize, GEMM_SMEM);
    cudaFuncSetAttribute(gemm_out, cudaFuncAttributeMaxDynamicSharedMemorySize, GEMM_SMEM);
    cudaFuncSetAttribute(flash_mma, cudaFuncAttributeMaxDynamicSharedMemorySize, FLASH_SMEM);

    convert_all<<<(N4ALL + 255) / 256, 256>>>((const float4*)x,
        (const float4*)Wq, (const float4*)Wk, (const float4*)Wv, (const float4*)Wo,
        xhi, xlo, whi, wlo);

    dim3 gq(12, M_TOT / 128);
    gemm_qkv<<<gq, 512, GEMM_SMEM>>>(xhi, xlo, whi, wlo, bq, bk, bv,
                                     qhi, qlo, khi, klo, vhi, vlo);

    dim3 ga(S_LEN / 128, BH);
    flash_mma<<<ga, 256, FLASH_SMEM>>>(qhi, qlo, khi, klo, vhi, vlo, ahi, alo);

    dim3 gg(EMB / 256, M_TOT / 128);
    gemm_out<<<gg, 512, GEMM_SMEM>>>(ahi, alo, whi + 3 * WSZ, wlo + 3 * WSZ, bo, out);
}

// round 16
// speedup vs baseline: 1.5094x; 1.2111x over previous
#include <cuda_runtime.h>
#include <cuda_bf16.h>
#include <cuda_fp16.h>
#include <cstdint>

#define BATCH 4
#define S_LEN 2048
#define EMB   1024
#define NH    16
#define HD    64
#define M_TOT (BATCH * S_LEN)   // 8192
#define BH    (BATCH * NH)      // 64
#define WSZ   ((size_t)EMB * EMB)
#define QSCALE 0.1803368802f    // 0.125 * log2(e)

// ---------------------------------------------------------------------------
// Scratch (device globals — no allocation allowed)
// ---------------------------------------------------------------------------
__device__ __nv_bfloat16 g_xhi[(size_t)M_TOT * EMB];
__device__ __nv_bfloat16 g_xlo[(size_t)M_TOT * EMB];
__device__ __nv_bfloat16 g_whi[4][WSZ];
__device__ __nv_bfloat16 g_wlo[4][WSZ];
__device__ __half g_qhi[(size_t)BH * S_LEN * HD];
__device__ __half g_qlo[(size_t)BH * S_LEN * HD];
__device__ __half g_khi[(size_t)BH * S_LEN * HD];
__device__ __half g_vhi[(size_t)BH * S_LEN * HD];
__device__ __nv_bfloat16 g_ahi[(size_t)M_TOT * EMB];
__device__ __nv_bfloat16 g_alo[(size_t)M_TOT * EMB];

// ---------------------------------------------------------------------------
// helpers
// ---------------------------------------------------------------------------
__device__ __forceinline__ uint32_t smem_u32(const void* p) {
    uint32_t a;
    asm("{ .reg .u64 t; cvta.to.shared.u64 t, %1; cvt.u32.u64 %0, t; }"
        : "=r"(a) : "l"(p));
    return a;
}
__device__ __forceinline__ void cp_async16(uint32_t dst, const void* src) {
    asm volatile("cp.async.cg.shared.global [%0], [%1], 16;"
                 :: "r"(dst), "l"(__cvta_generic_to_global(src)) : "memory");
}
#define MBAR_INIT(mbar, cnt) \
    asm volatile("mbarrier.init.shared.b64 [%0], %1;" :: "r"(mbar), "r"(cnt) : "memory")
#define MBAR_ARRIVE(mbar) \
    asm volatile("mbarrier.arrive.shared::cta.b64 _, [%0];" :: "r"(mbar) : "memory")
#define CPASYNC_MBAR_ARRIVE(mbar) \
    asm volatile("cp.async.mbarrier.arrive.noinc.shared::cta.b64 [%0];" :: "r"(mbar) : "memory")

__device__ __forceinline__ void mbar_wait(uint32_t mbar, uint32_t parity) {
    asm volatile(
        "{\n\t.reg .pred P;\n\t"
        "W_%=:\n\t"
        "mbarrier.try_wait.parity.acquire.cta.shared::cta.b64 P, [%0], %1, 0x989680;\n\t"
        "@P bra D_%=;\n\t"
        "bra W_%=;\n\t"
        "D_%=:\n\t}"
        :: "r"(mbar), "r"(parity) : "memory");
}

__device__ __forceinline__ void ldm_x4(uint32_t* r, uint32_t addr) {
    asm volatile("ldmatrix.sync.aligned.m8n8.x4.shared.b16 {%0,%1,%2,%3}, [%4];"
                 : "=r"(r[0]), "=r"(r[1]), "=r"(r[2]), "=r"(r[3]) : "r"(addr));
}
__device__ __forceinline__ void ldm_x4_t(uint32_t* r, uint32_t addr) {
    asm volatile("ldmatrix.sync.aligned.m8n8.x4.trans.shared.b16 {%0,%1,%2,%3}, [%4];"
                 : "=r"(r[0]), "=r"(r[1]), "=r"(r[2]), "=r"(r[3]) : "r"(addr));
}
__device__ __forceinline__ void mma_bf16(float* c, const uint32_t* a, const uint32_t* b) {
    asm volatile(
        "mma.sync.aligned.m16n8k16.row.col.f32.bf16.bf16.f32 "
        "{%0,%1,%2,%3}, {%4,%5,%6,%7}, {%8,%9}, {%0,%1,%2,%3};"
        : "+f"(c[0]), "+f"(c[1]), "+f"(c[2]), "+f"(c[3])
        : "r"(a[0]), "r"(a[1]), "r"(a[2]), "r"(a[3]), "r"(b[0]), "r"(b[1]));
}
__device__ __forceinline__ void mma_f16(float* c, const uint32_t* a, const uint32_t* b) {
    asm volatile(
        "mma.sync.aligned.m16n8k16.row.col.f32.f16.f16.f32 "
        "{%0,%1,%2,%3}, {%4,%5,%6,%7}, {%8,%9}, {%0,%1,%2,%3};"
        : "+f"(c[0]), "+f"(c[1]), "+f"(c[2]), "+f"(c[3])
        : "r"(a[0]), "r"(a[1]), "r"(a[2]), "r"(a[3]), "r"(b[0]), "r"(b[1]));
}
__device__ __forceinline__ float ex2f(float x) {
    float r;
    asm("ex2.approx.ftz.f32 %0, %1;" : "=f"(r) : "f"(x));
    return r;
}
__device__ __forceinline__ uint32_t h2_as_u32(__half2 h) {
    return *reinterpret_cast<uint32_t*>(&h);
}
__device__ __forceinline__ uint32_t sw64(int row, int c) {
    return (uint32_t)(row * 64 + (((c) ^ ((row >> 1) & 3)) << 4));
}
__device__ __forceinline__ uint32_t sw128(uint32_t off) {
    return off ^ ((off >> 3) & 0x70);
}

// ---------------------------------------------------------------------------
// single fused convert: x + 4 weights -> bf16 hi/lo
// ---------------------------------------------------------------------------
#define N4X (M_TOT * EMB / 4)
#define N4W (EMB * EMB / 4)
#define N4ALL (N4X + 4 * N4W)

__global__ void __launch_bounds__(256)
convert_all(const float4* __restrict__ x,
            const float4* __restrict__ Wq, const float4* __restrict__ Wk,
            const float4* __restrict__ Wv, const float4* __restrict__ Wo,
            __nv_bfloat16* __restrict__ xhi, __nv_bfloat16* __restrict__ xlo,
            __nv_bfloat16* __restrict__ whi, __nv_bfloat16* __restrict__ wlo)
{
    int i = blockIdx.x * 256 + threadIdx.x;
    if (i >= N4ALL) return;

    const float4* in;
    __nv_bfloat16 *hp, *lp;
    int idx;
    if (i < N4X) {
        in = x; hp = xhi; lp = xlo; idx = i;
    } else {
        int j = i - N4X;
        int w = j >> 18;
        idx = j & (N4W - 1);
        in = (w == 0) ? Wq : (w == 1) ? Wk : (w == 2) ? Wv : Wo;
        hp = whi + (size_t)w * WSZ;
        lp = wlo + (size_t)w * WSZ;
    }
    float4 v = in[idx];
    __nv_bfloat16 h0 = __float2bfloat16(v.x);
    __nv_bfloat16 h1 = __float2bfloat16(v.y);
    __nv_bfloat16 h2 = __float2bfloat16(v.z);
    __nv_bfloat16 h3 = __float2bfloat16(v.w);
    __nv_bfloat16 l0 = __float2bfloat16(v.x - __bfloat162float(h0));
    __nv_bfloat16 l1 = __float2bfloat16(v.y - __bfloat162float(h1));
    __nv_bfloat16 l2 = __float2bfloat16(v.z - __bfloat162float(h2));
    __nv_bfloat16 l3 = __float2bfloat16(v.w - __bfloat162float(h3));
    __nv_bfloat162* h2p = (__nv_bfloat162*)hp;
    __nv_bfloat162* l2p = (__nv_bfloat162*)lp;
    h2p[2 * idx + 0] = __halves2bfloat162(h0, h1);
    h2p[2 * idx + 1] = __halves2bfloat162(h2, h3);
    l2p[2 * idx + 0] = __halves2bfloat162(l0, l1);
    l2p[2 * idx + 1] = __halves2bfloat162(l2, l3);
}

// ---------------------------------------------------------------------------
// GEMM: 128x256 CTA tile, 512 threads (16 warps = 2m x 8n of 64x32), BK=32,
//       swizzled 64B rows, 4-stage mbarrier ring, PAIR consumption, 1 CTA/SM
//       (unchanged from R15 winner; 3-term bf16)
// ---------------------------------------------------------------------------
#define ST_AH 0
#define ST_AL 8192
#define ST_BH 16384
#define ST_BL 32768
#define STAGE_B 49152
#define MB_OFF (4 * STAGE_B)
#define GEMM_SMEM (MB_OFF + 64)
#define KITER (EMB / 32)

#define GEMM_STAGE_LAMBDA()                                                    \
    auto stage = [&](int buf, int kc) {                                        \
        const uint32_t base = sb + buf * STAGE_B;                              \
        const int arow = tid >> 2, ac = tid & 3;                               \
        const uint32_t soA = sw64(arow, ac);                                   \
        const int gca = kc * 32 + ac * 8;                                      \
        cp_async16(base + ST_AH + soA, gA[0] + (size_t)arow * EMB + gca);      \
        cp_async16(base + ST_AL + soA, gA[1] + (size_t)arow * EMB + gca);      \
        _Pragma("unroll")                                                      \
        for (int t = 0; t < 2; t++) {                                          \
            int item = tid + t * 512;                                          \
            int brow = item >> 2, bc = item & 3;                               \
            uint32_t soB = sw64(brow, bc);                                     \
            int gcb = kc * 32 + bc * 8;                                        \
            cp_async16(base + ST_BH + soB, gB[0] + (size_t)brow * EMB + gcb);  \
            cp_async16(base + ST_BL + soB, gB[1] + (size_t)brow * EMB + gcb);  \
        }                                                                      \
    };

#define GEMM_MAINLOOP()                                                        \
    if (tid == 0) {                                                            \
        _Pragma("unroll")                                                      \
        for (int s = 0; s < 4; s++) {                                          \
            MBAR_INIT(sb + MB_OFF + s * 16, 512);                              \
            MBAR_INIT(sb + MB_OFF + s * 16 + 8, 512);                          \
        }                                                                      \
    }                                                                          \
    __syncthreads();                                                           \
    float acc[4][4][4];                                                        \
    _Pragma("unroll")                                                          \
    for (int i = 0; i < 4; i++)                                                \
        _Pragma("unroll")                                                      \
        for (int j = 0; j < 4; j++)                                            \
            _Pragma("unroll")                                                  \
            for (int k = 0; k < 4; k++) acc[i][j][k] = 0.0f;                   \
    const int a_row  = wm * 64 + (lid & 15);                                   \
    const int a_c    = (lid >> 4);                                             \
    const int b_row4 = wn * 32 + (lid & 7) + ((lid >> 4) << 3);                \
    const int b_c    = (lid >> 3) & 1;                                         \
    auto chunk = [&](uint32_t bufb) {                                          \
        _Pragma("unroll")                                                      \
        for (int ks = 0; ks < 2; ks++) {                                       \
            const int kc0 = ks * 2;                                            \
            uint32_t ah[4][4], al[4][4], bhf[4][2], blf[4][2];                 \
            _Pragma("unroll")                                                  \
            for (int mi = 0; mi < 4; mi++) {                                   \
                uint32_t ra = sw64(a_row + mi * 16, kc0 + a_c);                \
                ldm_x4(ah[mi], bufb + ST_AH + ra);                             \
                ldm_x4(al[mi], bufb + ST_AL + ra);                             \
            }                                                                  \
            _Pragma("unroll")                                                  \
            for (int n2 = 0; n2 < 2; n2++) {                                   \
                uint32_t rb = sw64(b_row4 + n2 * 16, kc0 + b_c);               \
                uint32_t t4[4];                                                \
                ldm_x4(t4, bufb + ST_BH + rb);                                 \
                bhf[n2 * 2][0] = t4[0]; bhf[n2 * 2][1] = t4[1];                \
                bhf[n2 * 2 + 1][0] = t4[2]; bhf[n2 * 2 + 1][1] = t4[3];        \
                ldm_x4(t4, bufb + ST_BL + rb);                                 \
                blf[n2 * 2][0] = t4[0]; blf[n2 * 2][1] = t4[1];                \
                blf[n2 * 2 + 1][0] = t4[2]; blf[n2 * 2 + 1][1] = t4[3];        \
            }                                                                  \
            _Pragma("unroll")                                                  \
            for (int mi = 0; mi < 4; mi++)                                     \
                _Pragma("unroll")                                              \
                for (int ni = 0; ni < 4; ni++) {                               \
                    mma_bf16(acc[mi][ni], ah[mi], bhf[ni]);                    \
                    mma_bf16(acc[mi][ni], ah[mi], blf[ni]);                    \
                    mma_bf16(acc[mi][ni], al[mi], bhf[ni]);                    \
                }                                                              \
        }                                                                      \
    };                                                                         \
    int pstage = 0, pphase = 1;                                                \
    auto stage_issue = [&](int kc) {                                           \
        uint32_t fb = sb + MB_OFF + pstage * 16;                               \
        mbar_wait(fb + 8, pphase);                                             \
        stage(pstage, kc);                                                     \
        CPASYNC_MBAR_ARRIVE(fb);                                               \
        if (++pstage == 4) { pstage = 0; pphase ^= 1; }                        \
    };                                                                         \
    stage_issue(0); stage_issue(1);                                            \
    int cstage = 0, cphase = 0;                                                \
    _Pragma("unroll 1")                                                        \
    for (int kc = 0; kc < KITER; kc += 2) {                                    \
        mbar_wait(sb + MB_OFF + cstage * 16, cphase);                          \
        mbar_wait(sb + MB_OFF + (cstage + 1) * 16, cphase);                    \
        if (kc + 2 < KITER) { stage_issue(kc + 2); stage_issue(kc + 3); }      \
        chunk(sb + cstage * STAGE_B);                                          \
        chunk(sb + (cstage + 1) * STAGE_B);                                    \
        MBAR_ARRIVE(sb + MB_OFF + cstage * 16 + 8);                            \
        MBAR_ARRIVE(sb + MB_OFF + (cstage + 1) * 16 + 8);                      \
        cstage += 2;                                                           \
        if (cstage == 4) { cstage = 0; cphase ^= 1; }                          \
    }

// fused QKV GEMM: Q -> fp16 hi/lo (pre-scaled), K/V -> single fp16
__global__ void __launch_bounds__(512, 1)
gemm_qkv(const __nv_bfloat16* __restrict__ Ahi, const __nv_bfloat16* __restrict__ Alo,
         const __nv_bfloat16* __restrict__ Whi, const __nv_bfloat16* __restrict__ Wlo,
         const float* __restrict__ bq, const float* __restrict__ bk,
         const float* __restrict__ bv,
         __half* __restrict__ qhi, __half* __restrict__ qlo,
         __half* __restrict__ khi, __half* __restrict__ vhi)
{
    extern __shared__ char smem[];
    const uint32_t sb = smem_u32(smem);
    const int tid = threadIdx.x;
    const int wid = tid >> 5;
    const int lid = tid & 31;
    const int bn  = blockIdx.x;
    const int w   = bn >> 2;
    const int tm  = blockIdx.y * 128;
    const int tn  = (bn & 3) * 256;
    const int wm  = wid >> 3;
    const int wn  = wid & 7;

    const float* bias = (w == 0) ? bq : (w == 1) ? bk : bv;
    __half* Ch = (w == 0) ? qhi : (w == 1) ? khi : vhi;

    const __nv_bfloat16* gA[2] = { Ahi + (size_t)tm * EMB, Alo + (size_t)tm * EMB };
    const __nv_bfloat16* gB[2] = { Whi + (size_t)w * WSZ + (size_t)tn * EMB,
                                   Wlo + (size_t)w * WSZ + (size_t)tn * EMB };

    GEMM_STAGE_LAMBDA()
    GEMM_MAINLOOP()

    const int g   = lid >> 2;
    const int tig = lid & 3;
#pragma unroll
    for (int ni = 0; ni < 4; ni++) {
        const int n = tn + wn * 32 + ni * 8 + tig * 2;
        const float b0 = bias[n], b1 = bias[n + 1];
        const int hh = n >> 6, dd = n & 63;
#pragma unroll
        for (int mi = 0; mi < 4; mi++) {
#pragma unroll
            for (int half = 0; half < 2; half++) {
                int m = tm + wm * 64 + mi * 16 + g + half * 8;
                float vx = acc[mi][ni][half * 2 + 0] + b0;
                float vy = acc[mi][ni][half * 2 + 1] + b1;
                int bb = m >> 11, ss = m & 2047;
                size_t idx = (((size_t)(bb * NH + hh) * S_LEN) + ss) * HD + dd;
                if (w == 0) {
                    vx *= QSCALE; vy *= QSCALE;
                    __half hx = __float2half(vx);
                    __half hy = __float2half(vy);
                    float lx = vx - __half2float(hx);
                    float ly = vy - __half2float(hy);
                    *(__half2*)(qhi + idx) = __halves2half2(hx, hy);
                    *(__half2*)(qlo + idx) = __floats2half2_rn(lx, ly);
                } else {
                    *(__half2*)(Ch + idx) = __floats2half2_rn(vx, vy);
                }
            }
        }
    }
}

// output projection GEMM: grid (4, 64), fp32 C row-major (3-term bf16)
__global__ void __launch_bounds__(512, 1)
gemm_out(const __nv_bfloat16* __restrict__ Ahi, const __nv_bfloat16* __restrict__ Alo,
         const __nv_bfloat16* __restrict__ Bhi, const __nv_bfloat16* __restrict__ Blo,
         const float* __restrict__ bias, float* __restrict__ C)
{
    extern __shared__ char smem[];
    const uint32_t sb = smem_u32(smem);
    const int tid = threadIdx.x;
    const int wid = tid >> 5;
    const int lid = tid & 31;
    const int tm  = blockIdx.y * 128;
    const int tn  = blockIdx.x * 256;
    const int wm  = wid >> 3;
    const int wn  = wid & 7;

    const __nv_bfloat16* gA[2] = { Ahi + (size_t)tm * EMB, Alo + (size_t)tm * EMB };
    const __nv_bfloat16* gB[2] = { Bhi + (size_t)tn * EMB, Blo + (size_t)tn * EMB };

    GEMM_STAGE_LAMBDA()
    GEMM_MAINLOOP()

    const int g   = lid >> 2;
    const int tig = lid & 3;
#pragma unroll
    for (int ni = 0; ni < 4; ni++) {
        const int n = tn + wn * 32 + ni * 8 + tig * 2;
        const float b0 = bias[n], b1 = bias[n + 1];
#pragma unroll
        for (int mi = 0; mi < 4; mi++) {
#pragma unroll
            for (int half = 0; half < 2; half++) {
                int m = tm + wm * 64 + mi * 16 + g + half * 8;
                float2 v;
                v.x = acc[mi][ni][half * 2 + 0] + b0;
                v.y = acc[mi][ni][half * 2 + 1] + b1;
                *(float2*)(C + (size_t)m * EMB + n) = v;
            }
        }
    }
}

// ---------------------------------------------------------------------------
// Flash attention, 2-term fp16: QK = (Qh+Ql)·Kh, PV = (Ph+Pl)·Vh.
// No-max softmax, deferred l. 4-stage KV ring (16KB stages), 2 CTAs/SM.
// ---------------------------------------------------------------------------
#define FQ_H  0
#define FQ_L  16384
#define F_KH  0
#define F_VH  8192
#define F_STAGE 16384
#define F_STG0 32768
#define F_MB   (F_STG0 + 4 * F_STAGE)      // 98304
#define FLASH_SMEM (F_MB + 64)             // 98368
#define NCHUNK (S_LEN / 64)                // 32

__global__ void __launch_bounds__(256, 2)
flash_mma(const __half* __restrict__ Qhi, const __half* __restrict__ Qlo,
          const __half* __restrict__ Khi, const __half* __restrict__ Vhi,
          __nv_bfloat16* __restrict__ Ohi, __nv_bfloat16* __restrict__ Olo)
{
    extern __shared__ char smem[];
    const uint32_t sb = smem_u32(smem);
    const int tid = threadIdx.x;
    const int wid = tid >> 5;
    const int lid = tid & 31;
    const int bh  = blockIdx.y;
    const int b   = bh >> 4;
    const int h   = bh & 15;
    const int q0  = blockIdx.x * 128;

    const __half* Qh_g = Qhi + ((size_t)bh * S_LEN + q0) * HD;
    const __half* Ql_g = Qlo + ((size_t)bh * S_LEN + q0) * HD;
    const __half* Kh_g = Khi + (size_t)bh * S_LEN * HD;
    const __half* Vh_g = Vhi + (size_t)bh * S_LEN * HD;

    if (tid == 0) {
#pragma unroll
        for (int s = 0; s < 4; s++) {
            MBAR_INIT(sb + F_MB + s * 16, 256);
            MBAR_INIT(sb + F_MB + s * 16 + 8, 256);
        }
    }
    __syncthreads();

    // KV staging: 512 16B-items per array; 2 items/thread each
    auto stage = [&](int buf, int c) {
        const uint32_t base = sb + F_STG0 + buf * F_STAGE;
#pragma unroll
        for (int t = 0; t < 2; t++) {
            int item = tid + t * 256;
            int row = item >> 3, seg = item & 7;
            uint32_t so = sw128((uint32_t)(row * 128 + seg * 16));
            const size_t go = (size_t)(c * 64 + row) * HD + seg * 8;
            cp_async16(base + F_KH + so, Kh_g + go);
            cp_async16(base + F_VH + so, Vh_g + go);
        }
    };

    int pstage = 0, pphase = 1, cstage = 0, cphase = 0;
    auto stage_issue = [&](int c) {
        uint32_t fb = sb + F_MB + pstage * 16;
        mbar_wait(fb + 8, pphase);
        stage(pstage, c);
        CPASYNC_MBAR_ARRIVE(fb);
        if (++pstage == 4) { pstage = 0; pphase ^= 1; }
    };

    stage_issue(0); stage_issue(1); stage_issue(2);

    // stage Q (128 x 64 fp16) hi/lo into persistent swizzled smem
    {
        int row = tid >> 1;
#pragma unroll
        for (int t = 0; t < 4; t++) {
            int seg = (tid & 1) * 4 + t;
            uint32_t so = sw128((uint32_t)(row * 128 + seg * 16));
            *(uint4*)(smem + FQ_H + so) = *(const uint4*)(Qh_g + (size_t)row * HD + seg * 8);
            *(uint4*)(smem + FQ_L + so) = *(const uint4*)(Ql_g + (size_t)row * HD + seg * 8);
        }
    }
    __syncthreads();

    float o[8][4];
#pragma unroll
    for (int ni = 0; ni < 8; ni++)
#pragma unroll
        for (int j = 0; j < 4; j++) o[ni][j] = 0.0f;
    float l0 = 0.0f, l1 = 0.0f;

    const int a_row  = wid * 16 + (lid & 15);
    const int a_c    = (lid >> 4);
    const int kb_row = (lid & 7) + ((lid >> 4) << 3);
    const int kb_c   = (lid >> 3) & 1;
    const int v_row4 = (lid & 7) + (((lid >> 3) & 1) << 3);
    const int v_nh   = (lid >> 4);

#pragma unroll 1
    for (int c = 0; c < NCHUNK; c++) {
        mbar_wait(sb + F_MB + cstage * 16, cphase);
        if (c + 3 < NCHUNK) stage_issue(c + 3);
        const uint32_t bufb = sb + F_STG0 + cstage * F_STAGE;

        // ---- scores: S = (Qh + Ql)·Kh ----
        float sc[8][4];
#pragma unroll
        for (int ni = 0; ni < 8; ni++)
#pragma unroll
            for (int j = 0; j < 4; j++) sc[ni][j] = 0.0f;

#pragma unroll
        for (int ks = 0; ks < 4; ks++) {
            uint32_t qh4[4], ql4[4];
            uint32_t ra = sw128((uint32_t)(a_row * 128 + (ks * 2 + a_c) * 16));
            ldm_x4(qh4, sb + FQ_H + ra);
            ldm_x4(ql4, sb + FQ_L + ra);
#pragma unroll
            for (int n2 = 0; n2 < 4; n2++) {
                uint32_t rb = sw128((uint32_t)((n2 * 16 + kb_row) * 128 + (ks * 2 + kb_c) * 16));
                uint32_t t4[4];
                uint32_t kh0[2], kh1[2];
                ldm_x4(t4, bufb + F_KH + rb);
                kh0[0] = t4[0]; kh0[1] = t4[1]; kh1[0] = t4[2]; kh1[1] = t4[3];
                mma_f16(sc[n2 * 2 + 0], qh4, kh0);
                mma_f16(sc[n2 * 2 + 1], qh4, kh1);
                mma_f16(sc[n2 * 2 + 0], ql4, kh0);
                mma_f16(sc[n2 * 2 + 1], ql4, kh1);
            }
        }

        // ---- no-max softmax: P = 2^s; accumulate partial l ----
#pragma unroll
        for (int ni = 0; ni < 8; ni++) {
            sc[ni][0] = ex2f(sc[ni][0]);
            sc[ni][1] = ex2f(sc[ni][1]);
            sc[ni][2] = ex2f(sc[ni][2]);
            sc[ni][3] = ex2f(sc[ni][3]);
            l0 += sc[ni][0] + sc[ni][1];
            l1 += sc[ni][2] + sc[ni][3];
        }

        // ---- pack P into fp16 A-fragments (hi/lo) ----
        uint32_t ph[4][4], pl[4][4];
#pragma unroll
        for (int kk = 0; kk < 4; kk++) {
            float p00 = sc[2 * kk][0],     p01 = sc[2 * kk][1];
            float p02 = sc[2 * kk][2],     p03 = sc[2 * kk][3];
            float p10 = sc[2 * kk + 1][0], p11 = sc[2 * kk + 1][1];
            float p12 = sc[2 * kk + 1][2], p13 = sc[2 * kk + 1][3];
            __half h00 = __float2half(p00), h01 = __float2half(p01);
            __half h02 = __float2half(p02), h03 = __float2half(p03);
            __half h10 = __float2half(p10), h11 = __float2half(p11);
            __half h12 = __float2half(p12), h13 = __float2half(p13);
            ph[kk][0] = h2_as_u32(__halves2half2(h00, h01));
            ph[kk][1] = h2_as_u32(__halves2half2(h02, h03));
            ph[kk][2] = h2_as_u32(__halves2half2(h10, h11));
            ph[kk][3] = h2_as_u32(__halves2half2(h12, h13));
            pl[kk][0] = h2_as_u32(__floats2half2_rn(p00 - __half2float(h00), p01 - __half2float(h01)));
            pl[kk][1] = h2_as_u32(__floats2half2_rn(p02 - __half2float(h02), p03 - __half2float(h03)));
            pl[kk][2] = h2_as_u32(__floats2half2_rn(p10 - __half2float(h10), p11 - __half2float(h11)));
            pl[kk][3] = h2_as_u32(__floats2half2_rn(p12 - __half2float(h12), p13 - __half2float(h13)));
        }

        // ---- O += (Ph + Pl)·Vh ----
#pragma unroll
        for (int ks = 0; ks < 4; ks++) {
#pragma unroll
            for (int n2 = 0; n2 < 4; n2++) {
                uint32_t rv = sw128((uint32_t)((ks * 16 + v_row4) * 128 + (n2 * 2 + v_nh) * 16));
                uint32_t t4[4];
                uint32_t vh0[2], vh1[2];
                ldm_x4_t(t4, bufb + F_VH + rv);
                vh0[0] = t4[0]; vh0[1] = t4[1]; vh1[0] = t4[2]; vh1[1] = t4[3];
                mma_f16(o[n2 * 2 + 0], ph[ks], vh0);
                mma_f16(o[n2 * 2 + 1], ph[ks], vh1);
                mma_f16(o[n2 * 2 + 0], pl[ks], vh0);
                mma_f16(o[n2 * 2 + 1], pl[ks], vh1);
            }
        }

        MBAR_ARRIVE(sb + F_MB + cstage * 16 + 8);
        if (++cstage == 4) { cstage = 0; cphase ^= 1; }
    }

    // ---- deferred l reduction + epilogue (bf16 split output) ----
    l0 += __shfl_xor_sync(~0u, l0, 1);
    l0 += __shfl_xor_sync(~0u, l0, 2);
    l1 += __shfl_xor_sync(~0u, l1, 1);
    l1 += __shfl_xor_sync(~0u, l1, 2);

    const int g   = lid >> 2;
    const int tig = lid & 3;
    const float inv0 = 1.0f / l0, inv1 = 1.0f / l1;
#pragma unroll
    for (int half = 0; half < 2; half++) {
        int s = q0 + wid * 16 + g + half * 8;
        float inv = half ? inv1 : inv0;
        size_t rowbase = ((size_t)(b * S_LEN + s)) * EMB + h * HD;
#pragma unroll
        for (int ni = 0; ni < 8; ni++) {
            float vx = o[ni][half * 2 + 0] * inv;
            float vy = o[ni][half * 2 + 1] * inv;
            __nv_bfloat16 hx = __float2bfloat16(vx);
            __nv_bfloat16 hy = __float2bfloat16(vy);
            __nv_bfloat16 lx = __float2bfloat16(vx - __bfloat162float(hx));
            __nv_bfloat16 ly = __float2bfloat16(vy - __bfloat162float(hy));
            size_t idx = rowbase + ni * 8 + tig * 2;
            *(__nv_bfloat162*)(Ohi + idx) = __halves2bfloat162(hx, hy);
            *(__nv_bfloat162*)(Olo + idx) = __halves2bfloat162(lx, ly);
        }
    }
}

// ---------------------------------------------------------------------------
// Launch
// ---------------------------------------------------------------------------
extern "C" void kernel_launch(void* const* d_in, const int* in_sizes, int n_in,
                              void* d_out, int out_size)
{
    const float* x  = (const float*)d_in[0];
    const float* Wq = (const float*)d_in[1];
    const float* bq = (const float*)d_in[2];
    const float* Wk = (const float*)d_in[3];
    const float* bk = (const float*)d_in[4];
    const float* Wv = (const float*)d_in[5];
    const float* bv = (const float*)d_in[6];
    const float* Wo = (const float*)d_in[7];
    const float* bo = (const float*)d_in[8];
    float* out = (float*)d_out;

    __nv_bfloat16 *xhi, *xlo, *whi, *wlo, *ahi, *alo;
    __half *qhi, *qlo, *khi, *vhi;
    cudaGetSymbolAddress((void**)&xhi, g_xhi);
    cudaGetSymbolAddress((void**)&xlo, g_xlo);
    cudaGetSymbolAddress((void**)&whi, g_whi);
    cudaGetSymbolAddress((void**)&wlo, g_wlo);
    cudaGetSymbolAddress((void**)&ahi, g_ahi);
    cudaGetSymbolAddress((void**)&alo, g_alo);
    cudaGetSymbolAddress((void**)&qhi, g_qhi);
    cudaGetSymbolAddress((void**)&qlo, g_qlo);
    cudaGetSymbolAddress((void**)&khi, g_khi);
    cudaGetSymbolAddress((void**)&vhi, g_vhi);

    cudaFuncSetAttribute(gemm_qkv, cudaFuncAttributeMaxDynamicSharedMemorySize, GEMM_SMEM);
    cudaFuncSetAttribute(gemm_out, cudaFuncAttributeMaxDynamicSharedMemorySize, GEMM_SMEM);
    cudaFuncSetAttribute(flash_mma, cudaFuncAttributeMaxDynamicSharedMemorySize, FLASH_SMEM);

    convert_all<<<(N4ALL + 255) / 256, 256>>>((const float4*)x,
        (const float4*)Wq, (const float4*)Wk, (const float4*)Wv, (const float4*)Wo,
        xhi, xlo, whi, wlo);

    dim3 gq(12, M_TOT / 128);
    gemm_qkv<<<gq, 512, GEMM_SMEM>>>(xhi, xlo, whi, wlo, bq, bk, bv,
                                     qhi, qlo, khi, vhi);

    dim3 ga(S_LEN / 128, BH);
    flash_mma<<<ga, 256, FLASH_SMEM>>>(qhi, qlo, khi, vhi, ahi, alo);

    dim3 gg(EMB / 256, M_TOT / 128);
    gemm_out<<<gg, 512, GEMM_SMEM>>>(ahi, alo, whi + 3 * WSZ, wlo + 3 * WSZ, bo, out);
}

// round 17
// speedup vs baseline: 1.8693x; 1.2384x over previous
#include <cuda_runtime.h>
#include <cuda_bf16.h>
#include <cuda_fp16.h>
#include <cstdint>

#define BATCH 4
#define S_LEN 2048
#define EMB   1024
#define NH    16
#define HD    64
#define M_TOT (BATCH * S_LEN)   // 8192
#define BH    (BATCH * NH)      // 64
#define WSZ   ((size_t)EMB * EMB)
#define QSCALE 0.1803368802f    // 0.125 * log2(e)

// ---------------------------------------------------------------------------
// Scratch (device globals — no allocation allowed)
// ---------------------------------------------------------------------------
__device__ __half g_xhi[(size_t)M_TOT * EMB];
__device__ __half g_xlo[(size_t)M_TOT * EMB];
__device__ __half g_wh[4][WSZ];
__device__ __half g_qhi[(size_t)BH * S_LEN * HD];
__device__ __half g_qlo[(size_t)BH * S_LEN * HD];
__device__ __half g_khi[(size_t)BH * S_LEN * HD];
__device__ __half g_vhi[(size_t)BH * S_LEN * HD];
__device__ __half g_ahi[(size_t)M_TOT * EMB];
__device__ __half g_alo[(size_t)M_TOT * EMB];

// ---------------------------------------------------------------------------
// helpers
// ---------------------------------------------------------------------------
__device__ __forceinline__ uint32_t smem_u32(const void* p) {
    uint32_t a;
    asm("{ .reg .u64 t; cvta.to.shared.u64 t, %1; cvt.u32.u64 %0, t; }"
        : "=r"(a) : "l"(p));
    return a;
}
__device__ __forceinline__ void cp_async16(uint32_t dst, const void* src) {
    asm volatile("cp.async.cg.shared.global [%0], [%1], 16;"
                 :: "r"(dst), "l"(__cvta_generic_to_global(src)) : "memory");
}
#define MBAR_INIT(mbar, cnt) \
    asm volatile("mbarrier.init.shared.b64 [%0], %1;" :: "r"(mbar), "r"(cnt) : "memory")
#define MBAR_ARRIVE(mbar) \
    asm volatile("mbarrier.arrive.shared::cta.b64 _, [%0];" :: "r"(mbar) : "memory")
#define CPASYNC_MBAR_ARRIVE(mbar) \
    asm volatile("cp.async.mbarrier.arrive.noinc.shared::cta.b64 [%0];" :: "r"(mbar) : "memory")

__device__ __forceinline__ void mbar_wait(uint32_t mbar, uint32_t parity) {
    asm volatile(
        "{\n\t.reg .pred P;\n\t"
        "W_%=:\n\t"
        "mbarrier.try_wait.parity.acquire.cta.shared::cta.b64 P, [%0], %1, 0x989680;\n\t"
        "@P bra D_%=;\n\t"
        "bra W_%=;\n\t"
        "D_%=:\n\t}"
        :: "r"(mbar), "r"(parity) : "memory");
}

__device__ __forceinline__ void ldm_x4(uint32_t* r, uint32_t addr) {
    asm volatile("ldmatrix.sync.aligned.m8n8.x4.shared.b16 {%0,%1,%2,%3}, [%4];"
                 : "=r"(r[0]), "=r"(r[1]), "=r"(r[2]), "=r"(r[3]) : "r"(addr));
}
__device__ __forceinline__ void ldm_x4_t(uint32_t* r, uint32_t addr) {
    asm volatile("ldmatrix.sync.aligned.m8n8.x4.trans.shared.b16 {%0,%1,%2,%3}, [%4];"
                 : "=r"(r[0]), "=r"(r[1]), "=r"(r[2]), "=r"(r[3]) : "r"(addr));
}
__device__ __forceinline__ void mma_f16(float* c, const uint32_t* a, const uint32_t* b) {
    asm volatile(
        "mma.sync.aligned.m16n8k16.row.col.f32.f16.f16.f32 "
        "{%0,%1,%2,%3}, {%4,%5,%6,%7}, {%8,%9}, {%0,%1,%2,%3};"
        : "+f"(c[0]), "+f"(c[1]), "+f"(c[2]), "+f"(c[3])
        : "r"(a[0]), "r"(a[1]), "r"(a[2]), "r"(a[3]), "r"(b[0]), "r"(b[1]));
}
__device__ __forceinline__ float ex2f(float x) {
    float r;
    asm("ex2.approx.ftz.f32 %0, %1;" : "=f"(r) : "f"(x));
    return r;
}
__device__ __forceinline__ uint32_t h2_as_u32(__half2 h) {
    return *reinterpret_cast<uint32_t*>(&h);
}
__device__ __forceinline__ uint32_t sw64(int row, int c) {
    return (uint32_t)(row * 64 + (((c) ^ ((row >> 1) & 3)) << 4));
}
__device__ __forceinline__ uint32_t sw128(uint32_t off) {
    return off ^ ((off >> 3) & 0x70);
}

// ---------------------------------------------------------------------------
// single fused convert: x -> fp16 hi/lo, 4 weights -> single fp16
// ---------------------------------------------------------------------------
#define N4X (M_TOT * EMB / 4)
#define N4W (EMB * EMB / 4)
#define N4ALL (N4X + 4 * N4W)

__global__ void __launch_bounds__(256)
convert_all(const float4* __restrict__ x,
            const float4* __restrict__ Wq, const float4* __restrict__ Wk,
            const float4* __restrict__ Wv, const float4* __restrict__ Wo,
            __half* __restrict__ xhi, __half* __restrict__ xlo,
            __half* __restrict__ wh)
{
    int i = blockIdx.x * 256 + threadIdx.x;
    if (i >= N4ALL) return;

    if (i < N4X) {
        float4 v = x[i];
        __half h0 = __float2half(v.x);
        __half h1 = __float2half(v.y);
        __half h2 = __float2half(v.z);
        __half h3 = __float2half(v.w);
        __half2* hp = (__half2*)xhi;
        __half2* lp = (__half2*)xlo;
        hp[2 * i + 0] = __halves2half2(h0, h1);
        hp[2 * i + 1] = __halves2half2(h2, h3);
        lp[2 * i + 0] = __floats2half2_rn(v.x - __half2float(h0), v.y - __half2float(h1));
        lp[2 * i + 1] = __floats2half2_rn(v.z - __half2float(h2), v.w - __half2float(h3));
    } else {
        int j = i - N4X;
        int w = j >> 18;
        int idx = j & (N4W - 1);
        const float4* in = (w == 0) ? Wq : (w == 1) ? Wk : (w == 2) ? Wv : Wo;
        float4 v = in[idx];
        __half2* hp = (__half2*)(wh + (size_t)w * WSZ);
        hp[2 * idx + 0] = __floats2half2_rn(v.x, v.y);
        hp[2 * idx + 1] = __floats2half2_rn(v.z, v.w);
    }
}

// ---------------------------------------------------------------------------
// GEMM (2-term fp16): C = (Ah + Al) @ Wh^T.  128x256 CTA tile, 512 threads
// (16 warps = 2m x 8n of 64x32), BK=32, swizzled 64B rows, 4-stage mbarrier
// ring, PAIR consumption (128 MMA per window), 1 CTA/SM.
// ---------------------------------------------------------------------------
#define ST_AH 0
#define ST_AL 8192
#define ST_BH 16384
#define STAGE_B 32768                  // 8K + 8K + 16K
#define MB_OFF (4 * STAGE_B)           // 131072
#define GEMM_SMEM (MB_OFF + 64)        // 131136
#define KITER (EMB / 32)               // 32

// staging: A 512 items (1/thread per array); B 1024 items (2/thread)
#define GEMM_STAGE_LAMBDA()                                                    \
    auto stage = [&](int buf, int kc) {                                        \
        const uint32_t base = sb + buf * STAGE_B;                              \
        const int arow = tid >> 2, ac = tid & 3;                               \
        const uint32_t soA = sw64(arow, ac);                                   \
        const int gca = kc * 32 + ac * 8;                                      \
        cp_async16(base + ST_AH + soA, gAh + (size_t)arow * EMB + gca);        \
        cp_async16(base + ST_AL + soA, gAl + (size_t)arow * EMB + gca);        \
        _Pragma("unroll")                                                      \
        for (int t = 0; t < 2; t++) {                                          \
            int item = tid + t * 512;                                          \
            int brow = item >> 2, bc = item & 3;                               \
            uint32_t soB = sw64(brow, bc);                                     \
            int gcb = kc * 32 + bc * 8;                                        \
            cp_async16(base + ST_BH + soB, gBh + (size_t)brow * EMB + gcb);    \
        }                                                                      \
    };

#define GEMM_MAINLOOP()                                                        \
    if (tid == 0) {                                                            \
        _Pragma("unroll")                                                      \
        for (int s = 0; s < 4; s++) {                                          \
            MBAR_INIT(sb + MB_OFF + s * 16, 512);                              \
            MBAR_INIT(sb + MB_OFF + s * 16 + 8, 512);                          \
        }                                                                      \
    }                                                                          \
    __syncthreads();                                                           \
    float acc[4][4][4];                                                        \
    _Pragma("unroll")                                                          \
    for (int i = 0; i < 4; i++)                                                \
        _Pragma("unroll")                                                      \
        for (int j = 0; j < 4; j++)                                            \
            _Pragma("unroll")                                                  \
            for (int k = 0; k < 4; k++) acc[i][j][k] = 0.0f;                   \
    const int a_row  = wm * 64 + (lid & 15);                                   \
    const int a_c    = (lid >> 4);                                             \
    const int b_row4 = wn * 32 + (lid & 7) + ((lid >> 4) << 3);                \
    const int b_c    = (lid >> 3) & 1;                                         \
    auto chunk = [&](uint32_t bufb) {                                          \
        _Pragma("unroll")                                                      \
        for (int ks = 0; ks < 2; ks++) {                                       \
            const int kc0 = ks * 2;                                            \
            uint32_t ah[4][4], al[4][4], bhf[4][2];                            \
            _Pragma("unroll")                                                  \
            for (int mi = 0; mi < 4; mi++) {                                   \
                uint32_t ra = sw64(a_row + mi * 16, kc0 + a_c);                \
                ldm_x4(ah[mi], bufb + ST_AH + ra);                             \
                ldm_x4(al[mi], bufb + ST_AL + ra);                             \
            }                                                                  \
            _Pragma("unroll")                                                  \
            for (int n2 = 0; n2 < 2; n2++) {                                   \
                uint32_t rb = sw64(b_row4 + n2 * 16, kc0 + b_c);               \
                uint32_t t4[4];                                                \
                ldm_x4(t4, bufb + ST_BH + rb);                                 \
                bhf[n2 * 2][0] = t4[0]; bhf[n2 * 2][1] = t4[1];                \
                bhf[n2 * 2 + 1][0] = t4[2]; bhf[n2 * 2 + 1][1] = t4[3];        \
            }                                                                  \
            _Pragma("unroll")                                                  \
            for (int mi = 0; mi < 4; mi++)                                     \
                _Pragma("unroll")                                              \
                for (int ni = 0; ni < 4; ni++) {                               \
                    mma_f16(acc[mi][ni], ah[mi], bhf[ni]);                     \
                    mma_f16(acc[mi][ni], al[mi], bhf[ni]);                     \
                }                                                              \
        }                                                                      \
    };                                                                         \
    int pstage = 0, pphase = 1;                                                \
    auto stage_issue = [&](int kc) {                                           \
        uint32_t fb = sb + MB_OFF + pstage * 16;                               \
        mbar_wait(fb + 8, pphase);                                             \
        stage(pstage, kc);                                                     \
        CPASYNC_MBAR_ARRIVE(fb);                                               \
        if (++pstage == 4) { pstage = 0; pphase ^= 1; }                        \
    };                                                                         \
    stage_issue(0); stage_issue(1);                                            \
    int cstage = 0, cphase = 0;                                                \
    _Pragma("unroll 1")                                                        \
    for (int kc = 0; kc < KITER; kc += 2) {                                    \
        mbar_wait(sb + MB_OFF + cstage * 16, cphase);                          \
        mbar_wait(sb + MB_OFF + (cstage + 1) * 16, cphase);                    \
        if (kc + 2 < KITER) { stage_issue(kc + 2); stage_issue(kc + 3); }      \
        chunk(sb + cstage * STAGE_B);                                          \
        chunk(sb + (cstage + 1) * STAGE_B);                                    \
        MBAR_ARRIVE(sb + MB_OFF + cstage * 16 + 8);                            \
        MBAR_ARRIVE(sb + MB_OFF + (cstage + 1) * 16 + 8);                      \
        cstage += 2;                                                           \
        if (cstage == 4) { cstage = 0; cphase ^= 1; }                          \
    }

// fused QKV GEMM: Q -> fp16 hi/lo (pre-scaled), K/V -> single fp16
__global__ void __launch_bounds__(512, 1)
gemm_qkv(const __half* __restrict__ Ahi, const __half* __restrict__ Alo,
         const __half* __restrict__ Wh,
         const float* __restrict__ bq, const float* __restrict__ bk,
         const float* __restrict__ bv,
         __half* __restrict__ qhi, __half* __restrict__ qlo,
         __half* __restrict__ khi, __half* __restrict__ vhi)
{
    extern __shared__ char smem[];
    const uint32_t sb = smem_u32(smem);
    const int tid = threadIdx.x;
    const int wid = tid >> 5;
    const int lid = tid & 31;
    const int bn  = blockIdx.x;
    const int w   = bn >> 2;
    const int tm  = blockIdx.y * 128;
    const int tn  = (bn & 3) * 256;
    const int wm  = wid >> 3;
    const int wn  = wid & 7;

    const float* bias = (w == 0) ? bq : (w == 1) ? bk : bv;
    __half* Ch = (w == 0) ? qhi : (w == 1) ? khi : vhi;

    const __half* gAh = Ahi + (size_t)tm * EMB;
    const __half* gAl = Alo + (size_t)tm * EMB;
    const __half* gBh = Wh + (size_t)w * WSZ + (size_t)tn * EMB;

    GEMM_STAGE_LAMBDA()
    GEMM_MAINLOOP()

    const int g   = lid >> 2;
    const int tig = lid & 3;
#pragma unroll
    for (int ni = 0; ni < 4; ni++) {
        const int n = tn + wn * 32 + ni * 8 + tig * 2;
        const float b0 = bias[n], b1 = bias[n + 1];
        const int hh = n >> 6, dd = n & 63;
#pragma unroll
        for (int mi = 0; mi < 4; mi++) {
#pragma unroll
            for (int half = 0; half < 2; half++) {
                int m = tm + wm * 64 + mi * 16 + g + half * 8;
                float vx = acc[mi][ni][half * 2 + 0] + b0;
                float vy = acc[mi][ni][half * 2 + 1] + b1;
                int bb = m >> 11, ss = m & 2047;
                size_t idx = (((size_t)(bb * NH + hh) * S_LEN) + ss) * HD + dd;
                if (w == 0) {
                    vx *= QSCALE; vy *= QSCALE;
                    __half hx = __float2half(vx);
                    __half hy = __float2half(vy);
                    float lx = vx - __half2float(hx);
                    float ly = vy - __half2float(hy);
                    *(__half2*)(qhi + idx) = __halves2half2(hx, hy);
                    *(__half2*)(qlo + idx) = __floats2half2_rn(lx, ly);
                } else {
                    *(__half2*)(Ch + idx) = __floats2half2_rn(vx, vy);
                }
            }
        }
    }
}

// output projection GEMM: grid (4, 64), fp32 C row-major (2-term fp16)
__global__ void __launch_bounds__(512, 1)
gemm_out(const __half* __restrict__ Ahi, const __half* __restrict__ Alo,
         const __half* __restrict__ Wh,
         const float* __restrict__ bias, float* __restrict__ C)
{
    extern __shared__ char smem[];
    const uint32_t sb = smem_u32(smem);
    const int tid = threadIdx.x;
    const int wid = tid >> 5;
    const int lid = tid & 31;
    const int tm  = blockIdx.y * 128;
    const int tn  = blockIdx.x * 256;
    const int wm  = wid >> 3;
    const int wn  = wid & 7;

    const __half* gAh = Ahi + (size_t)tm * EMB;
    const __half* gAl = Alo + (size_t)tm * EMB;
    const __half* gBh = Wh + (size_t)tn * EMB;

    GEMM_STAGE_LAMBDA()
    GEMM_MAINLOOP()

    const int g   = lid >> 2;
    const int tig = lid & 3;
#pragma unroll
    for (int ni = 0; ni < 4; ni++) {
        const int n = tn + wn * 32 + ni * 8 + tig * 2;
        const float b0 = bias[n], b1 = bias[n + 1];
#pragma unroll
        for (int mi = 0; mi < 4; mi++) {
#pragma unroll
            for (int half = 0; half < 2; half++) {
                int m = tm + wm * 64 + mi * 16 + g + half * 8;
                float2 v;
                v.x = acc[mi][ni][half * 2 + 0] + b0;
                v.y = acc[mi][ni][half * 2 + 1] + b1;
                *(float2*)(C + (size_t)m * EMB + n) = v;
            }
        }
    }
}

// ---------------------------------------------------------------------------
// Flash attention, 2-term fp16 (unchanged from R16 winner except fp16 output):
// QK = (Qh+Ql)·Kh, PV = (Ph+Pl)·Vh, no-max softmax, deferred l,
// 4-stage KV ring, 2 CTAs/SM.
// ---------------------------------------------------------------------------
#define FQ_H  0
#define FQ_L  16384
#define F_KH  0
#define F_VH  8192
#define F_STAGE 16384
#define F_STG0 32768
#define F_MB   (F_STG0 + 4 * F_STAGE)      // 98304
#define FLASH_SMEM (F_MB + 64)             // 98368
#define NCHUNK (S_LEN / 64)                // 32

__global__ void __launch_bounds__(256, 2)
flash_mma(const __half* __restrict__ Qhi, const __half* __restrict__ Qlo,
          const __half* __restrict__ Khi, const __half* __restrict__ Vhi,
          __half* __restrict__ Ohi, __half* __restrict__ Olo)
{
    extern __shared__ char smem[];
    const uint32_t sb = smem_u32(smem);
    const int tid = threadIdx.x;
    const int wid = tid >> 5;
    const int lid = tid & 31;
    const int bh  = blockIdx.y;
    const int b   = bh >> 4;
    const int h   = bh & 15;
    const int q0  = blockIdx.x * 128;

    const __half* Qh_g = Qhi + ((size_t)bh * S_LEN + q0) * HD;
    const __half* Ql_g = Qlo + ((size_t)bh * S_LEN + q0) * HD;
    const __half* Kh_g = Khi + (size_t)bh * S_LEN * HD;
    const __half* Vh_g = Vhi + (size_t)bh * S_LEN * HD;

    if (tid == 0) {
#pragma unroll
        for (int s = 0; s < 4; s++) {
            MBAR_INIT(sb + F_MB + s * 16, 256);
            MBAR_INIT(sb + F_MB + s * 16 + 8, 256);
        }
    }
    __syncthreads();

    auto stage = [&](int buf, int c) {
        const uint32_t base = sb + F_STG0 + buf * F_STAGE;
#pragma unroll
        for (int t = 0; t < 2; t++) {
            int item = tid + t * 256;
            int row = item >> 3, seg = item & 7;
            uint32_t so = sw128((uint32_t)(row * 128 + seg * 16));
            const size_t go = (size_t)(c * 64 + row) * HD + seg * 8;
            cp_async16(base + F_KH + so, Kh_g + go);
            cp_async16(base + F_VH + so, Vh_g + go);
        }
    };

    int pstage = 0, pphase = 1, cstage = 0, cphase = 0;
    auto stage_issue = [&](int c) {
        uint32_t fb = sb + F_MB + pstage * 16;
        mbar_wait(fb + 8, pphase);
        stage(pstage, c);
        CPASYNC_MBAR_ARRIVE(fb);
        if (++pstage == 4) { pstage = 0; pphase ^= 1; }
    };

    stage_issue(0); stage_issue(1); stage_issue(2);

    {
        int row = tid >> 1;
#pragma unroll
        for (int t = 0; t < 4; t++) {
            int seg = (tid & 1) * 4 + t;
            uint32_t so = sw128((uint32_t)(row * 128 + seg * 16));
            *(uint4*)(smem + FQ_H + so) = *(const uint4*)(Qh_g + (size_t)row * HD + seg * 8);
            *(uint4*)(smem + FQ_L + so) = *(const uint4*)(Ql_g + (size_t)row * HD + seg * 8);
        }
    }
    __syncthreads();

    float o[8][4];
#pragma unroll
    for (int ni = 0; ni < 8; ni++)
#pragma unroll
        for (int j = 0; j < 4; j++) o[ni][j] = 0.0f;
    float l0 = 0.0f, l1 = 0.0f;

    const int a_row  = wid * 16 + (lid & 15);
    const int a_c    = (lid >> 4);
    const int kb_row = (lid & 7) + ((lid >> 4) << 3);
    const int kb_c   = (lid >> 3) & 1;
    const int v_row4 = (lid & 7) + (((lid >> 3) & 1) << 3);
    const int v_nh   = (lid >> 4);

#pragma unroll 1
    for (int c = 0; c < NCHUNK; c++) {
        mbar_wait(sb + F_MB + cstage * 16, cphase);
        if (c + 3 < NCHUNK) stage_issue(c + 3);
        const uint32_t bufb = sb + F_STG0 + cstage * F_STAGE;

        float sc[8][4];
#pragma unroll
        for (int ni = 0; ni < 8; ni++)
#pragma unroll
            for (int j = 0; j < 4; j++) sc[ni][j] = 0.0f;

#pragma unroll
        for (int ks = 0; ks < 4; ks++) {
            uint32_t qh4[4], ql4[4];
            uint32_t ra = sw128((uint32_t)(a_row * 128 + (ks * 2 + a_c) * 16));
            ldm_x4(qh4, sb + FQ_H + ra);
            ldm_x4(ql4, sb + FQ_L + ra);
#pragma unroll
            for (int n2 = 0; n2 < 4; n2++) {
                uint32_t rb = sw128((uint32_t)((n2 * 16 + kb_row) * 128 + (ks * 2 + kb_c) * 16));
                uint32_t t4[4];
                uint32_t kh0[2], kh1[2];
                ldm_x4(t4, bufb + F_KH + rb);
                kh0[0] = t4[0]; kh0[1] = t4[1]; kh1[0] = t4[2]; kh1[1] = t4[3];
                mma_f16(sc[n2 * 2 + 0], qh4, kh0);
                mma_f16(sc[n2 * 2 + 1], qh4, kh1);
                mma_f16(sc[n2 * 2 + 0], ql4, kh0);
                mma_f16(sc[n2 * 2 + 1], ql4, kh1);
            }
        }

#pragma unroll
        for (int ni = 0; ni < 8; ni++) {
            sc[ni][0] = ex2f(sc[ni][0]);
            sc[ni][1] = ex2f(sc[ni][1]);
            sc[ni][2] = ex2f(sc[ni][2]);
            sc[ni][3] = ex2f(sc[ni][3]);
            l0 += sc[ni][0] + sc[ni][1];
            l1 += sc[ni][2] + sc[ni][3];
        }

        uint32_t ph[4][4], pl[4][4];
#pragma unroll
        for (int kk = 0; kk < 4; kk++) {
            float p00 = sc[2 * kk][0],     p01 = sc[2 * kk][1];
            float p02 = sc[2 * kk][2],     p03 = sc[2 * kk][3];
            float p10 = sc[2 * kk + 1][0], p11 = sc[2 * kk + 1][1];
            float p12 = sc[2 * kk + 1][2], p13 = sc[2 * kk + 1][3];
            __half h00 = __float2half(p00), h01 = __float2half(p01);
            __half h02 = __float2half(p02), h03 = __float2half(p03);
            __half h10 = __float2half(p10), h11 = __float2half(p11);
            __half h12 = __float2half(p12), h13 = __float2half(p13);
            ph[kk][0] = h2_as_u32(__halves2half2(h00, h01));
            ph[kk][1] = h2_as_u32(__halves2half2(h02, h03));
            ph[kk][2] = h2_as_u32(__halves2half2(h10, h11));
            ph[kk][3] = h2_as_u32(__halves2half2(h12, h13));
            pl[kk][0] = h2_as_u32(__floats2half2_rn(p00 - __half2float(h00), p01 - __half2float(h01)));
            pl[kk][1] = h2_as_u32(__floats2half2_rn(p02 - __half2float(h02), p03 - __half2float(h03)));
            pl[kk][2] = h2_as_u32(__floats2half2_rn(p10 - __half2float(h10), p11 - __half2float(h11)));
            pl[kk][3] = h2_as_u32(__floats2half2_rn(p12 - __half2float(h12), p13 - __half2float(h13)));
        }

#pragma unroll
        for (int ks = 0; ks < 4; ks++) {
#pragma unroll
            for (int n2 = 0; n2 < 4; n2++) {
                uint32_t rv = sw128((uint32_t)((ks * 16 + v_row4) * 128 + (n2 * 2 + v_nh) * 16));
                uint32_t t4[4];
                uint32_t vh0[2], vh1[2];
                ldm_x4_t(t4, bufb + F_VH + rv);
                vh0[0] = t4[0]; vh0[1] = t4[1]; vh1[0] = t4[2]; vh1[1] = t4[3];
                mma_f16(o[n2 * 2 + 0], ph[ks], vh0);
                mma_f16(o[n2 * 2 + 1], ph[ks], vh1);
                mma_f16(o[n2 * 2 + 0], pl[ks], vh0);
                mma_f16(o[n2 * 2 + 1], pl[ks], vh1);
            }
        }

        MBAR_ARRIVE(sb + F_MB + cstage * 16 + 8);
        if (++cstage == 4) { cstage = 0; cphase ^= 1; }
    }

    // deferred l reduction + epilogue (fp16 hi/lo output)
    l0 += __shfl_xor_sync(~0u, l0, 1);
    l0 += __shfl_xor_sync(~0u, l0, 2);
    l1 += __shfl_xor_sync(~0u, l1, 1);
    l1 += __shfl_xor_sync(~0u, l1, 2);

    const int g   = lid >> 2;
    const int tig = lid & 3;
    const float inv0 = 1.0f / l0, inv1 = 1.0f / l1;
#pragma unroll
    for (int half = 0; half < 2; half++) {
        int s = q0 + wid * 16 + g + half * 8;
        float inv = half ? inv1 : inv0;
        size_t rowbase = ((size_t)(b * S_LEN + s)) * EMB + h * HD;
#pragma unroll
        for (int ni = 0; ni < 8; ni++) {
            float vx = o[ni][half * 2 + 0] * inv;
            float vy = o[ni][half * 2 + 1] * inv;
            __half hx = __float2half(vx);
            __half hy = __float2half(vy);
            float lx = vx - __half2float(hx);
            float ly = vy - __half2float(hy);
            size_t idx = rowbase + ni * 8 + tig * 2;
            *(__half2*)(Ohi + idx) = __halves2half2(hx, hy);
            *(__half2*)(Olo + idx) = __floats2half2_rn(lx, ly);
        }
    }
}

// ---------------------------------------------------------------------------
// Launch
// ---------------------------------------------------------------------------
extern "C" void kernel_launch(void* const* d_in, const int* in_sizes, int n_in,
                              void* d_out, int out_size)
{
    const float* x  = (const float*)d_in[0];
    const float* Wq = (const float*)d_in[1];
    const float* bq = (const float*)d_in[2];
    const float* Wk = (const float*)d_in[3];
    const float* bk = (const float*)d_in[4];
    const float* Wv = (const float*)d_in[5];
    const float* bv = (const float*)d_in[6];
    const float* Wo = (const float*)d_in[7];
    const float* bo = (const float*)d_in[8];
    float* out = (float*)d_out;

    __half *xhi, *xlo, *wh, *ahi, *alo;
    __half *qhi, *qlo, *khi, *vhi;
    cudaGetSymbolAddress((void**)&xhi, g_xhi);
    cudaGetSymbolAddress((void**)&xlo, g_xlo);
    cudaGetSymbolAddress((void**)&wh,  g_wh);
    cudaGetSymbolAddress((void**)&ahi, g_ahi);
    cudaGetSymbolAddress((void**)&alo, g_alo);
    cudaGetSymbolAddress((void**)&qhi, g_qhi);
    cudaGetSymbolAddress((void**)&qlo, g_qlo);
    cudaGetSymbolAddress((void**)&khi, g_khi);
    cudaGetSymbolAddress((void**)&vhi, g_vhi);

    cudaFuncSetAttribute(gemm_qkv, cudaFuncAttributeMaxDynamicSharedMemorySize, GEMM_SMEM);
    cudaFuncSetAttribute(gemm_out, cudaFuncAttributeMaxDynamicSharedMemorySize, GEMM_SMEM);
    cudaFuncSetAttribute(flash_mma, cudaFuncAttributeMaxDynamicSharedMemorySize, FLASH_SMEM);

    convert_all<<<(N4ALL + 255) / 256, 256>>>((const float4*)x,
        (const float4*)Wq, (const float4*)Wk, (const float4*)Wv, (const float4*)Wo,
        xhi, xlo, wh);

    dim3 gq(12, M_TOT / 128);
    gemm_qkv<<<gq, 512, GEMM_SMEM>>>(xhi, xlo, wh, bq, bk, bv,
                                     qhi, qlo, khi, vhi);

    dim3 ga(S_LEN / 128, BH);
    flash_mma<<<ga, 256, FLASH_SMEM>>>(qhi, qlo, khi, vhi, ahi, alo);

    dim3 gg(EMB / 256, M_TOT / 128);
    gemm_out<<<gg, 512, GEMM_SMEM>>>(ahi, alo, wh + 3 * WSZ, bo, out);
}